// round 8
// baseline (speedup 1.0000x reference)
#include <cuda_runtime.h>
#include <cuda_bf16.h>

#define NNODE 50000
#define NEDGE 300000
#define GTAB  1024
#define EPSBN 1e-5f
#define NTILE 2344              // ceil(NEDGE/128)
#define ROWB  272               // padded smem row bytes (136 bf16)
#define TCSM  (4 * 128 * ROWB)  // 139264: Ah|Al|Wh|Wl

// ---------------- scratch (device globals; no allocation) ----------------
__device__ uint4 g_a1split[(size_t)NTILE * 4096];  // per tile: 32KB bf16-hi | 32KB bf16-lo, row-major [m][k] 256B rows
__device__ uint4 g_a2split[(size_t)NTILE * 4096];
__device__ uint4 g_W2s[4096];                      // 64KB: W^T [n][k] hi | lo
__device__ uint4 g_W3s[4096];
__device__ float g_xd[(size_t)NNODE * 128];
__device__ float g_z [(size_t)NNODE * 128];
__device__ float g_an[(size_t)NNODE * 128];
__device__ float g_xtop[(size_t)NNODE * 128];
__device__ float g_xbot[(size_t)NNODE * 128];
__device__ float g_tab[4 * GTAB * 128];
__device__ float g_WbWe1[200 * 128];
__device__ float g_cvec[128];
__device__ float g_W2p[128 * 128];  __device__ float g_b2p[128];
__device__ float g_W3p[128 * 128];  __device__ float g_b3p[128];
__device__ float g_Wn2p[128 * 128]; __device__ float g_bn2p[128];
__device__ float g_sums[6][128];

// ---------------- helpers ----------------
__device__ __forceinline__ unsigned smem_u32(const void* p) {
    unsigned a;
    asm("{ .reg .u64 t; cvta.to.shared.u64 t, %1; cvt.u32.u64 %0, t; }" : "=r"(a) : "l"(p));
    return a;
}
#define LDMX4(r, addr)                                                         \
    asm volatile("ldmatrix.sync.aligned.m8n8.x4.shared.b16 {%0,%1,%2,%3}, [%4];" \
                 : "=r"((r)[0]), "=r"((r)[1]), "=r"((r)[2]), "=r"((r)[3])      \
                 : "r"(addr))
#define MMA_BF16(d, a0, a1, a2, a3, b0, b1)                                    \
    asm volatile("mma.sync.aligned.m16n8k16.row.col.f32.bf16.bf16.f32 "        \
                 "{%0,%1,%2,%3}, {%4,%5,%6,%7}, {%8,%9}, {%0,%1,%2,%3};"       \
                 : "+f"((d)[0]), "+f"((d)[1]), "+f"((d)[2]), "+f"((d)[3])      \
                 : "r"(a0), "r"(a1), "r"(a2), "r"(a3), "r"(b0), "r"(b1))
static __device__ __forceinline__ unsigned pack2bf(float a, float b) {
    return ((unsigned)__bfloat16_as_ushort(__float2bfloat16_rn(b)) << 16)
         |  (unsigned)__bfloat16_as_ushort(__float2bfloat16_rn(a));
}

// ---------------- tiny prep kernels ----------------
__global__ void zero_stats() { ((float*)g_sums)[threadIdx.x] = 0.0f; }

__global__ void wbwe1_kernel(const float* __restrict__ Wb, const float* __restrict__ We1) {
    int r = blockIdx.x, n = threadIdx.x;
    float acc = 0.f;
    #pragma unroll 8
    for (int k = 0; k < 128; k++) acc += Wb[r * 128 + k] * We1[(128 + k) * 128 + n];
    g_WbWe1[r * 128 + n] = acc;
}

__global__ void cvec_kernel(const float* __restrict__ bb, const float* __restrict__ We1,
                            const float* __restrict__ be1) {
    int n = threadIdx.x;
    float acc = be1[n];
    #pragma unroll 8
    for (int k = 0; k < 128; k++) acc += bb[k] * We1[(128 + k) * 128 + n];
    g_cvec[n] = acc;
}

__global__ void table_kernel() {
    __shared__ float gs[64];
    int b = blockIdx.x;
    int c = b >> 10;
    int gi = b & (GTAB - 1);
    float u = (float)gi * (1.0f / (GTAB - 1));
    int tid = threadIdx.x;
    if (tid < 50) {
        float d = u - (float)tid * (1.0f / 49.0f);
        gs[tid] = __expf(-d * d * 1250.0f);
    }
    __syncthreads();
    float acc = 0.f;
    #pragma unroll
    for (int j = 0; j < 50; j++) acc += gs[j] * g_WbWe1[(c * 50 + j) * 128 + tid];
    g_tab[b * 128 + tid] = acc;
}

__global__ void fold_kernel(int sidx, float invM,
                            const float* __restrict__ gamma, const float* __restrict__ beta,
                            const float* __restrict__ Wsrc, const float* __restrict__ be) {
    float* Wdst = (sidx == 0) ? g_W2p : (sidx == 2) ? g_W3p : g_Wn2p;
    float* bdst = (sidx == 0) ? g_b2p : (sidx == 2) ? g_b3p : g_bn2p;
    int n = threadIdx.x;
    if (blockIdx.x < 128) {
        int k = blockIdx.x;
        float m = g_sums[sidx][k] * invM;
        float var = g_sums[sidx + 1][k] * invM - m * m;
        float s = gamma[k] * rsqrtf(var + EPSBN);
        Wdst[k * 128 + n] = s * Wsrc[k * 128 + n];
    } else {
        float acc = be[n];
        for (int k = 0; k < 128; k++) {
            float m = g_sums[sidx][k] * invM;
            float var = g_sums[sidx + 1][k] * invM - m * m;
            float s = gamma[k] * rsqrtf(var + EPSBN);
            acc += (beta[k] - m * s) * Wsrc[k * 128 + n];
        }
        bdst[n] = acc;
    }
}

// Pack W^T ([n][k] row-major, 256B rows) into bf16 hi/lo staging (64KB)
__global__ void pack_kernel(const float* __restrict__ Wp, char* __restrict__ Ws) {
    int n = blockIdx.x, k = threadIdx.x;
    float v = Wp[k * 128 + n];
    float h = __bfloat162float(__float2bfloat16_rn(v));
    int off = n * 256 + 2 * k;
    *(unsigned short*)(Ws + off)         = __bfloat16_as_ushort(__float2bfloat16_rn(h));
    *(unsigned short*)(Ws + 32768 + off) = __bfloat16_as_ushort(__float2bfloat16_rn(v - h));
}

// ---------------- fused E1 -> bf16 hi/lo tiles (smem staged, coalesced table) ----------------
__global__ __launch_bounds__(128)
void e1_fuse_kernel(const float* __restrict__ ea, const int* __restrict__ eidx) {
    extern __shared__ char stg[];   // 64KB: hi 32KB | lo 32KB
    int t = threadIdx.x;
    int e0 = blockIdx.x * 128;
    float cv = g_cvec[t];
    float csum = 0.f, csq = 0.f;
    int eend = e0 + 128;
    if (eend > NEDGE) eend = NEDGE;
    for (int e = e0; e < eend; e++) {
        int s = __ldg(eidx + e);
        int d = __ldg(eidx + NEDGE + e);
        float val = g_xtop[(size_t)s * 128 + t] + g_xbot[(size_t)d * 128 + t] + cv;
        #pragma unroll
        for (int c = 0; c < 4; c++) {
            float f = __ldg(ea + (size_t)e * 4 + c);
            float p = f * (float)(GTAB - 1);
            int i0 = (int)p;
            if (i0 < 0) i0 = 0;
            if (i0 > GTAB - 2) i0 = GTAB - 2;
            float w = p - (float)i0;
            const float* t0 = g_tab + ((size_t)(c * GTAB + i0) * 128 + t);
            float u = t0[0], v2 = t0[128];
            val += u + w * (v2 - u);
        }
        val = (val >= 0.f) ? val : 0.01f * val;
        csum += val; csq += val * val;
        float h = __bfloat162float(__float2bfloat16_rn(val));
        int off = (e - e0) * 256 + 2 * t;
        *(unsigned short*)(stg + off)         = __bfloat16_as_ushort(__float2bfloat16_rn(h));
        *(unsigned short*)(stg + 32768 + off) = __bfloat16_as_ushort(__float2bfloat16_rn(val - h));
    }
    for (int e = eend; e < e0 + 128; e++) {
        int off = (e - e0) * 256 + 2 * t;
        *(unsigned short*)(stg + off) = 0;
        *(unsigned short*)(stg + 32768 + off) = 0;
    }
    atomicAdd(&g_sums[0][t], csum);
    atomicAdd(&g_sums[1][t], csq);
    __syncthreads();
    uint4* outb = (uint4*)((char*)g_a1split + (size_t)blockIdx.x * 65536);
    const uint4* src = (const uint4*)stg;
    #pragma unroll
    for (int i = t; i < 2048; i += 128) {
        outb[i]        = src[i];
        outb[i + 2048] = src[i + 2048];
    }
}

// ---------------- bf16 tensor-core edge GEMMs (M=128, 512 threads / 16 warps) ----------------
// MODE 0 = E2, MODE 1 = E3
template <int MODE>
__global__ __launch_bounds__(512)
void tc_gemm(const float* __restrict__ ea, const int* __restrict__ eidx) {
    extern __shared__ char sm[];
    __shared__ float s_bias[128];
    const int tid = threadIdx.x;
    const int lane = tid & 31, wid = tid >> 5;
    const int wm = wid & 3, wn = wid >> 2;     // 4 row groups x 4 col groups (32x32 per warp)

    const unsigned sAh_u = smem_u32(sm);
    const unsigned sAl_u = sAh_u + 128 * ROWB;
    const unsigned sWh_u = sAh_u + 2 * 128 * ROWB;
    const unsigned sWl_u = sAh_u + 3 * 128 * ROWB;

    if (tid < 128) s_bias[tid] = (MODE == 0) ? g_b2p[tid] : g_b3p[tid];

    // ---- load tiles (gmem row-major [r][k] bf16, 256B rows) -> smem padded 272B rows ----
    const uint4* Asrc = (MODE == 0 ? g_a1split : g_a2split) + (size_t)blockIdx.x * 4096;
    const uint4* Wsrc = (MODE == 0 ? g_W2s : g_W3s);
    {
        char* sAh = sm;
        char* sAl = sm + 128 * ROWB;
        char* sWh = sm + 2 * 128 * ROWB;
        char* sWl = sWh + 128 * ROWB;
        #pragma unroll
        for (int i = tid; i < 2048; i += 512) {
            int row = i >> 4, ch = i & 15;
            *(uint4*)(sAh + row * ROWB + ch * 16) = Asrc[i];
            *(uint4*)(sAl + row * ROWB + ch * 16) = Asrc[i + 2048];
            *(uint4*)(sWh + row * ROWB + ch * 16) = Wsrc[i];
            *(uint4*)(sWl + row * ROWB + ch * 16) = Wsrc[i + 2048];
        }
    }
    __syncthreads();

    // ---- mma mainloop: 3 products (Ah*Wh + Al*Wh + Ah*Wl), K=128 ----
    const int laneRow = lane & 15;
    const unsigned laneK = (unsigned)((lane >> 4) << 4);
    const unsigned aoff = (unsigned)((wm * 32 + laneRow) * ROWB) + laneK;
    const unsigned woff = (unsigned)((wn * 32 + laneRow) * ROWB) + laneK;

    float acc[2][4][4];
    #pragma unroll
    for (int t = 0; t < 2; t++)
        #pragma unroll
        for (int n = 0; n < 4; n++)
            #pragma unroll
            for (int q = 0; q < 4; q++) acc[t][n][q] = 0.f;

    #pragma unroll 1
    for (int ks = 0; ks < 8; ks++) {
        unsigned kb = (unsigned)(ks * 32);
        unsigned ah[2][4], al[2][4], bh[2][4], bl[2][4];
        LDMX4(ah[0], sAh_u + aoff + kb);
        LDMX4(ah[1], sAh_u + aoff + 16 * ROWB + kb);
        LDMX4(al[0], sAl_u + aoff + kb);
        LDMX4(al[1], sAl_u + aoff + 16 * ROWB + kb);
        LDMX4(bh[0], sWh_u + woff + kb);
        LDMX4(bh[1], sWh_u + woff + 16 * ROWB + kb);
        LDMX4(bl[0], sWl_u + woff + kb);
        LDMX4(bl[1], sWl_u + woff + 16 * ROWB + kb);
        #pragma unroll
        for (int t = 0; t < 2; t++)
            #pragma unroll
            for (int p = 0; p < 2; p++) {
                MMA_BF16(acc[t][2 * p],     ah[t][0], ah[t][1], ah[t][2], ah[t][3], bh[p][0], bh[p][2]);
                MMA_BF16(acc[t][2 * p + 1], ah[t][0], ah[t][1], ah[t][2], ah[t][3], bh[p][1], bh[p][3]);
                MMA_BF16(acc[t][2 * p],     al[t][0], al[t][1], al[t][2], al[t][3], bh[p][0], bh[p][2]);
                MMA_BF16(acc[t][2 * p + 1], al[t][0], al[t][1], al[t][2], al[t][3], bh[p][1], bh[p][3]);
                MMA_BF16(acc[t][2 * p],     ah[t][0], ah[t][1], ah[t][2], ah[t][3], bl[p][0], bl[p][2]);
                MMA_BF16(acc[t][2 * p + 1], ah[t][0], ah[t][1], ah[t][2], ah[t][3], bl[p][1], bl[p][3]);
            }
    }
    __syncthreads();   // smem tiles free; reuse as fp32 stage

    // ---- stage D into smem fp32 [128][132] ----
    float* sF = (float*)sm;
    {
        int mr = lane >> 2;
        int nc = 2 * (lane & 3);
        #pragma unroll
        for (int t = 0; t < 2; t++) {
            int row = wm * 32 + t * 16 + mr;
            #pragma unroll
            for (int nt = 0; nt < 4; nt++) {
                int col = wn * 32 + nt * 8 + nc;
                sF[row * 132 + col]           = acc[t][nt][0];
                sF[row * 132 + col + 1]       = acc[t][nt][1];
                sF[(row + 8) * 132 + col]     = acc[t][nt][2];
                sF[(row + 8) * 132 + col + 1] = acc[t][nt][3];
            }
        }
    }
    __syncthreads();

    if (MODE == 0) {
        // Row pass: bias + lrelu, write back to sF, pack bf16 hi/lo, coalesced uint4 stores
        int rl = tid >> 2, h = tid & 3;        // 128 rows x 4 col-quarters (32 cols)
        long gbase = (long)blockIdx.x * 128;
        bool valid = (gbase + rl) < NEDGE;
        char* outb = (char*)g_a2split + (size_t)blockIdx.x * 65536;
        uint4* dh = (uint4*)(outb + rl * 256 + h * 64);
        uint4* dl = (uint4*)(outb + 32768 + rl * 256 + h * 64);
        float* fr = sF + rl * 132 + h * 32;
        const float* bp = s_bias + h * 32;
        #pragma unroll
        for (int q = 0; q < 4; q++) {          // 4 uint4 per 32-col quarter (8 cols each)
            unsigned ph[4], pl[4];
            #pragma unroll
            for (int j = 0; j < 4; j++) {
                int c = q * 8 + j * 2;
                float v0 = fr[c]     + bp[c];
                float v1 = fr[c + 1] + bp[c + 1];
                v0 = (v0 >= 0.f) ? v0 : 0.01f * v0;
                v1 = (v1 >= 0.f) ? v1 : 0.01f * v1;
                if (!valid) { v0 = 0.f; v1 = 0.f; }
                fr[c] = v0; fr[c + 1] = v1;
                float h0 = __bfloat162float(__float2bfloat16_rn(v0));
                float h1 = __bfloat162float(__float2bfloat16_rn(v1));
                ph[j] = pack2bf(h0, h1);
                pl[j] = pack2bf(v0 - h0, v1 - h1);
            }
            dh[q] = make_uint4(ph[0], ph[1], ph[2], ph[3]);
            dl[q] = make_uint4(pl[0], pl[1], pl[2], pl[3]);
        }
        __syncthreads();
        // Column pass for stats (invalid rows already zeroed in sF)
        {
            int c = tid & 127, qr = tid >> 7;   // 4 row quarters of 32
            float s0 = 0.f, s1 = 0.f;
            #pragma unroll 8
            for (int r = 0; r < 32; r++) {
                float v = sF[(qr * 32 + r) * 132 + c];
                s0 += v; s1 += v * v;
            }
            atomicAdd(&g_sums[2][c], s0);
            atomicAdd(&g_sums[3][c], s1);
        }
    } else {
        // z[dst] += coeff * (D + b3p) * xd[src]
        int rt = tid >> 2, h = tid & 3;
        long grow = (long)blockIdx.x * 128 + rt;
        if (grow < NEDGE) {
            int s_ = eidx[grow], d_ = eidx[NEDGE + grow];
            float coeff = cosf(1.5707963267948966f * ea[grow * 4 + 3]);
            const float4* xp = (const float4*)(g_xd + (size_t)s_ * 128) + h * 8;
            float* zp = g_z + (size_t)d_ * 128 + h * 32;
            const float* fr = sF + rt * 132 + h * 32;
            const float* bp = s_bias + h * 32;
            #pragma unroll
            for (int q = 0; q < 8; q++) {
                float4 xv = xp[q];
                float v0 = coeff * (fr[4 * q + 0] + bp[4 * q + 0]) * xv.x;
                float v1 = coeff * (fr[4 * q + 1] + bp[4 * q + 1]) * xv.y;
                float v2 = coeff * (fr[4 * q + 2] + bp[4 * q + 2]) * xv.z;
                float v3 = coeff * (fr[4 * q + 3] + bp[4 * q + 3]) * xv.w;
                asm volatile("red.global.add.v4.f32 [%0], {%1,%2,%3,%4};"
                             :: "l"(zp + 4 * q), "f"(v0), "f"(v1), "f"(v2), "f"(v3) : "memory");
            }
        }
    }
}

// ---------------- SIMT node GEMMs (128x128 tile, 256 threads) ----------------
enum { M_XD = 0, M_PLAIN = 1, M_N1 = 4, M_OUT = 5 };

template <int MODE>
__global__ __launch_bounds__(256)
void gemm_kernel(const float* __restrict__ A, const float* __restrict__ Wparam,
                 const float* __restrict__ biasExt, const float* __restrict__ x,
                 const float* __restrict__ vparam, float* __restrict__ outp, int M) {
    __shared__ float As[16][132];
    __shared__ float Ws[16][132];

    const int tid = threadIdx.x;
    const int blockRow = blockIdx.x * 128;
    const int tr = tid >> 4;
    const int tc = tid & 15;
    const int c0 = tc * 8;

    const float* W = (MODE == M_OUT) ? g_Wn2p : Wparam;
    const float* bias = (MODE == M_OUT) ? g_bn2p : biasExt;
    const float* Aeff = (MODE == M_N1) ? g_z : (MODE == M_OUT) ? g_an : A;

    const int lr = tid >> 1;
    const int lh = (tid & 1) * 8;
    const float* arow;
    {
        int r = blockRow + lr;
        if (r > M - 1) r = M - 1;
        arow = Aeff + (size_t)r * 128;
    }

    float acc[8][8];
    #pragma unroll
    for (int i = 0; i < 8; i++)
        #pragma unroll
        for (int j = 0; j < 8; j++) acc[i][j] = 0.f;

    #pragma unroll 1
    for (int k0 = 0; k0 < 128; k0 += 16) {
        const float* ap = arow + k0 + lh;
        float4 a0 = *(const float4*)ap;
        float4 a1 = *(const float4*)(ap + 4);
        int krow = k0 + tr;
        float4 b0 = *(const float4*)(W + (size_t)krow * 128 + c0);
        float4 b1 = *(const float4*)(W + (size_t)krow * 128 + c0 + 4);

        __syncthreads();
        As[lh + 0][lr] = a0.x; As[lh + 1][lr] = a0.y;
        As[lh + 2][lr] = a0.z; As[lh + 3][lr] = a0.w;
        As[lh + 4][lr] = a1.x; As[lh + 5][lr] = a1.y;
        As[lh + 6][lr] = a1.z; As[lh + 7][lr] = a1.w;
        *(float4*)&Ws[tr][c0]     = b0;
        *(float4*)&Ws[tr][c0 + 4] = b1;
        __syncthreads();

        #pragma unroll
        for (int kk = 0; kk < 16; kk++) {
            float af[8], bf[8];
            *(float4*)(af)     = *(const float4*)&As[kk][tr * 8];
            *(float4*)(af + 4) = *(const float4*)&As[kk][tr * 8 + 4];
            *(float4*)(bf)     = *(const float4*)&Ws[kk][c0];
            *(float4*)(bf + 4) = *(const float4*)&Ws[kk][c0 + 4];
            #pragma unroll
            for (int i = 0; i < 8; i++)
                #pragma unroll
                for (int j = 0; j < 8; j++)
                    acc[i][j] += af[i] * bf[j];
        }
    }
    __syncthreads();

    float bj[8];
    #pragma unroll
    for (int j = 0; j < 8; j++) bj[j] = (MODE == M_PLAIN) ? 0.f : bias[c0 + j];

    if (MODE == M_PLAIN) {
        #pragma unroll
        for (int i = 0; i < 8; i++) {
            int r = blockRow + tr * 8 + i;
            if (r >= M) break;
            float* dp = outp + (size_t)r * 128 + c0;
            *(float4*)dp       = make_float4(acc[i][0], acc[i][1], acc[i][2], acc[i][3]);
            *(float4*)(dp + 4) = make_float4(acc[i][4], acc[i][5], acc[i][6], acc[i][7]);
        }
        return;
    }
    if (MODE == M_XD) {
        float vj[8];
        #pragma unroll
        for (int j = 0; j < 8; j++) vj[j] = vparam[c0 + j];
        #pragma unroll
        for (int i = 0; i < 8; i++) {
            int r = blockRow + tr * 8 + i;
            if (r >= M) break;
            float vals[8], zv[8];
            #pragma unroll
            for (int j = 0; j < 8; j++) { vals[j] = acc[i][j] + bj[j]; zv[j] = vj[j] * vals[j]; }
            float* dp = g_xd + (size_t)r * 128 + c0;
            *(float4*)dp       = make_float4(vals[0], vals[1], vals[2], vals[3]);
            *(float4*)(dp + 4) = make_float4(vals[4], vals[5], vals[6], vals[7]);
            float* zp = g_z + (size_t)r * 128 + c0;
            *(float4*)zp       = make_float4(zv[0], zv[1], zv[2], zv[3]);
            *(float4*)(zp + 4) = make_float4(zv[4], zv[5], zv[6], zv[7]);
        }
        return;
    }
    if (MODE == M_OUT) {
        #pragma unroll
        for (int i = 0; i < 8; i++) {
            int r = blockRow + tr * 8 + i;
            if (r >= M) break;
            const float* xp = x + (size_t)r * 128 + c0;
            float4 x0 = *(const float4*)xp;
            float4 x1 = *(const float4*)(xp + 4);
            float* dp = outp + (size_t)r * 128 + c0;
            *(float4*)dp = make_float4(acc[i][0] + bj[0] + x0.x, acc[i][1] + bj[1] + x0.y,
                                       acc[i][2] + bj[2] + x0.z, acc[i][3] + bj[3] + x0.w);
            *(float4*)(dp + 4) = make_float4(acc[i][4] + bj[4] + x1.x, acc[i][5] + bj[5] + x1.y,
                                             acc[i][6] + bj[6] + x1.z, acc[i][7] + bj[7] + x1.w);
        }
        return;
    }
    // M_N1: lrelu + store + stats
    {
        float csum[8], csq[8];
        #pragma unroll
        for (int j = 0; j < 8; j++) { csum[j] = 0.f; csq[j] = 0.f; }
        #pragma unroll 1
        for (int i = 0; i < 8; i++) {
            int r = blockRow + tr * 8 + i;
            if (r >= M) break;
            float vals[8];
            #pragma unroll
            for (int j = 0; j < 8; j++) {
                float v_ = acc[i][j] + bj[j];
                v_ = (v_ >= 0.f) ? v_ : 0.01f * v_;
                vals[j] = v_; csum[j] += v_; csq[j] += v_ * v_;
            }
            float* dp = g_an + (size_t)r * 128 + c0;
            *(float4*)dp       = make_float4(vals[0], vals[1], vals[2], vals[3]);
            *(float4*)(dp + 4) = make_float4(vals[4], vals[5], vals[6], vals[7]);
        }
        #pragma unroll
        for (int j = 0; j < 8; j++) As[tr][c0 + j] = csum[j];
        __syncthreads();
        if (tid < 128) {
            float s = 0.f;
            #pragma unroll
            for (int t = 0; t < 16; t++) s += As[t][tid];
            atomicAdd(&g_sums[4][tid], s);
        }
        __syncthreads();
        #pragma unroll
        for (int j = 0; j < 8; j++) As[tr][c0 + j] = csq[j];
        __syncthreads();
        if (tid < 128) {
            float s = 0.f;
            #pragma unroll
            for (int t = 0; t < 16; t++) s += As[t][tid];
            atomicAdd(&g_sums[5][tid], s);
        }
    }
}

// ---------------- launcher ----------------
extern "C" void kernel_launch(void* const* d_in, const int* in_sizes, int n_in,
                              void* d_out, int out_size) {
    const float* x    = (const float*)d_in[0];
    const float* ea   = (const float*)d_in[1];
    const int*   eidx = (const int*)  d_in[2];
    const float* Wb   = (const float*)d_in[3];
    const float* bb   = (const float*)d_in[4];
    const float* We1  = (const float*)d_in[5];
    const float* be1  = (const float*)d_in[6];
    const float* ge1  = (const float*)d_in[7];
    const float* bte1 = (const float*)d_in[8];
    const float* We2  = (const float*)d_in[9];
    const float* be2  = (const float*)d_in[10];
    const float* ge2  = (const float*)d_in[11];
    const float* bte2 = (const float*)d_in[12];
    const float* We3  = (const float*)d_in[13];
    const float* be3  = (const float*)d_in[14];
    const float* Wd   = (const float*)d_in[15];
    const float* bd   = (const float*)d_in[16];
    const float* v    = (const float*)d_in[17];
    const float* Wn1  = (const float*)d_in[18];
    const float* bn1  = (const float*)d_in[19];
    const float* gn   = (const float*)d_in[20];
    const float* btn  = (const float*)d_in[21];
    const float* Wn2  = (const float*)d_in[22];
    const float* bn2  = (const float*)d_in[23];
    float* outp = (float*)d_out;

    const int gridN = (NNODE + 127) / 128;

    float* d_xtop; cudaGetSymbolAddress((void**)&d_xtop, g_xtop);
    float* d_xbot; cudaGetSymbolAddress((void**)&d_xbot, g_xbot);
    float* d_W2p;  cudaGetSymbolAddress((void**)&d_W2p, g_W2p);
    float* d_W3p;  cudaGetSymbolAddress((void**)&d_W3p, g_W3p);
    char*  d_W2s;  cudaGetSymbolAddress((void**)&d_W2s, g_W2s);
    char*  d_W3s;  cudaGetSymbolAddress((void**)&d_W3s, g_W3s);

    cudaFuncSetAttribute(tc_gemm<0>, cudaFuncAttributeMaxDynamicSharedMemorySize, TCSM);
    cudaFuncSetAttribute(tc_gemm<1>, cudaFuncAttributeMaxDynamicSharedMemorySize, TCSM);
    cudaFuncSetAttribute(e1_fuse_kernel, cudaFuncAttributeMaxDynamicSharedMemorySize, 65536);

    zero_stats<<<1, 768>>>();
    wbwe1_kernel<<<200, 128>>>(Wb, We1);
    cvec_kernel<<<1, 128>>>(bb, We1, be1);
    table_kernel<<<4 * GTAB, 128>>>();

    gemm_kernel<M_XD><<<gridN, 256>>>(x, Wd, bd, nullptr, v, nullptr, NNODE);
    gemm_kernel<M_PLAIN><<<gridN, 256>>>(x, We1,             nullptr, nullptr, nullptr, d_xtop, NNODE);
    gemm_kernel<M_PLAIN><<<gridN, 256>>>(x, We1 + 256 * 128, nullptr, nullptr, nullptr, d_xbot, NNODE);

    e1_fuse_kernel<<<NTILE, 128, 65536>>>(ea, eidx);
    fold_kernel<<<129, 128>>>(0, 1.0f / NEDGE, ge1, bte1, We2, be2);
    pack_kernel<<<128, 128>>>(d_W2p, d_W2s);

    tc_gemm<0><<<NTILE, 512, TCSM>>>(ea, eidx);
    fold_kernel<<<129, 128>>>(2, 1.0f / NEDGE, ge2, bte2, We3, be3);
    pack_kernel<<<128, 128>>>(d_W3p, d_W3s);

    tc_gemm<1><<<NTILE, 512, TCSM>>>(ea, eidx);

    gemm_kernel<M_N1><<<gridN, 256>>>(nullptr, Wn1, bn1, nullptr, nullptr, nullptr, NNODE);
    fold_kernel<<<129, 128>>>(4, 1.0f / NNODE, gn, btn, Wn2, bn2);
    gemm_kernel<M_OUT><<<gridN, 256>>>(nullptr, nullptr, nullptr, x, nullptr, outp, NNODE);
}

// round 9
// speedup vs baseline: 1.0162x; 1.0162x over previous
#include <cuda_runtime.h>
#include <cuda_bf16.h>

#define NNODE 50000
#define NEDGE 300000
#define GTAB  1024
#define EPSBN 1e-5f
#define NTILE 2344              // ceil(NEDGE/128)
#define ROWB  272               // padded smem row bytes (136 bf16)
#define TCSM  (4 * 128 * ROWB)  // 139264: Ah|Al|Wh|Wl

// ---------------- scratch (device globals; no allocation) ----------------
__device__ uint4 g_a1split[(size_t)NTILE * 4096];  // per tile: 32KB bf16-hi | 32KB bf16-lo, row-major [m][k] 256B rows
__device__ uint4 g_a2split[(size_t)NTILE * 4096];
__device__ uint4 g_W2s[4096];                      // 64KB: W^T [n][k] hi | lo
__device__ uint4 g_W3s[4096];
__device__ float g_xd[(size_t)NNODE * 128];
__device__ float g_z [(size_t)NNODE * 128];
__device__ float g_an[(size_t)NNODE * 128];
__device__ float g_xtop[(size_t)NNODE * 128];
__device__ float g_xbot[(size_t)NNODE * 128];
__device__ float g_tab[4 * GTAB * 128];
__device__ float g_WbWe1[200 * 128];
__device__ float g_cvec[128];
__device__ float g_W2p[128 * 128];  __device__ float g_b2p[128];
__device__ float g_W3p[128 * 128];  __device__ float g_b3p[128];
__device__ float g_Wn2p[128 * 128]; __device__ float g_bn2p[128];
__device__ float g_sums[6][128];

// ---------------- helpers ----------------
__device__ __forceinline__ unsigned smem_u32(const void* p) {
    unsigned a;
    asm("{ .reg .u64 t; cvta.to.shared.u64 t, %1; cvt.u32.u64 %0, t; }" : "=r"(a) : "l"(p));
    return a;
}
#define LDMX4(r, addr)                                                         \
    asm volatile("ldmatrix.sync.aligned.m8n8.x4.shared.b16 {%0,%1,%2,%3}, [%4];" \
                 : "=r"((r)[0]), "=r"((r)[1]), "=r"((r)[2]), "=r"((r)[3])      \
                 : "r"(addr))
#define MMA_BF16(d, a0, a1, a2, a3, b0, b1)                                    \
    asm volatile("mma.sync.aligned.m16n8k16.row.col.f32.bf16.bf16.f32 "        \
                 "{%0,%1,%2,%3}, {%4,%5,%6,%7}, {%8,%9}, {%0,%1,%2,%3};"       \
                 : "+f"((d)[0]), "+f"((d)[1]), "+f"((d)[2]), "+f"((d)[3])      \
                 : "r"(a0), "r"(a1), "r"(a2), "r"(a3), "r"(b0), "r"(b1))
static __device__ __forceinline__ unsigned pack2bf(float a, float b) {
    return ((unsigned)__bfloat16_as_ushort(__float2bfloat16_rn(b)) << 16)
         |  (unsigned)__bfloat16_as_ushort(__float2bfloat16_rn(a));
}

// ---------------- tiny prep kernels ----------------
__global__ void zero_stats() { ((float*)g_sums)[threadIdx.x] = 0.0f; }

__global__ void wbwe1_kernel(const float* __restrict__ Wb, const float* __restrict__ We1) {
    int r = blockIdx.x, n = threadIdx.x;
    float acc = 0.f;
    #pragma unroll 8
    for (int k = 0; k < 128; k++) acc += Wb[r * 128 + k] * We1[(128 + k) * 128 + n];
    g_WbWe1[r * 128 + n] = acc;
}

__global__ void cvec_kernel(const float* __restrict__ bb, const float* __restrict__ We1,
                            const float* __restrict__ be1) {
    int n = threadIdx.x;
    float acc = be1[n];
    #pragma unroll 8
    for (int k = 0; k < 128; k++) acc += bb[k] * We1[(128 + k) * 128 + n];
    g_cvec[n] = acc;
}

__global__ void table_kernel() {
    __shared__ float gs[64];
    int b = blockIdx.x;
    int c = b >> 10;
    int gi = b & (GTAB - 1);
    float u = (float)gi * (1.0f / (GTAB - 1));
    int tid = threadIdx.x;
    if (tid < 50) {
        float d = u - (float)tid * (1.0f / 49.0f);
        gs[tid] = __expf(-d * d * 1250.0f);
    }
    __syncthreads();
    float acc = 0.f;
    #pragma unroll
    for (int j = 0; j < 50; j++) acc += gs[j] * g_WbWe1[(c * 50 + j) * 128 + tid];
    g_tab[b * 128 + tid] = acc;
}

__global__ void fold_kernel(int sidx, float invM,
                            const float* __restrict__ gamma, const float* __restrict__ beta,
                            const float* __restrict__ Wsrc, const float* __restrict__ be) {
    float* Wdst = (sidx == 0) ? g_W2p : (sidx == 2) ? g_W3p : g_Wn2p;
    float* bdst = (sidx == 0) ? g_b2p : (sidx == 2) ? g_b3p : g_bn2p;
    int n = threadIdx.x;
    if (blockIdx.x < 128) {
        int k = blockIdx.x;
        float m = g_sums[sidx][k] * invM;
        float var = g_sums[sidx + 1][k] * invM - m * m;
        float s = gamma[k] * rsqrtf(var + EPSBN);
        Wdst[k * 128 + n] = s * Wsrc[k * 128 + n];
    } else {
        float acc = be[n];
        for (int k = 0; k < 128; k++) {
            float m = g_sums[sidx][k] * invM;
            float var = g_sums[sidx + 1][k] * invM - m * m;
            float s = gamma[k] * rsqrtf(var + EPSBN);
            acc += (beta[k] - m * s) * Wsrc[k * 128 + n];
        }
        bdst[n] = acc;
    }
}

// Pack W^T ([n][k] row-major, 256B rows) into bf16 hi/lo staging (64KB)
__global__ void pack_kernel(const float* __restrict__ Wp, char* __restrict__ Ws) {
    int n = blockIdx.x, k = threadIdx.x;
    float v = Wp[k * 128 + n];
    float h = __bfloat162float(__float2bfloat16_rn(v));
    int off = n * 256 + 2 * k;
    *(unsigned short*)(Ws + off)         = __bfloat16_as_ushort(__float2bfloat16_rn(h));
    *(unsigned short*)(Ws + 32768 + off) = __bfloat16_as_ushort(__float2bfloat16_rn(v - h));
}

// ---------------- fused E1 -> bf16 hi/lo tiles (smem staged, coalesced table) ----------------
__global__ __launch_bounds__(128)
void e1_fuse_kernel(const float* __restrict__ ea, const int* __restrict__ eidx) {
    extern __shared__ char stg[];   // 64KB: hi 32KB | lo 32KB
    int t = threadIdx.x;
    int e0 = blockIdx.x * 128;
    float cv = g_cvec[t];
    float csum = 0.f, csq = 0.f;
    int eend = e0 + 128;
    if (eend > NEDGE) eend = NEDGE;
    for (int e = e0; e < eend; e++) {
        int s = __ldg(eidx + e);
        int d = __ldg(eidx + NEDGE + e);
        float val = g_xtop[(size_t)s * 128 + t] + g_xbot[(size_t)d * 128 + t] + cv;
        #pragma unroll
        for (int c = 0; c < 4; c++) {
            float f = __ldg(ea + (size_t)e * 4 + c);
            float p = f * (float)(GTAB - 1);
            int i0 = (int)p;
            if (i0 < 0) i0 = 0;
            if (i0 > GTAB - 2) i0 = GTAB - 2;
            float w = p - (float)i0;
            const float* t0 = g_tab + ((size_t)(c * GTAB + i0) * 128 + t);
            float u = t0[0], v2 = t0[128];
            val += u + w * (v2 - u);
        }
        val = (val >= 0.f) ? val : 0.01f * val;
        csum += val; csq += val * val;
        float h = __bfloat162float(__float2bfloat16_rn(val));
        int off = (e - e0) * 256 + 2 * t;
        *(unsigned short*)(stg + off)         = __bfloat16_as_ushort(__float2bfloat16_rn(h));
        *(unsigned short*)(stg + 32768 + off) = __bfloat16_as_ushort(__float2bfloat16_rn(val - h));
    }
    for (int e = eend; e < e0 + 128; e++) {
        int off = (e - e0) * 256 + 2 * t;
        *(unsigned short*)(stg + off) = 0;
        *(unsigned short*)(stg + 32768 + off) = 0;
    }
    atomicAdd(&g_sums[0][t], csum);
    atomicAdd(&g_sums[1][t], csq);
    __syncthreads();
    uint4* outb = (uint4*)((char*)g_a1split + (size_t)blockIdx.x * 65536);
    const uint4* src = (const uint4*)stg;
    #pragma unroll
    for (int i = t; i < 2048; i += 128) {
        outb[i]        = src[i];
        outb[i + 2048] = src[i + 2048];
    }
}

// ---------------- bf16 tensor-core edge GEMMs (R4 mainloop, 256 thr / 8 warps) ----------------
// MODE 0 = E2, MODE 1 = E3
template <int MODE>
__global__ __launch_bounds__(256)
void tc_gemm(const float* __restrict__ ea, const int* __restrict__ eidx) {
    extern __shared__ char sm[];
    __shared__ float s_bias[128];
    const int tid = threadIdx.x;
    const int lane = tid & 31, wid = tid >> 5;
    const int wm = wid & 3, wn = wid >> 2;

    const unsigned sAh_u = smem_u32(sm);
    const unsigned sAl_u = sAh_u + 128 * ROWB;
    const unsigned sWh_u = sAh_u + 2 * 128 * ROWB;
    const unsigned sWl_u = sAh_u + 3 * 128 * ROWB;

    if (tid < 128) s_bias[tid] = (MODE == 0) ? g_b2p[tid] : g_b3p[tid];

    // ---- load tiles (gmem row-major [r][k] bf16, 256B rows) -> smem padded rows ----
    const uint4* Asrc = (MODE == 0 ? g_a1split : g_a2split) + (size_t)blockIdx.x * 4096;
    const uint4* Wsrc = (MODE == 0 ? g_W2s : g_W3s);
    {
        char* sAh = sm;
        char* sAl = sm + 128 * ROWB;
        char* sWh = sm + 2 * 128 * ROWB;
        char* sWl = sm + 3 * 128 * ROWB;
        #pragma unroll
        for (int i = tid; i < 2048; i += 256) {
            int row = i >> 4, ch = i & 15;
            *(uint4*)(sAh + row * ROWB + ch * 16) = Asrc[i];
            *(uint4*)(sAl + row * ROWB + ch * 16) = Asrc[i + 2048];
            *(uint4*)(sWh + row * ROWB + ch * 16) = Wsrc[i];
            *(uint4*)(sWl + row * ROWB + ch * 16) = Wsrc[i + 2048];
        }
    }
    __syncthreads();

    // ---- mma mainloop: 3 products (Ah*Wh + Al*Wh + Ah*Wl), K=128 ----
    const int laneRow = lane & 15;
    const unsigned laneK = (unsigned)((lane >> 4) << 4);
    const unsigned aoff = (unsigned)((wm * 32 + laneRow) * ROWB) + laneK;
    const unsigned woff = (unsigned)((wn * 64 + laneRow) * ROWB) + laneK;

    float acc[2][8][4];
    #pragma unroll
    for (int t = 0; t < 2; t++)
        #pragma unroll
        for (int n = 0; n < 8; n++)
            #pragma unroll
            for (int q = 0; q < 4; q++) acc[t][n][q] = 0.f;

    #pragma unroll 1
    for (int ks = 0; ks < 8; ks++) {
        unsigned kb = (unsigned)(ks * 32);
        unsigned ah[2][4], al[2][4], bw[4][4];
        LDMX4(ah[0], sAh_u + aoff + kb);
        LDMX4(ah[1], sAh_u + aoff + 16 * ROWB + kb);
        LDMX4(al[0], sAl_u + aoff + kb);
        LDMX4(al[1], sAl_u + aoff + 16 * ROWB + kb);
        #pragma unroll
        for (int p = 0; p < 4; p++)
            LDMX4(bw[p], sWh_u + woff + p * 16 * ROWB + kb);
        #pragma unroll
        for (int t = 0; t < 2; t++)
            #pragma unroll
            for (int p = 0; p < 4; p++) {
                MMA_BF16(acc[t][2 * p],     ah[t][0], ah[t][1], ah[t][2], ah[t][3], bw[p][0], bw[p][2]);
                MMA_BF16(acc[t][2 * p + 1], ah[t][0], ah[t][1], ah[t][2], ah[t][3], bw[p][1], bw[p][3]);
            }
        #pragma unroll
        for (int t = 0; t < 2; t++)
            #pragma unroll
            for (int p = 0; p < 4; p++) {
                MMA_BF16(acc[t][2 * p],     al[t][0], al[t][1], al[t][2], al[t][3], bw[p][0], bw[p][2]);
                MMA_BF16(acc[t][2 * p + 1], al[t][0], al[t][1], al[t][2], al[t][3], bw[p][1], bw[p][3]);
            }
        #pragma unroll
        for (int p = 0; p < 4; p++)
            LDMX4(bw[p], sWl_u + woff + p * 16 * ROWB + kb);
        #pragma unroll
        for (int t = 0; t < 2; t++)
            #pragma unroll
            for (int p = 0; p < 4; p++) {
                MMA_BF16(acc[t][2 * p],     ah[t][0], ah[t][1], ah[t][2], ah[t][3], bw[p][0], bw[p][2]);
                MMA_BF16(acc[t][2 * p + 1], ah[t][0], ah[t][1], ah[t][2], ah[t][3], bw[p][1], bw[p][3]);
            }
    }
    __syncthreads();   // done reading smem tiles; reuse as fp32 stage

    // ---- stage D into smem fp32 [128][132] ----
    float* sF = (float*)sm;
    {
        int mr = lane >> 2;
        int nc = 2 * (lane & 3);
        #pragma unroll
        for (int t = 0; t < 2; t++) {
            int row = wm * 32 + t * 16 + mr;
            #pragma unroll
            for (int nt = 0; nt < 8; nt++) {
                int col = wn * 64 + nt * 8 + nc;
                sF[row * 132 + col]           = acc[t][nt][0];
                sF[row * 132 + col + 1]       = acc[t][nt][1];
                sF[(row + 8) * 132 + col]     = acc[t][nt][2];
                sF[(row + 8) * 132 + col + 1] = acc[t][nt][3];
            }
        }
    }
    __syncthreads();

    if (MODE == 0) {
        // Row pass: bias + lrelu, write back to sF, pack bf16 hi/lo, coalesced uint4 stores
        int rl = tid >> 1, h = tid & 1;
        long gbase = (long)blockIdx.x * 128;
        bool valid = (gbase + rl) < NEDGE;
        char* outb = (char*)g_a2split + (size_t)blockIdx.x * 65536;
        uint4* dh = (uint4*)(outb + rl * 256 + h * 128);
        uint4* dl = (uint4*)(outb + 32768 + rl * 256 + h * 128);
        float* fr = sF + rl * 132 + h * 64;
        const float* bp = s_bias + h * 64;
        #pragma unroll
        for (int q = 0; q < 8; q++) {          // 8 uint4 per 64-col half (8 cols each)
            unsigned ph[4], pl[4];
            #pragma unroll
            for (int j = 0; j < 4; j++) {
                int c = q * 8 + j * 2;
                float v0 = fr[c]     + bp[c];
                float v1 = fr[c + 1] + bp[c + 1];
                v0 = (v0 >= 0.f) ? v0 : 0.01f * v0;
                v1 = (v1 >= 0.f) ? v1 : 0.01f * v1;
                if (!valid) { v0 = 0.f; v1 = 0.f; }
                fr[c] = v0; fr[c + 1] = v1;
                float h0 = __bfloat162float(__float2bfloat16_rn(v0));
                float h1 = __bfloat162float(__float2bfloat16_rn(v1));
                ph[j] = pack2bf(h0, h1);
                pl[j] = pack2bf(v0 - h0, v1 - h1);
            }
            dh[q] = make_uint4(ph[0], ph[1], ph[2], ph[3]);
            dl[q] = make_uint4(pl[0], pl[1], pl[2], pl[3]);
        }
        __syncthreads();
        // Column pass for stats (invalid rows already zeroed in sF)
        {
            int c = tid & 127, h2 = tid >> 7;
            float s0 = 0.f, s1 = 0.f;
            #pragma unroll 8
            for (int r = 0; r < 64; r++) {
                float v = sF[(h2 * 64 + r) * 132 + c];
                s0 += v; s1 += v * v;
            }
            atomicAdd(&g_sums[2][c], s0);
            atomicAdd(&g_sums[3][c], s1);
        }
    } else {
        // z[dst] += coeff * (D + b3p) * xd[src]
        int rt = tid >> 1, h = tid & 1;
        long grow = (long)blockIdx.x * 128 + rt;
        if (grow < NEDGE) {
            int s_ = eidx[grow], d_ = eidx[NEDGE + grow];
            float coeff = cosf(1.5707963267948966f * ea[grow * 4 + 3]);
            const float4* xp = (const float4*)(g_xd + (size_t)s_ * 128) + h * 16;
            float* zp = g_z + (size_t)d_ * 128 + h * 64;
            const float* fr = sF + rt * 132 + h * 64;
            const float* bp = s_bias + h * 64;
            #pragma unroll
            for (int q = 0; q < 16; q++) {
                float4 xv = xp[q];
                float v0 = coeff * (fr[4 * q + 0] + bp[4 * q + 0]) * xv.x;
                float v1 = coeff * (fr[4 * q + 1] + bp[4 * q + 1]) * xv.y;
                float v2 = coeff * (fr[4 * q + 2] + bp[4 * q + 2]) * xv.z;
                float v3 = coeff * (fr[4 * q + 3] + bp[4 * q + 3]) * xv.w;
                asm volatile("red.global.add.v4.f32 [%0], {%1,%2,%3,%4};"
                             :: "l"(zp + 4 * q), "f"(v0), "f"(v1), "f"(v2), "f"(v3) : "memory");
            }
        }
    }
}

// ---------------- SIMT node GEMMs (128x128 tile, 256 threads) ----------------
enum { M_XD = 0, M_PLAIN = 1, M_N1 = 4, M_OUT = 5 };

template <int MODE>
__global__ __launch_bounds__(256)
void gemm_kernel(const float* __restrict__ A, const float* __restrict__ Wparam,
                 const float* __restrict__ biasExt, const float* __restrict__ x,
                 const float* __restrict__ vparam, float* __restrict__ outp, int M) {
    __shared__ float As[16][132];
    __shared__ float Ws[16][132];

    const int tid = threadIdx.x;
    const int blockRow = blockIdx.x * 128;
    const int tr = tid >> 4;
    const int tc = tid & 15;
    const int c0 = tc * 8;

    const float* W = (MODE == M_OUT) ? g_Wn2p : Wparam;
    const float* bias = (MODE == M_OUT) ? g_bn2p : biasExt;
    const float* Aeff = (MODE == M_N1) ? g_z : (MODE == M_OUT) ? g_an : A;

    const int lr = tid >> 1;
    const int lh = (tid & 1) * 8;
    const float* arow;
    {
        int r = blockRow + lr;
        if (r > M - 1) r = M - 1;
        arow = Aeff + (size_t)r * 128;
    }

    float acc[8][8];
    #pragma unroll
    for (int i = 0; i < 8; i++)
        #pragma unroll
        for (int j = 0; j < 8; j++) acc[i][j] = 0.f;

    #pragma unroll 1
    for (int k0 = 0; k0 < 128; k0 += 16) {
        const float* ap = arow + k0 + lh;
        float4 a0 = *(const float4*)ap;
        float4 a1 = *(const float4*)(ap + 4);
        int krow = k0 + tr;
        float4 b0 = *(const float4*)(W + (size_t)krow * 128 + c0);
        float4 b1 = *(const float4*)(W + (size_t)krow * 128 + c0 + 4);

        __syncthreads();
        As[lh + 0][lr] = a0.x; As[lh + 1][lr] = a0.y;
        As[lh + 2][lr] = a0.z; As[lh + 3][lr] = a0.w;
        As[lh + 4][lr] = a1.x; As[lh + 5][lr] = a1.y;
        As[lh + 6][lr] = a1.z; As[lh + 7][lr] = a1.w;
        *(float4*)&Ws[tr][c0]     = b0;
        *(float4*)&Ws[tr][c0 + 4] = b1;
        __syncthreads();

        #pragma unroll
        for (int kk = 0; kk < 16; kk++) {
            float af[8], bf[8];
            *(float4*)(af)     = *(const float4*)&As[kk][tr * 8];
            *(float4*)(af + 4) = *(const float4*)&As[kk][tr * 8 + 4];
            *(float4*)(bf)     = *(const float4*)&Ws[kk][c0];
            *(float4*)(bf + 4) = *(const float4*)&Ws[kk][c0 + 4];
            #pragma unroll
            for (int i = 0; i < 8; i++)
                #pragma unroll
                for (int j = 0; j < 8; j++)
                    acc[i][j] += af[i] * bf[j];
        }
    }
    __syncthreads();

    float bj[8];
    #pragma unroll
    for (int j = 0; j < 8; j++) bj[j] = (MODE == M_PLAIN) ? 0.f : bias[c0 + j];

    if (MODE == M_PLAIN) {
        #pragma unroll
        for (int i = 0; i < 8; i++) {
            int r = blockRow + tr * 8 + i;
            if (r >= M) break;
            float* dp = outp + (size_t)r * 128 + c0;
            *(float4*)dp       = make_float4(acc[i][0], acc[i][1], acc[i][2], acc[i][3]);
            *(float4*)(dp + 4) = make_float4(acc[i][4], acc[i][5], acc[i][6], acc[i][7]);
        }
        return;
    }
    if (MODE == M_XD) {
        float vj[8];
        #pragma unroll
        for (int j = 0; j < 8; j++) vj[j] = vparam[c0 + j];
        #pragma unroll
        for (int i = 0; i < 8; i++) {
            int r = blockRow + tr * 8 + i;
            if (r >= M) break;
            float vals[8], zv[8];
            #pragma unroll
            for (int j = 0; j < 8; j++) { vals[j] = acc[i][j] + bj[j]; zv[j] = vj[j] * vals[j]; }
            float* dp = g_xd + (size_t)r * 128 + c0;
            *(float4*)dp       = make_float4(vals[0], vals[1], vals[2], vals[3]);
            *(float4*)(dp + 4) = make_float4(vals[4], vals[5], vals[6], vals[7]);
            float* zp = g_z + (size_t)r * 128 + c0;
            *(float4*)zp       = make_float4(zv[0], zv[1], zv[2], zv[3]);
            *(float4*)(zp + 4) = make_float4(zv[4], zv[5], zv[6], zv[7]);
        }
        return;
    }
    if (MODE == M_OUT) {
        #pragma unroll
        for (int i = 0; i < 8; i++) {
            int r = blockRow + tr * 8 + i;
            if (r >= M) break;
            const float* xp = x + (size_t)r * 128 + c0;
            float4 x0 = *(const float4*)xp;
            float4 x1 = *(const float4*)(xp + 4);
            float* dp = outp + (size_t)r * 128 + c0;
            *(float4*)dp = make_float4(acc[i][0] + bj[0] + x0.x, acc[i][1] + bj[1] + x0.y,
                                       acc[i][2] + bj[2] + x0.z, acc[i][3] + bj[3] + x0.w);
            *(float4*)(dp + 4) = make_float4(acc[i][4] + bj[4] + x1.x, acc[i][5] + bj[5] + x1.y,
                                             acc[i][6] + bj[6] + x1.z, acc[i][7] + bj[7] + x1.w);
        }
        return;
    }
    // M_N1: lrelu + store + stats
    {
        float csum[8], csq[8];
        #pragma unroll
        for (int j = 0; j < 8; j++) { csum[j] = 0.f; csq[j] = 0.f; }
        #pragma unroll 1
        for (int i = 0; i < 8; i++) {
            int r = blockRow + tr * 8 + i;
            if (r >= M) break;
            float vals[8];
            #pragma unroll
            for (int j = 0; j < 8; j++) {
                float v_ = acc[i][j] + bj[j];
                v_ = (v_ >= 0.f) ? v_ : 0.01f * v_;
                vals[j] = v_; csum[j] += v_; csq[j] += v_ * v_;
            }
            float* dp = g_an + (size_t)r * 128 + c0;
            *(float4*)dp       = make_float4(vals[0], vals[1], vals[2], vals[3]);
            *(float4*)(dp + 4) = make_float4(vals[4], vals[5], vals[6], vals[7]);
        }
        #pragma unroll
        for (int j = 0; j < 8; j++) As[tr][c0 + j] = csum[j];
        __syncthreads();
        if (tid < 128) {
            float s = 0.f;
            #pragma unroll
            for (int t = 0; t < 16; t++) s += As[t][tid];
            atomicAdd(&g_sums[4][tid], s);
        }
        __syncthreads();
        #pragma unroll
        for (int j = 0; j < 8; j++) As[tr][c0 + j] = csq[j];
        __syncthreads();
        if (tid < 128) {
            float s = 0.f;
            #pragma unroll
            for (int t = 0; t < 16; t++) s += As[t][tid];
            atomicAdd(&g_sums[5][tid], s);
        }
    }
}

// ---------------- launcher ----------------
extern "C" void kernel_launch(void* const* d_in, const int* in_sizes, int n_in,
                              void* d_out, int out_size) {
    const float* x    = (const float*)d_in[0];
    const float* ea   = (const float*)d_in[1];
    const int*   eidx = (const int*)  d_in[2];
    const float* Wb   = (const float*)d_in[3];
    const float* bb   = (const float*)d_in[4];
    const float* We1  = (const float*)d_in[5];
    const float* be1  = (const float*)d_in[6];
    const float* ge1  = (const float*)d_in[7];
    const float* bte1 = (const float*)d_in[8];
    const float* We2  = (const float*)d_in[9];
    const float* be2  = (const float*)d_in[10];
    const float* ge2  = (const float*)d_in[11];
    const float* bte2 = (const float*)d_in[12];
    const float* We3  = (const float*)d_in[13];
    const float* be3  = (const float*)d_in[14];
    const float* Wd   = (const float*)d_in[15];
    const float* bd   = (const float*)d_in[16];
    const float* v    = (const float*)d_in[17];
    const float* Wn1  = (const float*)d_in[18];
    const float* bn1  = (const float*)d_in[19];
    const float* gn   = (const float*)d_in[20];
    const float* btn  = (const float*)d_in[21];
    const float* Wn2  = (const float*)d_in[22];
    const float* bn2  = (const float*)d_in[23];
    float* outp = (float*)d_out;

    const int gridN = (NNODE + 127) / 128;

    float* d_xtop; cudaGetSymbolAddress((void**)&d_xtop, g_xtop);
    float* d_xbot; cudaGetSymbolAddress((void**)&d_xbot, g_xbot);
    float* d_W2p;  cudaGetSymbolAddress((void**)&d_W2p, g_W2p);
    float* d_W3p;  cudaGetSymbolAddress((void**)&d_W3p, g_W3p);
    char*  d_W2s;  cudaGetSymbolAddress((void**)&d_W2s, g_W2s);
    char*  d_W3s;  cudaGetSymbolAddress((void**)&d_W3s, g_W3s);

    cudaFuncSetAttribute(tc_gemm<0>, cudaFuncAttributeMaxDynamicSharedMemorySize, TCSM);
    cudaFuncSetAttribute(tc_gemm<1>, cudaFuncAttributeMaxDynamicSharedMemorySize, TCSM);
    cudaFuncSetAttribute(e1_fuse_kernel, cudaFuncAttributeMaxDynamicSharedMemorySize, 65536);

    zero_stats<<<1, 768>>>();
    wbwe1_kernel<<<200, 128>>>(Wb, We1);
    cvec_kernel<<<1, 128>>>(bb, We1, be1);
    table_kernel<<<4 * GTAB, 128>>>();

    gemm_kernel<M_XD><<<gridN, 256>>>(x, Wd, bd, nullptr, v, nullptr, NNODE);
    gemm_kernel<M_PLAIN><<<gridN, 256>>>(x, We1,             nullptr, nullptr, nullptr, d_xtop, NNODE);
    gemm_kernel<M_PLAIN><<<gridN, 256>>>(x, We1 + 256 * 128, nullptr, nullptr, nullptr, d_xbot, NNODE);

    e1_fuse_kernel<<<NTILE, 128, 65536>>>(ea, eidx);
    fold_kernel<<<129, 128>>>(0, 1.0f / NEDGE, ge1, bte1, We2, be2);
    pack_kernel<<<128, 128>>>(d_W2p, d_W2s);

    tc_gemm<0><<<NTILE, 256, TCSM>>>(ea, eidx);
    fold_kernel<<<129, 128>>>(2, 1.0f / NEDGE, ge2, bte2, We3, be3);
    pack_kernel<<<128, 128>>>(d_W3p, d_W3s);

    tc_gemm<1><<<NTILE, 256, TCSM>>>(ea, eidx);

    gemm_kernel<M_N1><<<gridN, 256>>>(nullptr, Wn1, bn1, nullptr, nullptr, nullptr, NNODE);
    fold_kernel<<<129, 128>>>(4, 1.0f / NNODE, gn, btn, Wn2, bn2);
    gemm_kernel<M_OUT><<<gridN, 256>>>(nullptr, nullptr, nullptr, x, nullptr, outp, NNODE);
}

// round 10
// speedup vs baseline: 1.5140x; 1.4899x over previous
#include <cuda_runtime.h>
#include <cuda_bf16.h>

#define NNODE 50000
#define NEDGE 300000
#define GTAB  1024
#define EPSBN 1e-5f
#define NTILE 2344              // ceil(NEDGE/128)
#define ROWB  272               // padded smem row bytes (136 bf16)
#define TCSM  (4 * 128 * ROWB)  // 139264: Ah|Al|Wh|Wl

// ---------------- scratch (device globals; no allocation) ----------------
__device__ uint4 g_a1split[(size_t)NTILE * 4096];  // per tile: 32KB bf16-hi | 32KB bf16-lo, row-major [m][k] 256B rows
__device__ uint4 g_a2split[(size_t)NTILE * 4096];
__device__ uint4 g_W2s[4096];                      // 64KB: W^T [n][k] hi | lo
__device__ uint4 g_W3s[4096];
__device__ float g_xd[(size_t)NNODE * 128];
__device__ float g_z [(size_t)NNODE * 128];
__device__ float g_an[(size_t)NNODE * 128];
__device__ float g_xtop[(size_t)NNODE * 128];
__device__ float g_xbot[(size_t)NNODE * 128];
__device__ float g_tab[4 * GTAB * 128];
__device__ float g_WbWe1[200 * 128];
__device__ float g_cvec[128];
__device__ float g_W2p[128 * 128];  __device__ float g_b2p[128];
__device__ float g_W3p[128 * 128];  __device__ float g_b3p[128];
__device__ float g_Wn2p[128 * 128]; __device__ float g_bn2p[128];
__device__ float g_sums[6][128];

// ---------------- helpers ----------------
__device__ __forceinline__ unsigned smem_u32(const void* p) {
    unsigned a;
    asm("{ .reg .u64 t; cvta.to.shared.u64 t, %1; cvt.u32.u64 %0, t; }" : "=r"(a) : "l"(p));
    return a;
}
#define LDMX4(r, addr)                                                         \
    asm volatile("ldmatrix.sync.aligned.m8n8.x4.shared.b16 {%0,%1,%2,%3}, [%4];" \
                 : "=r"((r)[0]), "=r"((r)[1]), "=r"((r)[2]), "=r"((r)[3])      \
                 : "r"(addr))
#define MMA_BF16(d, a0, a1, a2, a3, b0, b1)                                    \
    asm volatile("mma.sync.aligned.m16n8k16.row.col.f32.bf16.bf16.f32 "        \
                 "{%0,%1,%2,%3}, {%4,%5,%6,%7}, {%8,%9}, {%0,%1,%2,%3};"       \
                 : "+f"((d)[0]), "+f"((d)[1]), "+f"((d)[2]), "+f"((d)[3])      \
                 : "r"(a0), "r"(a1), "r"(a2), "r"(a3), "r"(b0), "r"(b1))
static __device__ __forceinline__ unsigned pack2bf(float a, float b) {
    return ((unsigned)__bfloat16_as_ushort(__float2bfloat16_rn(b)) << 16)
         |  (unsigned)__bfloat16_as_ushort(__float2bfloat16_rn(a));
}

// ---------------- tiny prep kernels ----------------
__global__ void zero_stats() { ((float*)g_sums)[threadIdx.x] = 0.0f; }

__global__ void wbwe1_kernel(const float* __restrict__ Wb, const float* __restrict__ We1) {
    int r = blockIdx.x, n = threadIdx.x;
    float acc = 0.f;
    #pragma unroll 8
    for (int k = 0; k < 128; k++) acc += Wb[r * 128 + k] * We1[(128 + k) * 128 + n];
    g_WbWe1[r * 128 + n] = acc;
}

__global__ void cvec_kernel(const float* __restrict__ bb, const float* __restrict__ We1,
                            const float* __restrict__ be1) {
    int n = threadIdx.x;
    float acc = be1[n];
    #pragma unroll 8
    for (int k = 0; k < 128; k++) acc += bb[k] * We1[(128 + k) * 128 + n];
    g_cvec[n] = acc;
}

__global__ void table_kernel() {
    __shared__ float gs[64];
    int b = blockIdx.x;
    int c = b >> 10;
    int gi = b & (GTAB - 1);
    float u = (float)gi * (1.0f / (GTAB - 1));
    int tid = threadIdx.x;
    if (tid < 50) {
        float d = u - (float)tid * (1.0f / 49.0f);
        gs[tid] = __expf(-d * d * 1250.0f);
    }
    __syncthreads();
    float acc = 0.f;
    #pragma unroll
    for (int j = 0; j < 50; j++) acc += gs[j] * g_WbWe1[(c * 50 + j) * 128 + tid];
    g_tab[b * 128 + tid] = acc;
}

__global__ void fold_kernel(int sidx, float invM,
                            const float* __restrict__ gamma, const float* __restrict__ beta,
                            const float* __restrict__ Wsrc, const float* __restrict__ be) {
    float* Wdst = (sidx == 0) ? g_W2p : (sidx == 2) ? g_W3p : g_Wn2p;
    float* bdst = (sidx == 0) ? g_b2p : (sidx == 2) ? g_b3p : g_bn2p;
    int n = threadIdx.x;
    if (blockIdx.x < 128) {
        int k = blockIdx.x;
        float m = g_sums[sidx][k] * invM;
        float var = g_sums[sidx + 1][k] * invM - m * m;
        float s = gamma[k] * rsqrtf(var + EPSBN);
        Wdst[k * 128 + n] = s * Wsrc[k * 128 + n];
    } else {
        float acc = be[n];
        for (int k = 0; k < 128; k++) {
            float m = g_sums[sidx][k] * invM;
            float var = g_sums[sidx + 1][k] * invM - m * m;
            float s = gamma[k] * rsqrtf(var + EPSBN);
            acc += (beta[k] - m * s) * Wsrc[k * 128 + n];
        }
        bdst[n] = acc;
    }
}

// Pack W^T ([n][k] row-major, 256B rows) into bf16 hi/lo staging (64KB)
__global__ void pack_kernel(const float* __restrict__ Wp, char* __restrict__ Ws) {
    int n = blockIdx.x, k = threadIdx.x;
    float v = Wp[k * 128 + n];
    float h = __bfloat162float(__float2bfloat16_rn(v));
    int off = n * 256 + 2 * k;
    *(unsigned short*)(Ws + off)         = __bfloat16_as_ushort(__float2bfloat16_rn(h));
    *(unsigned short*)(Ws + 32768 + off) = __bfloat16_as_ushort(__float2bfloat16_rn(v - h));
}

// ---------------- fused E1 -> bf16 hi/lo tiles (zero smem, direct stores, high occupancy) ----------------
__global__ __launch_bounds__(128)
void e1_fuse_kernel(const float* __restrict__ ea, const int* __restrict__ eidx) {
    int t = threadIdx.x;
    int e0 = blockIdx.x * 128;
    char* tb = (char*)g_a1split + (size_t)blockIdx.x * 65536;
    float cv = g_cvec[t];
    float csum = 0.f, csq = 0.f;
    int eend = e0 + 128;
    if (eend > NEDGE) eend = NEDGE;
    #pragma unroll 4
    for (int e = e0; e < eend; e++) {
        int s = __ldg(eidx + e);
        int d = __ldg(eidx + NEDGE + e);
        float4 eav = __ldg((const float4*)ea + e);
        float val = g_xtop[(size_t)s * 128 + t] + g_xbot[(size_t)d * 128 + t] + cv;
        float fa[4] = {eav.x, eav.y, eav.z, eav.w};
        #pragma unroll
        for (int c = 0; c < 4; c++) {
            float p = fa[c] * (float)(GTAB - 1);
            int i0 = (int)p;
            if (i0 < 0) i0 = 0;
            if (i0 > GTAB - 2) i0 = GTAB - 2;
            float w = p - (float)i0;
            const float* t0 = g_tab + ((size_t)(c * GTAB + i0) * 128 + t);
            float u = t0[0], v2 = t0[128];
            val += u + w * (v2 - u);
        }
        val = (val >= 0.f) ? val : 0.01f * val;
        csum += val; csq += val * val;
        float h = __bfloat162float(__float2bfloat16_rn(val));
        int off = (e - e0) * 256 + 2 * t;
        *(unsigned short*)(tb + off)         = __bfloat16_as_ushort(__float2bfloat16_rn(h));
        *(unsigned short*)(tb + 32768 + off) = __bfloat16_as_ushort(__float2bfloat16_rn(val - h));
    }
    for (int e = eend; e < e0 + 128; e++) {   // zero tail rows
        int off = (e - e0) * 256 + 2 * t;
        *(unsigned short*)(tb + off) = 0;
        *(unsigned short*)(tb + 32768 + off) = 0;
    }
    atomicAdd(&g_sums[0][t], csum);
    atomicAdd(&g_sums[1][t], csq);
}

// ---------------- bf16 tensor-core edge GEMMs (R4 mainloop, 256 thr / 8 warps) ----------------
// MODE 0 = E2, MODE 1 = E3
template <int MODE>
__global__ __launch_bounds__(256)
void tc_gemm(const float* __restrict__ ea, const int* __restrict__ eidx) {
    extern __shared__ char sm[];
    __shared__ float s_bias[128];
    const int tid = threadIdx.x;
    const int lane = tid & 31, wid = tid >> 5;
    const int wm = wid & 3, wn = wid >> 2;

    const unsigned sAh_u = smem_u32(sm);
    const unsigned sAl_u = sAh_u + 128 * ROWB;
    const unsigned sWh_u = sAh_u + 2 * 128 * ROWB;
    const unsigned sWl_u = sAh_u + 3 * 128 * ROWB;

    if (tid < 128) s_bias[tid] = (MODE == 0) ? g_b2p[tid] : g_b3p[tid];

    // ---- load tiles (gmem row-major [r][k] bf16, 256B rows) -> smem padded rows ----
    const uint4* Asrc = (MODE == 0 ? g_a1split : g_a2split) + (size_t)blockIdx.x * 4096;
    const uint4* Wsrc = (MODE == 0 ? g_W2s : g_W3s);
    {
        char* sAh = sm;
        char* sAl = sm + 128 * ROWB;
        char* sWh = sm + 2 * 128 * ROWB;
        char* sWl = sm + 3 * 128 * ROWB;
        #pragma unroll
        for (int i = tid; i < 2048; i += 256) {
            int row = i >> 4, ch = i & 15;
            *(uint4*)(sAh + row * ROWB + ch * 16) = Asrc[i];
            *(uint4*)(sAl + row * ROWB + ch * 16) = Asrc[i + 2048];
            *(uint4*)(sWh + row * ROWB + ch * 16) = Wsrc[i];
            *(uint4*)(sWl + row * ROWB + ch * 16) = Wsrc[i + 2048];
        }
    }
    __syncthreads();

    // ---- mma mainloop: 3 products (Ah*Wh + Al*Wh + Ah*Wl), K=128 ----
    const int laneRow = lane & 15;
    const unsigned laneK = (unsigned)((lane >> 4) << 4);
    const unsigned aoff = (unsigned)((wm * 32 + laneRow) * ROWB) + laneK;
    const unsigned woff = (unsigned)((wn * 64 + laneRow) * ROWB) + laneK;

    float acc[2][8][4];
    #pragma unroll
    for (int t = 0; t < 2; t++)
        #pragma unroll
        for (int n = 0; n < 8; n++)
            #pragma unroll
            for (int q = 0; q < 4; q++) acc[t][n][q] = 0.f;

    #pragma unroll 1
    for (int ks = 0; ks < 8; ks++) {
        unsigned kb = (unsigned)(ks * 32);
        unsigned ah[2][4], al[2][4], bw[4][4];
        LDMX4(ah[0], sAh_u + aoff + kb);
        LDMX4(ah[1], sAh_u + aoff + 16 * ROWB + kb);
        LDMX4(al[0], sAl_u + aoff + kb);
        LDMX4(al[1], sAl_u + aoff + 16 * ROWB + kb);
        #pragma unroll
        for (int p = 0; p < 4; p++)
            LDMX4(bw[p], sWh_u + woff + p * 16 * ROWB + kb);
        #pragma unroll
        for (int t = 0; t < 2; t++)
            #pragma unroll
            for (int p = 0; p < 4; p++) {
                MMA_BF16(acc[t][2 * p],     ah[t][0], ah[t][1], ah[t][2], ah[t][3], bw[p][0], bw[p][2]);
                MMA_BF16(acc[t][2 * p + 1], ah[t][0], ah[t][1], ah[t][2], ah[t][3], bw[p][1], bw[p][3]);
            }
        #pragma unroll
        for (int t = 0; t < 2; t++)
            #pragma unroll
            for (int p = 0; p < 4; p++) {
                MMA_BF16(acc[t][2 * p],     al[t][0], al[t][1], al[t][2], al[t][3], bw[p][0], bw[p][2]);
                MMA_BF16(acc[t][2 * p + 1], al[t][0], al[t][1], al[t][2], al[t][3], bw[p][1], bw[p][3]);
            }
        #pragma unroll
        for (int p = 0; p < 4; p++)
            LDMX4(bw[p], sWl_u + woff + p * 16 * ROWB + kb);
        #pragma unroll
        for (int t = 0; t < 2; t++)
            #pragma unroll
            for (int p = 0; p < 4; p++) {
                MMA_BF16(acc[t][2 * p],     ah[t][0], ah[t][1], ah[t][2], ah[t][3], bw[p][0], bw[p][2]);
                MMA_BF16(acc[t][2 * p + 1], ah[t][0], ah[t][1], ah[t][2], ah[t][3], bw[p][1], bw[p][3]);
            }
    }
    __syncthreads();   // done reading smem tiles; reuse as fp32 stage

    // ---- stage D into smem fp32 [128][132] ----
    float* sF = (float*)sm;
    {
        int mr = lane >> 2;
        int nc = 2 * (lane & 3);
        #pragma unroll
        for (int t = 0; t < 2; t++) {
            int row = wm * 32 + t * 16 + mr;
            #pragma unroll
            for (int nt = 0; nt < 8; nt++) {
                int col = wn * 64 + nt * 8 + nc;
                sF[row * 132 + col]           = acc[t][nt][0];
                sF[row * 132 + col + 1]       = acc[t][nt][1];
                sF[(row + 8) * 132 + col]     = acc[t][nt][2];
                sF[(row + 8) * 132 + col + 1] = acc[t][nt][3];
            }
        }
    }
    __syncthreads();

    if (MODE == 0) {
        // Row pass: bias + lrelu, write back to sF, pack bf16 hi/lo, coalesced uint4 stores
        int rl = tid >> 1, h = tid & 1;
        long gbase = (long)blockIdx.x * 128;
        bool valid = (gbase + rl) < NEDGE;
        char* outb = (char*)g_a2split + (size_t)blockIdx.x * 65536;
        uint4* dh = (uint4*)(outb + rl * 256 + h * 128);
        uint4* dl = (uint4*)(outb + 32768 + rl * 256 + h * 128);
        float* fr = sF + rl * 132 + h * 64;
        const float* bp = s_bias + h * 64;
        #pragma unroll
        for (int q = 0; q < 8; q++) {          // 8 uint4 per 64-col half (8 cols each)
            unsigned ph[4], pl[4];
            #pragma unroll
            for (int j = 0; j < 4; j++) {
                int c = q * 8 + j * 2;
                float v0 = fr[c]     + bp[c];
                float v1 = fr[c + 1] + bp[c + 1];
                v0 = (v0 >= 0.f) ? v0 : 0.01f * v0;
                v1 = (v1 >= 0.f) ? v1 : 0.01f * v1;
                if (!valid) { v0 = 0.f; v1 = 0.f; }
                fr[c] = v0; fr[c + 1] = v1;
                float h0 = __bfloat162float(__float2bfloat16_rn(v0));
                float h1 = __bfloat162float(__float2bfloat16_rn(v1));
                ph[j] = pack2bf(h0, h1);
                pl[j] = pack2bf(v0 - h0, v1 - h1);
            }
            dh[q] = make_uint4(ph[0], ph[1], ph[2], ph[3]);
            dl[q] = make_uint4(pl[0], pl[1], pl[2], pl[3]);
        }
        __syncthreads();
        // Column pass for stats (invalid rows already zeroed in sF)
        {
            int c = tid & 127, h2 = tid >> 7;
            float s0 = 0.f, s1 = 0.f;
            #pragma unroll 8
            for (int r = 0; r < 64; r++) {
                float v = sF[(h2 * 64 + r) * 132 + c];
                s0 += v; s1 += v * v;
            }
            atomicAdd(&g_sums[2][c], s0);
            atomicAdd(&g_sums[3][c], s1);
        }
    } else {
        // z[dst] += coeff * (D + b3p) * xd[src]
        int rt = tid >> 1, h = tid & 1;
        long grow = (long)blockIdx.x * 128 + rt;
        if (grow < NEDGE) {
            int s_ = eidx[grow], d_ = eidx[NEDGE + grow];
            float coeff = cosf(1.5707963267948966f * ea[grow * 4 + 3]);
            const float4* xp = (const float4*)(g_xd + (size_t)s_ * 128) + h * 16;
            float* zp = g_z + (size_t)d_ * 128 + h * 64;
            const float* fr = sF + rt * 132 + h * 64;
            const float* bp = s_bias + h * 64;
            #pragma unroll
            for (int q = 0; q < 16; q++) {
                float4 xv = xp[q];
                float v0 = coeff * (fr[4 * q + 0] + bp[4 * q + 0]) * xv.x;
                float v1 = coeff * (fr[4 * q + 1] + bp[4 * q + 1]) * xv.y;
                float v2 = coeff * (fr[4 * q + 2] + bp[4 * q + 2]) * xv.z;
                float v3 = coeff * (fr[4 * q + 3] + bp[4 * q + 3]) * xv.w;
                asm volatile("red.global.add.v4.f32 [%0], {%1,%2,%3,%4};"
                             :: "l"(zp + 4 * q), "f"(v0), "f"(v1), "f"(v2), "f"(v3) : "memory");
            }
        }
    }
}

// ---------------- SIMT node GEMMs (128x128 tile, 256 threads) ----------------
enum { M_XD = 0, M_PLAIN = 1, M_N1 = 4, M_OUT = 5 };

template <int MODE>
__global__ __launch_bounds__(256)
void gemm_kernel(const float* __restrict__ A, const float* __restrict__ Wparam,
                 const float* __restrict__ biasExt, const float* __restrict__ x,
                 const float* __restrict__ vparam, float* __restrict__ outp, int M) {
    __shared__ float As[16][132];
    __shared__ float Ws[16][132];

    const int tid = threadIdx.x;
    const int blockRow = blockIdx.x * 128;
    const int tr = tid >> 4;
    const int tc = tid & 15;
    const int c0 = tc * 8;

    const float* W = (MODE == M_OUT) ? g_Wn2p : Wparam;
    const float* bias = (MODE == M_OUT) ? g_bn2p : biasExt;
    const float* Aeff = (MODE == M_N1) ? g_z : (MODE == M_OUT) ? g_an : A;

    const int lr = tid >> 1;
    const int lh = (tid & 1) * 8;
    const float* arow;
    {
        int r = blockRow + lr;
        if (r > M - 1) r = M - 1;
        arow = Aeff + (size_t)r * 128;
    }

    float acc[8][8];
    #pragma unroll
    for (int i = 0; i < 8; i++)
        #pragma unroll
        for (int j = 0; j < 8; j++) acc[i][j] = 0.f;

    #pragma unroll 1
    for (int k0 = 0; k0 < 128; k0 += 16) {
        const float* ap = arow + k0 + lh;
        float4 a0 = *(const float4*)ap;
        float4 a1 = *(const float4*)(ap + 4);
        int krow = k0 + tr;
        float4 b0 = *(const float4*)(W + (size_t)krow * 128 + c0);
        float4 b1 = *(const float4*)(W + (size_t)krow * 128 + c0 + 4);

        __syncthreads();
        As[lh + 0][lr] = a0.x; As[lh + 1][lr] = a0.y;
        As[lh + 2][lr] = a0.z; As[lh + 3][lr] = a0.w;
        As[lh + 4][lr] = a1.x; As[lh + 5][lr] = a1.y;
        As[lh + 6][lr] = a1.z; As[lh + 7][lr] = a1.w;
        *(float4*)&Ws[tr][c0]     = b0;
        *(float4*)&Ws[tr][c0 + 4] = b1;
        __syncthreads();

        #pragma unroll
        for (int kk = 0; kk < 16; kk++) {
            float af[8], bf[8];
            *(float4*)(af)     = *(const float4*)&As[kk][tr * 8];
            *(float4*)(af + 4) = *(const float4*)&As[kk][tr * 8 + 4];
            *(float4*)(bf)     = *(const float4*)&Ws[kk][c0];
            *(float4*)(bf + 4) = *(const float4*)&Ws[kk][c0 + 4];
            #pragma unroll
            for (int i = 0; i < 8; i++)
                #pragma unroll
                for (int j = 0; j < 8; j++)
                    acc[i][j] += af[i] * bf[j];
        }
    }
    __syncthreads();

    float bj[8];
    #pragma unroll
    for (int j = 0; j < 8; j++) bj[j] = (MODE == M_PLAIN) ? 0.f : bias[c0 + j];

    if (MODE == M_PLAIN) {
        #pragma unroll
        for (int i = 0; i < 8; i++) {
            int r = blockRow + tr * 8 + i;
            if (r >= M) break;
            float* dp = outp + (size_t)r * 128 + c0;
            *(float4*)dp       = make_float4(acc[i][0], acc[i][1], acc[i][2], acc[i][3]);
            *(float4*)(dp + 4) = make_float4(acc[i][4], acc[i][5], acc[i][6], acc[i][7]);
        }
        return;
    }
    if (MODE == M_XD) {
        float vj[8];
        #pragma unroll
        for (int j = 0; j < 8; j++) vj[j] = vparam[c0 + j];
        #pragma unroll
        for (int i = 0; i < 8; i++) {
            int r = blockRow + tr * 8 + i;
            if (r >= M) break;
            float vals[8], zv[8];
            #pragma unroll
            for (int j = 0; j < 8; j++) { vals[j] = acc[i][j] + bj[j]; zv[j] = vj[j] * vals[j]; }
            float* dp = g_xd + (size_t)r * 128 + c0;
            *(float4*)dp       = make_float4(vals[0], vals[1], vals[2], vals[3]);
            *(float4*)(dp + 4) = make_float4(vals[4], vals[5], vals[6], vals[7]);
            float* zp = g_z + (size_t)r * 128 + c0;
            *(float4*)zp       = make_float4(zv[0], zv[1], zv[2], zv[3]);
            *(float4*)(zp + 4) = make_float4(zv[4], zv[5], zv[6], zv[7]);
        }
        return;
    }
    if (MODE == M_OUT) {
        #pragma unroll
        for (int i = 0; i < 8; i++) {
            int r = blockRow + tr * 8 + i;
            if (r >= M) break;
            const float* xp = x + (size_t)r * 128 + c0;
            float4 x0 = *(const float4*)xp;
            float4 x1 = *(const float4*)(xp + 4);
            float* dp = outp + (size_t)r * 128 + c0;
            *(float4*)dp = make_float4(acc[i][0] + bj[0] + x0.x, acc[i][1] + bj[1] + x0.y,
                                       acc[i][2] + bj[2] + x0.z, acc[i][3] + bj[3] + x0.w);
            *(float4*)(dp + 4) = make_float4(acc[i][4] + bj[4] + x1.x, acc[i][5] + bj[5] + x1.y,
                                             acc[i][6] + bj[6] + x1.z, acc[i][7] + bj[7] + x1.w);
        }
        return;
    }
    // M_N1: lrelu + store + stats
    {
        float csum[8], csq[8];
        #pragma unroll
        for (int j = 0; j < 8; j++) { csum[j] = 0.f; csq[j] = 0.f; }
        #pragma unroll 1
        for (int i = 0; i < 8; i++) {
            int r = blockRow + tr * 8 + i;
            if (r >= M) break;
            float vals[8];
            #pragma unroll
            for (int j = 0; j < 8; j++) {
                float v_ = acc[i][j] + bj[j];
                v_ = (v_ >= 0.f) ? v_ : 0.01f * v_;
                vals[j] = v_; csum[j] += v_; csq[j] += v_ * v_;
            }
            float* dp = g_an + (size_t)r * 128 + c0;
            *(float4*)dp       = make_float4(vals[0], vals[1], vals[2], vals[3]);
            *(float4*)(dp + 4) = make_float4(vals[4], vals[5], vals[6], vals[7]);
        }
        #pragma unroll
        for (int j = 0; j < 8; j++) As[tr][c0 + j] = csum[j];
        __syncthreads();
        if (tid < 128) {
            float s = 0.f;
            #pragma unroll
            for (int t = 0; t < 16; t++) s += As[t][tid];
            atomicAdd(&g_sums[4][tid], s);
        }
        __syncthreads();
        #pragma unroll
        for (int j = 0; j < 8; j++) As[tr][c0 + j] = csq[j];
        __syncthreads();
        if (tid < 128) {
            float s = 0.f;
            #pragma unroll
            for (int t = 0; t < 16; t++) s += As[t][tid];
            atomicAdd(&g_sums[5][tid], s);
        }
    }
}

// ---------------- launcher ----------------
extern "C" void kernel_launch(void* const* d_in, const int* in_sizes, int n_in,
                              void* d_out, int out_size) {
    const float* x    = (const float*)d_in[0];
    const float* ea   = (const float*)d_in[1];
    const int*   eidx = (const int*)  d_in[2];
    const float* Wb   = (const float*)d_in[3];
    const float* bb   = (const float*)d_in[4];
    const float* We1  = (const float*)d_in[5];
    const float* be1  = (const float*)d_in[6];
    const float* ge1  = (const float*)d_in[7];
    const float* bte1 = (const float*)d_in[8];
    const float* We2  = (const float*)d_in[9];
    const float* be2  = (const float*)d_in[10];
    const float* ge2  = (const float*)d_in[11];
    const float* bte2 = (const float*)d_in[12];
    const float* We3  = (const float*)d_in[13];
    const float* be3  = (const float*)d_in[14];
    const float* Wd   = (const float*)d_in[15];
    const float* bd   = (const float*)d_in[16];
    const float* v    = (const float*)d_in[17];
    const float* Wn1  = (const float*)d_in[18];
    const float* bn1  = (const float*)d_in[19];
    const float* gn   = (const float*)d_in[20];
    const float* btn  = (const float*)d_in[21];
    const float* Wn2  = (const float*)d_in[22];
    const float* bn2  = (const float*)d_in[23];
    float* outp = (float*)d_out;

    const int gridN = (NNODE + 127) / 128;

    float* d_xtop; cudaGetSymbolAddress((void**)&d_xtop, g_xtop);
    float* d_xbot; cudaGetSymbolAddress((void**)&d_xbot, g_xbot);
    float* d_W2p;  cudaGetSymbolAddress((void**)&d_W2p, g_W2p);
    float* d_W3p;  cudaGetSymbolAddress((void**)&d_W3p, g_W3p);
    char*  d_W2s;  cudaGetSymbolAddress((void**)&d_W2s, g_W2s);
    char*  d_W3s;  cudaGetSymbolAddress((void**)&d_W3s, g_W3s);

    cudaFuncSetAttribute(tc_gemm<0>, cudaFuncAttributeMaxDynamicSharedMemorySize, TCSM);
    cudaFuncSetAttribute(tc_gemm<1>, cudaFuncAttributeMaxDynamicSharedMemorySize, TCSM);

    zero_stats<<<1, 768>>>();
    wbwe1_kernel<<<200, 128>>>(Wb, We1);
    cvec_kernel<<<1, 128>>>(bb, We1, be1);
    table_kernel<<<4 * GTAB, 128>>>();

    gemm_kernel<M_XD><<<gridN, 256>>>(x, Wd, bd, nullptr, v, nullptr, NNODE);
    gemm_kernel<M_PLAIN><<<gridN, 256>>>(x, We1,             nullptr, nullptr, nullptr, d_xtop, NNODE);
    gemm_kernel<M_PLAIN><<<gridN, 256>>>(x, We1 + 256 * 128, nullptr, nullptr, nullptr, d_xbot, NNODE);

    e1_fuse_kernel<<<NTILE, 128>>>(ea, eidx);
    fold_kernel<<<129, 128>>>(0, 1.0f / NEDGE, ge1, bte1, We2, be2);
    pack_kernel<<<128, 128>>>(d_W2p, d_W2s);

    tc_gemm<0><<<NTILE, 256, TCSM>>>(ea, eidx);
    fold_kernel<<<129, 128>>>(2, 1.0f / NEDGE, ge2, bte2, We3, be3);
    pack_kernel<<<128, 128>>>(d_W3p, d_W3s);

    tc_gemm<1><<<NTILE, 256, TCSM>>>(ea, eidx);

    gemm_kernel<M_N1><<<gridN, 256>>>(nullptr, Wn1, bn1, nullptr, nullptr, nullptr, NNODE);
    fold_kernel<<<129, 128>>>(4, 1.0f / NNODE, gn, btn, Wn2, bn2);
    gemm_kernel<M_OUT><<<gridN, 256>>>(nullptr, nullptr, nullptr, x, nullptr, outp, NNODE);
}

// round 11
// speedup vs baseline: 1.5336x; 1.0130x over previous
#include <cuda_runtime.h>
#include <cuda_bf16.h>

#define NNODE 50000
#define NEDGE 300000
#define GTAB  1024
#define EPSBN 1e-5f
#define NTILE 2344              // ceil(NEDGE/128)
#define ROWB  272               // padded smem row bytes (136 bf16)
#define WBYTES 34816            // 128 * ROWB (one hi or lo tile)
#define ABUF   69632            // Ah+Al per buffer
#define TCSM  (3 * 69632)       // W(hi+lo) + 2 A buffers = 208896
#define GRID_TC 148

// ---------------- scratch (device globals; no allocation) ----------------
__device__ uint4 g_a1split[(size_t)NTILE * 4096];  // per tile: 32KB bf16-hi | 32KB bf16-lo, row-major [m][k] 256B rows
__device__ uint4 g_a2split[(size_t)NTILE * 4096];
__device__ uint4 g_W2s[4096];                      // 64KB: W^T [n][k] hi | lo
__device__ uint4 g_W3s[4096];
__device__ float g_xd[(size_t)NNODE * 128];
__device__ float g_z [(size_t)NNODE * 128];
__device__ float g_an[(size_t)NNODE * 128];
__device__ float g_xtop[(size_t)NNODE * 128];
__device__ float g_xbot[(size_t)NNODE * 128];
__device__ float g_tab[4 * GTAB * 128];
__device__ float g_WbWe1[200 * 128];
__device__ float g_cvec[128];
__device__ float g_W2p[128 * 128];  __device__ float g_b2p[128];
__device__ float g_W3p[128 * 128];  __device__ float g_b3p[128];
__device__ float g_Wn2p[128 * 128]; __device__ float g_bn2p[128];
__device__ float g_sums[6][128];

// ---------------- helpers ----------------
__device__ __forceinline__ unsigned smem_u32(const void* p) {
    unsigned a;
    asm("{ .reg .u64 t; cvta.to.shared.u64 t, %1; cvt.u32.u64 %0, t; }" : "=r"(a) : "l"(p));
    return a;
}
#define CP_ASYNC16(dst, src)                                                   \
    asm volatile("cp.async.cg.shared.global [%0], [%1], 16;"                   \
                 :: "r"(dst), "l"(src) : "memory")
#define CP_COMMIT() asm volatile("cp.async.commit_group;" ::: "memory")
#define CP_WAIT0()  asm volatile("cp.async.wait_group 0;" ::: "memory")
#define LDMX4(r, addr)                                                         \
    asm volatile("ldmatrix.sync.aligned.m8n8.x4.shared.b16 {%0,%1,%2,%3}, [%4];" \
                 : "=r"((r)[0]), "=r"((r)[1]), "=r"((r)[2]), "=r"((r)[3])      \
                 : "r"(addr))
#define MMA_BF16(d, a0, a1, a2, a3, b0, b1)                                    \
    asm volatile("mma.sync.aligned.m16n8k16.row.col.f32.bf16.bf16.f32 "        \
                 "{%0,%1,%2,%3}, {%4,%5,%6,%7}, {%8,%9}, {%0,%1,%2,%3};"       \
                 : "+f"((d)[0]), "+f"((d)[1]), "+f"((d)[2]), "+f"((d)[3])      \
                 : "r"(a0), "r"(a1), "r"(a2), "r"(a3), "r"(b0), "r"(b1))
static __device__ __forceinline__ unsigned pack2bf(float a, float b) {
    return ((unsigned)__bfloat16_as_ushort(__float2bfloat16_rn(b)) << 16)
         |  (unsigned)__bfloat16_as_ushort(__float2bfloat16_rn(a));
}

// ---------------- tiny prep kernels ----------------
__global__ void zero_stats() { ((float*)g_sums)[threadIdx.x] = 0.0f; }

__global__ void wbwe1_kernel(const float* __restrict__ Wb, const float* __restrict__ We1) {
    int r = blockIdx.x, n = threadIdx.x;
    float acc = 0.f;
    #pragma unroll 8
    for (int k = 0; k < 128; k++) acc += Wb[r * 128 + k] * We1[(128 + k) * 128 + n];
    g_WbWe1[r * 128 + n] = acc;
}

__global__ void cvec_kernel(const float* __restrict__ bb, const float* __restrict__ We1,
                            const float* __restrict__ be1) {
    int n = threadIdx.x;
    float acc = be1[n];
    #pragma unroll 8
    for (int k = 0; k < 128; k++) acc += bb[k] * We1[(128 + k) * 128 + n];
    g_cvec[n] = acc;
}

__global__ void table_kernel() {
    __shared__ float gs[64];
    int b = blockIdx.x;
    int c = b >> 10;
    int gi = b & (GTAB - 1);
    float u = (float)gi * (1.0f / (GTAB - 1));
    int tid = threadIdx.x;
    if (tid < 50) {
        float d = u - (float)tid * (1.0f / 49.0f);
        gs[tid] = __expf(-d * d * 1250.0f);
    }
    __syncthreads();
    float acc = 0.f;
    #pragma unroll
    for (int j = 0; j < 50; j++) acc += gs[j] * g_WbWe1[(c * 50 + j) * 128 + tid];
    g_tab[b * 128 + tid] = acc;
}

__global__ void fold_kernel(int sidx, float invM,
                            const float* __restrict__ gamma, const float* __restrict__ beta,
                            const float* __restrict__ Wsrc, const float* __restrict__ be) {
    float* Wdst = (sidx == 0) ? g_W2p : (sidx == 2) ? g_W3p : g_Wn2p;
    float* bdst = (sidx == 0) ? g_b2p : (sidx == 2) ? g_b3p : g_bn2p;
    int n = threadIdx.x;
    if (blockIdx.x < 128) {
        int k = blockIdx.x;
        float m = g_sums[sidx][k] * invM;
        float var = g_sums[sidx + 1][k] * invM - m * m;
        float s = gamma[k] * rsqrtf(var + EPSBN);
        Wdst[k * 128 + n] = s * Wsrc[k * 128 + n];
    } else {
        float acc = be[n];
        for (int k = 0; k < 128; k++) {
            float m = g_sums[sidx][k] * invM;
            float var = g_sums[sidx + 1][k] * invM - m * m;
            float s = gamma[k] * rsqrtf(var + EPSBN);
            acc += (beta[k] - m * s) * Wsrc[k * 128 + n];
        }
        bdst[n] = acc;
    }
}

// Pack W^T ([n][k] row-major, 256B rows) into bf16 hi/lo staging (64KB)
__global__ void pack_kernel(const float* __restrict__ Wp, char* __restrict__ Ws) {
    int n = blockIdx.x, k = threadIdx.x;
    float v = Wp[k * 128 + n];
    float h = __bfloat162float(__float2bfloat16_rn(v));
    int off = n * 256 + 2 * k;
    *(unsigned short*)(Ws + off)         = __bfloat16_as_ushort(__float2bfloat16_rn(h));
    *(unsigned short*)(Ws + 32768 + off) = __bfloat16_as_ushort(__float2bfloat16_rn(v - h));
}

// ---------------- fused E1 -> bf16 hi/lo tiles (zero smem, direct stores, high occupancy) ----------------
__global__ __launch_bounds__(128)
void e1_fuse_kernel(const float* __restrict__ ea, const int* __restrict__ eidx) {
    int t = threadIdx.x;
    int e0 = blockIdx.x * 128;
    char* tb = (char*)g_a1split + (size_t)blockIdx.x * 65536;
    float cv = g_cvec[t];
    float csum = 0.f, csq = 0.f;
    int eend = e0 + 128;
    if (eend > NEDGE) eend = NEDGE;
    #pragma unroll 4
    for (int e = e0; e < eend; e++) {
        int s = __ldg(eidx + e);
        int d = __ldg(eidx + NEDGE + e);
        float4 eav = __ldg((const float4*)ea + e);
        float val = g_xtop[(size_t)s * 128 + t] + g_xbot[(size_t)d * 128 + t] + cv;
        float fa[4] = {eav.x, eav.y, eav.z, eav.w};
        #pragma unroll
        for (int c = 0; c < 4; c++) {
            float p = fa[c] * (float)(GTAB - 1);
            int i0 = (int)p;
            if (i0 < 0) i0 = 0;
            if (i0 > GTAB - 2) i0 = GTAB - 2;
            float w = p - (float)i0;
            const float* t0 = g_tab + ((size_t)(c * GTAB + i0) * 128 + t);
            float u = t0[0], v2 = t0[128];
            val += u + w * (v2 - u);
        }
        val = (val >= 0.f) ? val : 0.01f * val;
        csum += val; csq += val * val;
        float h = __bfloat162float(__float2bfloat16_rn(val));
        int off = (e - e0) * 256 + 2 * t;
        *(unsigned short*)(tb + off)         = __bfloat16_as_ushort(__float2bfloat16_rn(h));
        *(unsigned short*)(tb + 32768 + off) = __bfloat16_as_ushort(__float2bfloat16_rn(val - h));
    }
    for (int e = eend; e < e0 + 128; e++) {   // zero tail rows
        int off = (e - e0) * 256 + 2 * t;
        *(unsigned short*)(tb + off) = 0;
        *(unsigned short*)(tb + 32768 + off) = 0;
    }
    atomicAdd(&g_sums[0][t], csum);
    atomicAdd(&g_sums[1][t], csq);
}

// ---------------- persistent bf16 tensor-core edge GEMMs with cp.async double buffering ----------------
// MODE 0 = E2, MODE 1 = E3
template <int MODE>
__global__ __launch_bounds__(256)
void tc_gemm(const float* __restrict__ ea, const int* __restrict__ eidx) {
    extern __shared__ char sm[];
    __shared__ float s_bias[128];
    const int tid = threadIdx.x;
    const int lane = tid & 31, wid = tid >> 5;
    const int wm = wid & 3, wn = wid >> 2;

    const unsigned base_u = smem_u32(sm);
    const unsigned sWh_u = base_u;
    const unsigned sWl_u = base_u + WBYTES;

    if (tid < 128) s_bias[tid] = (MODE == 0) ? g_b2p[tid] : g_b3p[tid];

    const uint4* Abase = (MODE == 0 ? g_a1split : g_a2split);
    const uint4* Wsrc  = (MODE == 0 ? g_W2s : g_W3s);

    // prefetch first A tile into buffer 0 (cp.async), then load W with plain stores
    int tile = blockIdx.x;
    {
        const uint4* src = Abase + (size_t)tile * 4096;
        unsigned dst = base_u + 2 * WBYTES;      // A buf0
        #pragma unroll
        for (int i = tid; i < 2048; i += 256) {
            int row = i >> 4, ch = i & 15;
            unsigned d = dst + (unsigned)(row * ROWB + ch * 16);
            CP_ASYNC16(d, src + i);
            CP_ASYNC16(d + WBYTES, src + i + 2048);
        }
        CP_COMMIT();
        #pragma unroll
        for (int i = tid; i < 2048; i += 256) {
            int row = i >> 4, ch = i & 15;
            *(uint4*)(sm + row * ROWB + ch * 16)          = Wsrc[i];
            *(uint4*)(sm + WBYTES + row * ROWB + ch * 16) = Wsrc[i + 2048];
        }
        CP_WAIT0();
    }
    __syncthreads();

    const int laneRow = lane & 15;
    const unsigned laneK = (unsigned)((lane >> 4) << 4);
    const unsigned aoff0 = (unsigned)((wm * 32 + laneRow) * ROWB) + laneK;
    const unsigned woff  = (unsigned)((wn * 64 + laneRow) * ROWB) + laneK;

    int buf = 0;
    for (; tile < NTILE; tile += GRID_TC) {
        // prefetch next tile into the other buffer (overlaps with MMA + epilogue)
        int nxt = tile + GRID_TC;
        if (nxt < NTILE) {
            const uint4* src = Abase + (size_t)nxt * 4096;
            unsigned dst = base_u + 2 * WBYTES + (unsigned)((buf ^ 1) * ABUF);
            #pragma unroll
            for (int i = tid; i < 2048; i += 256) {
                int row = i >> 4, ch = i & 15;
                unsigned d = dst + (unsigned)(row * ROWB + ch * 16);
                CP_ASYNC16(d, src + i);
                CP_ASYNC16(d + WBYTES, src + i + 2048);
            }
        }
        CP_COMMIT();

        const unsigned sAh_u = base_u + 2 * WBYTES + (unsigned)(buf * ABUF);
        const unsigned sAl_u = sAh_u + WBYTES;

        float acc[2][8][4];
        #pragma unroll
        for (int t = 0; t < 2; t++)
            #pragma unroll
            for (int n = 0; n < 8; n++)
                #pragma unroll
                for (int q = 0; q < 4; q++) acc[t][n][q] = 0.f;

        #pragma unroll 1
        for (int ks = 0; ks < 8; ks++) {
            unsigned kb = (unsigned)(ks * 32);
            unsigned ah[2][4], al[2][4], bw[4][4];
            LDMX4(ah[0], sAh_u + aoff0 + kb);
            LDMX4(ah[1], sAh_u + aoff0 + 16 * ROWB + kb);
            LDMX4(al[0], sAl_u + aoff0 + kb);
            LDMX4(al[1], sAl_u + aoff0 + 16 * ROWB + kb);
            #pragma unroll
            for (int p = 0; p < 4; p++)
                LDMX4(bw[p], sWh_u + woff + p * 16 * ROWB + kb);
            #pragma unroll
            for (int t = 0; t < 2; t++)
                #pragma unroll
                for (int p = 0; p < 4; p++) {
                    MMA_BF16(acc[t][2 * p],     ah[t][0], ah[t][1], ah[t][2], ah[t][3], bw[p][0], bw[p][2]);
                    MMA_BF16(acc[t][2 * p + 1], ah[t][0], ah[t][1], ah[t][2], ah[t][3], bw[p][1], bw[p][3]);
                }
            #pragma unroll
            for (int t = 0; t < 2; t++)
                #pragma unroll
                for (int p = 0; p < 4; p++) {
                    MMA_BF16(acc[t][2 * p],     al[t][0], al[t][1], al[t][2], al[t][3], bw[p][0], bw[p][2]);
                    MMA_BF16(acc[t][2 * p + 1], al[t][0], al[t][1], al[t][2], al[t][3], bw[p][1], bw[p][3]);
                }
            #pragma unroll
            for (int p = 0; p < 4; p++)
                LDMX4(bw[p], sWl_u + woff + p * 16 * ROWB + kb);
            #pragma unroll
            for (int t = 0; t < 2; t++)
                #pragma unroll
                for (int p = 0; p < 4; p++) {
                    MMA_BF16(acc[t][2 * p],     ah[t][0], ah[t][1], ah[t][2], ah[t][3], bw[p][0], bw[p][2]);
                    MMA_BF16(acc[t][2 * p + 1], ah[t][0], ah[t][1], ah[t][2], ah[t][3], bw[p][1], bw[p][3]);
                }
        }
        __syncthreads();   // all warps done reading A[buf]; reuse it as fp32 stage

        float* sF = (float*)(sm + 2 * WBYTES + buf * ABUF);
        {
            int mr = lane >> 2;
            int nc = 2 * (lane & 3);
            #pragma unroll
            for (int t = 0; t < 2; t++) {
                int row = wm * 32 + t * 16 + mr;
                #pragma unroll
                for (int nt = 0; nt < 8; nt++) {
                    int col = wn * 64 + nt * 8 + nc;
                    sF[row * 132 + col]           = acc[t][nt][0];
                    sF[row * 132 + col + 1]       = acc[t][nt][1];
                    sF[(row + 8) * 132 + col]     = acc[t][nt][2];
                    sF[(row + 8) * 132 + col + 1] = acc[t][nt][3];
                }
            }
        }
        __syncthreads();

        if (MODE == 0) {
            int rl = tid >> 1, h = tid & 1;
            long gbase = (long)tile * 128;
            bool valid = (gbase + rl) < NEDGE;
            char* outb = (char*)g_a2split + (size_t)tile * 65536;
            uint4* dh = (uint4*)(outb + rl * 256 + h * 128);
            uint4* dl = (uint4*)(outb + 32768 + rl * 256 + h * 128);
            float* fr = sF + rl * 132 + h * 64;
            const float* bp = s_bias + h * 64;
            #pragma unroll
            for (int q = 0; q < 8; q++) {
                unsigned ph[4], pl[4];
                #pragma unroll
                for (int j = 0; j < 4; j++) {
                    int c = q * 8 + j * 2;
                    float v0 = fr[c]     + bp[c];
                    float v1 = fr[c + 1] + bp[c + 1];
                    v0 = (v0 >= 0.f) ? v0 : 0.01f * v0;
                    v1 = (v1 >= 0.f) ? v1 : 0.01f * v1;
                    if (!valid) { v0 = 0.f; v1 = 0.f; }
                    fr[c] = v0; fr[c + 1] = v1;
                    float h0 = __bfloat162float(__float2bfloat16_rn(v0));
                    float h1 = __bfloat162float(__float2bfloat16_rn(v1));
                    ph[j] = pack2bf(h0, h1);
                    pl[j] = pack2bf(v0 - h0, v1 - h1);
                }
                dh[q] = make_uint4(ph[0], ph[1], ph[2], ph[3]);
                dl[q] = make_uint4(pl[0], pl[1], pl[2], pl[3]);
            }
            __syncthreads();
            {
                int c = tid & 127, h2 = tid >> 7;
                float s0 = 0.f, s1 = 0.f;
                #pragma unroll 8
                for (int r = 0; r < 64; r++) {
                    float v = sF[(h2 * 64 + r) * 132 + c];
                    s0 += v; s1 += v * v;
                }
                atomicAdd(&g_sums[2][c], s0);
                atomicAdd(&g_sums[3][c], s1);
            }
        } else {
            int rt = tid >> 1, h = tid & 1;
            long grow = (long)tile * 128 + rt;
            if (grow < NEDGE) {
                int s_ = eidx[grow], d_ = eidx[NEDGE + grow];
                float coeff = cosf(1.5707963267948966f * ea[grow * 4 + 3]);
                const float4* xp = (const float4*)(g_xd + (size_t)s_ * 128) + h * 16;
                float* zp = g_z + (size_t)d_ * 128 + h * 64;
                const float* fr = sF + rt * 132 + h * 64;
                const float* bp = s_bias + h * 64;
                #pragma unroll
                for (int q = 0; q < 16; q++) {
                    float4 xv = xp[q];
                    float v0 = coeff * (fr[4 * q + 0] + bp[4 * q + 0]) * xv.x;
                    float v1 = coeff * (fr[4 * q + 1] + bp[4 * q + 1]) * xv.y;
                    float v2 = coeff * (fr[4 * q + 2] + bp[4 * q + 2]) * xv.z;
                    float v3 = coeff * (fr[4 * q + 3] + bp[4 * q + 3]) * xv.w;
                    asm volatile("red.global.add.v4.f32 [%0], {%1,%2,%3,%4};"
                                 :: "l"(zp + 4 * q), "f"(v0), "f"(v1), "f"(v2), "f"(v3) : "memory");
                }
            }
        }
        __syncthreads();
        CP_WAIT0();          // next A tile landed
        __syncthreads();
        buf ^= 1;
    }
}

// ---------------- SIMT node GEMMs (128x128 tile, 256 threads) ----------------
enum { M_XD = 0, M_PLAIN = 1, M_N1 = 4, M_OUT = 5 };

template <int MODE>
__global__ __launch_bounds__(256)
void gemm_kernel(const float* __restrict__ A, const float* __restrict__ Wparam,
                 const float* __restrict__ biasExt, const float* __restrict__ x,
                 const float* __restrict__ vparam, float* __restrict__ outp, int M) {
    __shared__ float As[16][132];
    __shared__ float Ws[16][132];

    const int tid = threadIdx.x;
    const int blockRow = blockIdx.x * 128;
    const int tr = tid >> 4;
    const int tc = tid & 15;
    const int c0 = tc * 8;

    const float* W = (MODE == M_OUT) ? g_Wn2p : Wparam;
    const float* bias = (MODE == M_OUT) ? g_bn2p : biasExt;
    const float* Aeff = (MODE == M_N1) ? g_z : (MODE == M_OUT) ? g_an : A;

    const int lr = tid >> 1;
    const int lh = (tid & 1) * 8;
    const float* arow;
    {
        int r = blockRow + lr;
        if (r > M - 1) r = M - 1;
        arow = Aeff + (size_t)r * 128;
    }

    float acc[8][8];
    #pragma unroll
    for (int i = 0; i < 8; i++)
        #pragma unroll
        for (int j = 0; j < 8; j++) acc[i][j] = 0.f;

    #pragma unroll 1
    for (int k0 = 0; k0 < 128; k0 += 16) {
        const float* ap = arow + k0 + lh;
        float4 a0 = *(const float4*)ap;
        float4 a1 = *(const float4*)(ap + 4);
        int krow = k0 + tr;
        float4 b0 = *(const float4*)(W + (size_t)krow * 128 + c0);
        float4 b1 = *(const float4*)(W + (size_t)krow * 128 + c0 + 4);

        __syncthreads();
        As[lh + 0][lr] = a0.x; As[lh + 1][lr] = a0.y;
        As[lh + 2][lr] = a0.z; As[lh + 3][lr] = a0.w;
        As[lh + 4][lr] = a1.x; As[lh + 5][lr] = a1.y;
        As[lh + 6][lr] = a1.z; As[lh + 7][lr] = a1.w;
        *(float4*)&Ws[tr][c0]     = b0;
        *(float4*)&Ws[tr][c0 + 4] = b1;
        __syncthreads();

        #pragma unroll
        for (int kk = 0; kk < 16; kk++) {
            float af[8], bf[8];
            *(float4*)(af)     = *(const float4*)&As[kk][tr * 8];
            *(float4*)(af + 4) = *(const float4*)&As[kk][tr * 8 + 4];
            *(float4*)(bf)     = *(const float4*)&Ws[kk][c0];
            *(float4*)(bf + 4) = *(const float4*)&Ws[kk][c0 + 4];
            #pragma unroll
            for (int i = 0; i < 8; i++)
                #pragma unroll
                for (int j = 0; j < 8; j++)
                    acc[i][j] += af[i] * bf[j];
        }
    }
    __syncthreads();

    float bj[8];
    #pragma unroll
    for (int j = 0; j < 8; j++) bj[j] = (MODE == M_PLAIN) ? 0.f : bias[c0 + j];

    if (MODE == M_PLAIN) {
        #pragma unroll
        for (int i = 0; i < 8; i++) {
            int r = blockRow + tr * 8 + i;
            if (r >= M) break;
            float* dp = outp + (size_t)r * 128 + c0;
            *(float4*)dp       = make_float4(acc[i][0], acc[i][1], acc[i][2], acc[i][3]);
            *(float4*)(dp + 4) = make_float4(acc[i][4], acc[i][5], acc[i][6], acc[i][7]);
        }
        return;
    }
    if (MODE == M_XD) {
        float vj[8];
        #pragma unroll
        for (int j = 0; j < 8; j++) vj[j] = vparam[c0 + j];
        #pragma unroll
        for (int i = 0; i < 8; i++) {
            int r = blockRow + tr * 8 + i;
            if (r >= M) break;
            float vals[8], zv[8];
            #pragma unroll
            for (int j = 0; j < 8; j++) { vals[j] = acc[i][j] + bj[j]; zv[j] = vj[j] * vals[j]; }
            float* dp = g_xd + (size_t)r * 128 + c0;
            *(float4*)dp       = make_float4(vals[0], vals[1], vals[2], vals[3]);
            *(float4*)(dp + 4) = make_float4(vals[4], vals[5], vals[6], vals[7]);
            float* zp = g_z + (size_t)r * 128 + c0;
            *(float4*)zp       = make_float4(zv[0], zv[1], zv[2], zv[3]);
            *(float4*)(zp + 4) = make_float4(zv[4], zv[5], zv[6], zv[7]);
        }
        return;
    }
    if (MODE == M_OUT) {
        #pragma unroll
        for (int i = 0; i < 8; i++) {
            int r = blockRow + tr * 8 + i;
            if (r >= M) break;
            const float* xp = x + (size_t)r * 128 + c0;
            float4 x0 = *(const float4*)xp;
            float4 x1 = *(const float4*)(xp + 4);
            float* dp = outp + (size_t)r * 128 + c0;
            *(float4*)dp = make_float4(acc[i][0] + bj[0] + x0.x, acc[i][1] + bj[1] + x0.y,
                                       acc[i][2] + bj[2] + x0.z, acc[i][3] + bj[3] + x0.w);
            *(float4*)(dp + 4) = make_float4(acc[i][4] + bj[4] + x1.x, acc[i][5] + bj[5] + x1.y,
                                             acc[i][6] + bj[6] + x1.z, acc[i][7] + bj[7] + x1.w);
        }
        return;
    }
    // M_N1: lrelu + store + stats
    {
        float csum[8], csq[8];
        #pragma unroll
        for (int j = 0; j < 8; j++) { csum[j] = 0.f; csq[j] = 0.f; }
        #pragma unroll 1
        for (int i = 0; i < 8; i++) {
            int r = blockRow + tr * 8 + i;
            if (r >= M) break;
            float vals[8];
            #pragma unroll
            for (int j = 0; j < 8; j++) {
                float v_ = acc[i][j] + bj[j];
                v_ = (v_ >= 0.f) ? v_ : 0.01f * v_;
                vals[j] = v_; csum[j] += v_; csq[j] += v_ * v_;
            }
            float* dp = g_an + (size_t)r * 128 + c0;
            *(float4*)dp       = make_float4(vals[0], vals[1], vals[2], vals[3]);
            *(float4*)(dp + 4) = make_float4(vals[4], vals[5], vals[6], vals[7]);
        }
        #pragma unroll
        for (int j = 0; j < 8; j++) As[tr][c0 + j] = csum[j];
        __syncthreads();
        if (tid < 128) {
            float s = 0.f;
            #pragma unroll
            for (int t = 0; t < 16; t++) s += As[t][tid];
            atomicAdd(&g_sums[4][tid], s);
        }
        __syncthreads();
        #pragma unroll
        for (int j = 0; j < 8; j++) As[tr][c0 + j] = csq[j];
        __syncthreads();
        if (tid < 128) {
            float s = 0.f;
            #pragma unroll
            for (int t = 0; t < 16; t++) s += As[t][tid];
            atomicAdd(&g_sums[5][tid], s);
        }
    }
}

// ---------------- launcher ----------------
extern "C" void kernel_launch(void* const* d_in, const int* in_sizes, int n_in,
                              void* d_out, int out_size) {
    const float* x    = (const float*)d_in[0];
    const float* ea   = (const float*)d_in[1];
    const int*   eidx = (const int*)  d_in[2];
    const float* Wb   = (const float*)d_in[3];
    const float* bb   = (const float*)d_in[4];
    const float* We1  = (const float*)d_in[5];
    const float* be1  = (const float*)d_in[6];
    const float* ge1  = (const float*)d_in[7];
    const float* bte1 = (const float*)d_in[8];
    const float* We2  = (const float*)d_in[9];
    const float* be2  = (const float*)d_in[10];
    const float* ge2  = (const float*)d_in[11];
    const float* bte2 = (const float*)d_in[12];
    const float* We3  = (const float*)d_in[13];
    const float* be3  = (const float*)d_in[14];
    const float* Wd   = (const float*)d_in[15];
    const float* bd   = (const float*)d_in[16];
    const float* v    = (const float*)d_in[17];
    const float* Wn1  = (const float*)d_in[18];
    const float* bn1  = (const float*)d_in[19];
    const float* gn   = (const float*)d_in[20];
    const float* btn  = (const float*)d_in[21];
    const float* Wn2  = (const float*)d_in[22];
    const float* bn2  = (const float*)d_in[23];
    float* outp = (float*)d_out;

    const int gridN = (NNODE + 127) / 128;

    float* d_xtop; cudaGetSymbolAddress((void**)&d_xtop, g_xtop);
    float* d_xbot; cudaGetSymbolAddress((void**)&d_xbot, g_xbot);
    float* d_W2p;  cudaGetSymbolAddress((void**)&d_W2p, g_W2p);
    float* d_W3p;  cudaGetSymbolAddress((void**)&d_W3p, g_W3p);
    char*  d_W2s;  cudaGetSymbolAddress((void**)&d_W2s, g_W2s);
    char*  d_W3s;  cudaGetSymbolAddress((void**)&d_W3s, g_W3s);

    cudaFuncSetAttribute(tc_gemm<0>, cudaFuncAttributeMaxDynamicSharedMemorySize, TCSM);
    cudaFuncSetAttribute(tc_gemm<1>, cudaFuncAttributeMaxDynamicSharedMemorySize, TCSM);

    zero_stats<<<1, 768>>>();
    wbwe1_kernel<<<200, 128>>>(Wb, We1);
    cvec_kernel<<<1, 128>>>(bb, We1, be1);
    table_kernel<<<4 * GTAB, 128>>>();

    gemm_kernel<M_XD><<<gridN, 256>>>(x, Wd, bd, nullptr, v, nullptr, NNODE);
    gemm_kernel<M_PLAIN><<<gridN, 256>>>(x, We1,             nullptr, nullptr, nullptr, d_xtop, NNODE);
    gemm_kernel<M_PLAIN><<<gridN, 256>>>(x, We1 + 256 * 128, nullptr, nullptr, nullptr, d_xbot, NNODE);

    e1_fuse_kernel<<<NTILE, 128>>>(ea, eidx);
    fold_kernel<<<129, 128>>>(0, 1.0f / NEDGE, ge1, bte1, We2, be2);
    pack_kernel<<<128, 128>>>(d_W2p, d_W2s);

    tc_gemm<0><<<GRID_TC, 256, TCSM>>>(ea, eidx);
    fold_kernel<<<129, 128>>>(2, 1.0f / NEDGE, ge2, bte2, We3, be3);
    pack_kernel<<<128, 128>>>(d_W3p, d_W3s);

    tc_gemm<1><<<GRID_TC, 256, TCSM>>>(ea, eidx);

    gemm_kernel<M_N1><<<gridN, 256>>>(nullptr, Wn1, bn1, nullptr, nullptr, nullptr, NNODE);
    fold_kernel<<<129, 128>>>(4, 1.0f / NNODE, gn, btn, Wn2, bn2);
    gemm_kernel<M_OUT><<<gridN, 256>>>(nullptr, nullptr, nullptr, x, nullptr, outp, NNODE);
}

// round 12
// speedup vs baseline: 1.6130x; 1.0518x over previous
#include <cuda_runtime.h>
#include <cuda_bf16.h>

#define NNODE 50000
#define NNPAD 50048             // 391 * 128
#define NEDGE 300000
#define GTAB  1024
#define EPSBN 1e-5f
#define NTILE 2344              // ceil(NEDGE/128)
#define NTILEN 391              // ceil(NNODE/128)
#define ROWB  272               // padded smem row bytes (136 bf16)
#define WBYTES 34816            // 128 * ROWB
#define ABUF   69632            // Ah+Al per buffer
#define TCSM_E (3 * 69632)      // persistent edge gemm: W(hi+lo) + 2 A buffers
#define TCSM_N (2 * 69632)      // node gemm: A(hi+lo) + Wchunk(hi+lo)
#define GRID_TC 148

// ---------------- scratch (device globals; no allocation) ----------------
__device__ uint4 g_a1split[(size_t)NTILE * 4096];  // per tile: 32KB hi | 32KB lo, [m][k] 256B rows
__device__ uint4 g_a2split[(size_t)NTILE * 4096];
__device__ uint4 g_W2s[4096];                      // 64KB: W^T [n][k] hi | lo
__device__ uint4 g_W3s[4096];
__device__ uint4 g_xs_hi[(size_t)NNPAD * 16];      // x bf16-hi, [m][k] 256B rows
__device__ uint4 g_xs_lo[(size_t)NNPAD * 16];
__device__ uint4 g_Wns[12288];                     // 192KB: [384 n][128 k] hi (96KB) | lo (96KB)
__device__ float g_xd[(size_t)NNODE * 128];
__device__ float g_z [(size_t)NNODE * 128];
__device__ float g_an[(size_t)NNODE * 128];
__device__ float g_xtop[(size_t)NNODE * 128];
__device__ float g_xbot[(size_t)NNODE * 128];
__device__ float g_tab[4 * GTAB * 128];
__device__ float g_WbWe1[200 * 128];
__device__ float g_cvec[128];
__device__ float g_W2p[128 * 128];  __device__ float g_b2p[128];
__device__ float g_W3p[128 * 128];  __device__ float g_b3p[128];
__device__ float g_Wn2p[128 * 128]; __device__ float g_bn2p[128];
__device__ float g_sums[6][128];

// ---------------- helpers ----------------
__device__ __forceinline__ unsigned smem_u32(const void* p) {
    unsigned a;
    asm("{ .reg .u64 t; cvta.to.shared.u64 t, %1; cvt.u32.u64 %0, t; }" : "=r"(a) : "l"(p));
    return a;
}
#define CP_ASYNC16(dst, src)                                                   \
    asm volatile("cp.async.cg.shared.global [%0], [%1], 16;"                   \
                 :: "r"(dst), "l"(src) : "memory")
#define CP_COMMIT() asm volatile("cp.async.commit_group;" ::: "memory")
#define CP_WAIT0()  asm volatile("cp.async.wait_group 0;" ::: "memory")
#define LDMX4(r, addr)                                                         \
    asm volatile("ldmatrix.sync.aligned.m8n8.x4.shared.b16 {%0,%1,%2,%3}, [%4];" \
                 : "=r"((r)[0]), "=r"((r)[1]), "=r"((r)[2]), "=r"((r)[3])      \
                 : "r"(addr))
#define MMA_BF16(d, a0, a1, a2, a3, b0, b1)                                    \
    asm volatile("mma.sync.aligned.m16n8k16.row.col.f32.bf16.bf16.f32 "        \
                 "{%0,%1,%2,%3}, {%4,%5,%6,%7}, {%8,%9}, {%0,%1,%2,%3};"       \
                 : "+f"((d)[0]), "+f"((d)[1]), "+f"((d)[2]), "+f"((d)[3])      \
                 : "r"(a0), "r"(a1), "r"(a2), "r"(a3), "r"(b0), "r"(b1))
static __device__ __forceinline__ unsigned pack2bf(float a, float b) {
    return ((unsigned)__bfloat16_as_ushort(__float2bfloat16_rn(b)) << 16)
         |  (unsigned)__bfloat16_as_ushort(__float2bfloat16_rn(a));
}

// ---------------- tiny prep kernels ----------------
__global__ void zero_stats() { ((float*)g_sums)[threadIdx.x] = 0.0f; }

__global__ void wbwe1_kernel(const float* __restrict__ Wb, const float* __restrict__ We1) {
    int r = blockIdx.x, n = threadIdx.x;
    float acc = 0.f;
    #pragma unroll 8
    for (int k = 0; k < 128; k++) acc += Wb[r * 128 + k] * We1[(128 + k) * 128 + n];
    g_WbWe1[r * 128 + n] = acc;
}

__global__ void cvec_kernel(const float* __restrict__ bb, const float* __restrict__ We1,
                            const float* __restrict__ be1) {
    int n = threadIdx.x;
    float acc = be1[n];
    #pragma unroll 8
    for (int k = 0; k < 128; k++) acc += bb[k] * We1[(128 + k) * 128 + n];
    g_cvec[n] = acc;
}

__global__ void table_kernel() {
    __shared__ float gs[64];
    int b = blockIdx.x;
    int c = b >> 10;
    int gi = b & (GTAB - 1);
    float u = (float)gi * (1.0f / (GTAB - 1));
    int tid = threadIdx.x;
    if (tid < 50) {
        float d = u - (float)tid * (1.0f / 49.0f);
        gs[tid] = __expf(-d * d * 1250.0f);
    }
    __syncthreads();
    float acc = 0.f;
    #pragma unroll
    for (int j = 0; j < 50; j++) acc += gs[j] * g_WbWe1[(c * 50 + j) * 128 + tid];
    g_tab[b * 128 + tid] = acc;
}

__global__ void fold_kernel(int sidx, float invM,
                            const float* __restrict__ gamma, const float* __restrict__ beta,
                            const float* __restrict__ Wsrc, const float* __restrict__ be) {
    float* Wdst = (sidx == 0) ? g_W2p : (sidx == 2) ? g_W3p : g_Wn2p;
    float* bdst = (sidx == 0) ? g_b2p : (sidx == 2) ? g_b3p : g_bn2p;
    int n = threadIdx.x;
    if (blockIdx.x < 128) {
        int k = blockIdx.x;
        float m = g_sums[sidx][k] * invM;
        float var = g_sums[sidx + 1][k] * invM - m * m;
        float s = gamma[k] * rsqrtf(var + EPSBN);
        Wdst[k * 128 + n] = s * Wsrc[k * 128 + n];
    } else {
        float acc = be[n];
        for (int k = 0; k < 128; k++) {
            float m = g_sums[sidx][k] * invM;
            float var = g_sums[sidx + 1][k] * invM - m * m;
            float s = gamma[k] * rsqrtf(var + EPSBN);
            acc += (beta[k] - m * s) * Wsrc[k * 128 + n];
        }
        bdst[n] = acc;
    }
}

// Pack W^T ([n][k] row-major, 256B rows) into bf16 hi/lo staging (64KB)
__global__ void pack_kernel(const float* __restrict__ Wp, char* __restrict__ Ws) {
    int n = blockIdx.x, k = threadIdx.x;
    float v = Wp[k * 128 + n];
    float h = __bfloat162float(__float2bfloat16_rn(v));
    int off = n * 256 + 2 * k;
    *(unsigned short*)(Ws + off)         = __bfloat16_as_ushort(__float2bfloat16_rn(h));
    *(unsigned short*)(Ws + 32768 + off) = __bfloat16_as_ushort(__float2bfloat16_rn(v - h));
}

// Pack node weights: n<128 -> We1_top^T, n<256 -> We1_bot^T, else Wd^T
__global__ void packnode_kernel(const float* __restrict__ We1, const float* __restrict__ Wd) {
    int n = blockIdx.x, k = threadIdx.x;
    float v;
    if (n < 128)       v = We1[k * 128 + n];
    else if (n < 256)  v = We1[(256 + k) * 128 + (n - 128)];
    else               v = Wd[k * 128 + (n - 256)];
    float h = __bfloat162float(__float2bfloat16_rn(v));
    char* Ws = (char*)g_Wns;
    int off = n * 256 + 2 * k;
    *(unsigned short*)(Ws + off)         = __bfloat16_as_ushort(__float2bfloat16_rn(h));
    *(unsigned short*)(Ws + 98304 + off) = __bfloat16_as_ushort(__float2bfloat16_rn(v - h));
}

// Split x into bf16 hi/lo, pad tail rows with zero
__global__ __launch_bounds__(256)
void xsplit_kernel(const float* __restrict__ x) {
    int base = blockIdx.x * 16384;
    char* hb = (char*)g_xs_hi;
    char* lb = (char*)g_xs_lo;
    #pragma unroll
    for (int i = 0; i < 64; i++) {
        int idx = base + threadIdx.x + i * 256;
        float v = (idx < NNODE * 128) ? __ldg(x + idx) : 0.f;
        float h = __bfloat162float(__float2bfloat16_rn(v));
        *(unsigned short*)(hb + 2 * idx) = __bfloat16_as_ushort(__float2bfloat16_rn(h));
        *(unsigned short*)(lb + 2 * idx) = __bfloat16_as_ushort(__float2bfloat16_rn(v - h));
    }
}

// ---------------- fused E1 -> bf16 hi/lo tiles (zero smem, direct stores) ----------------
__global__ __launch_bounds__(128)
void e1_fuse_kernel(const float* __restrict__ ea, const int* __restrict__ eidx) {
    int t = threadIdx.x;
    int e0 = blockIdx.x * 128;
    char* tb = (char*)g_a1split + (size_t)blockIdx.x * 65536;
    float cv = g_cvec[t];
    float csum = 0.f, csq = 0.f;
    int eend = e0 + 128;
    if (eend > NEDGE) eend = NEDGE;
    #pragma unroll 4
    for (int e = e0; e < eend; e++) {
        int s = __ldg(eidx + e);
        int d = __ldg(eidx + NEDGE + e);
        float4 eav = __ldg((const float4*)ea + e);
        float val = g_xtop[(size_t)s * 128 + t] + g_xbot[(size_t)d * 128 + t] + cv;
        float fa[4] = {eav.x, eav.y, eav.z, eav.w};
        #pragma unroll
        for (int c = 0; c < 4; c++) {
            float p = fa[c] * (float)(GTAB - 1);
            int i0 = (int)p;
            if (i0 < 0) i0 = 0;
            if (i0 > GTAB - 2) i0 = GTAB - 2;
            float w = p - (float)i0;
            const float* t0 = g_tab + ((size_t)(c * GTAB + i0) * 128 + t);
            float u = t0[0], v2 = t0[128];
            val += u + w * (v2 - u);
        }
        val = (val >= 0.f) ? val : 0.01f * val;
        csum += val; csq += val * val;
        float h = __bfloat162float(__float2bfloat16_rn(val));
        int off = (e - e0) * 256 + 2 * t;
        *(unsigned short*)(tb + off)         = __bfloat16_as_ushort(__float2bfloat16_rn(h));
        *(unsigned short*)(tb + 32768 + off) = __bfloat16_as_ushort(__float2bfloat16_rn(val - h));
    }
    for (int e = eend; e < e0 + 128; e++) {
        int off = (e - e0) * 256 + 2 * t;
        *(unsigned short*)(tb + off) = 0;
        *(unsigned short*)(tb + 32768 + off) = 0;
    }
    atomicAdd(&g_sums[0][t], csum);
    atomicAdd(&g_sums[1][t], csq);
}

// ---------------- tc node GEMM: [xtop | xbot | xd,z] = x @ Wns (3 chunks of N=128) ----------------
__global__ __launch_bounds__(256)
void tc_node(const float* __restrict__ bd, const float* __restrict__ vparam) {
    extern __shared__ char sm[];
    __shared__ float s_bd[128], s_v[128];
    const int tid = threadIdx.x;
    const int lane = tid & 31, wid = tid >> 5;
    const int wm = wid & 3, wn = wid >> 2;

    if (tid < 128) { s_bd[tid] = bd[tid]; s_v[tid] = vparam[tid]; }

    const unsigned base_u = smem_u32(sm);
    const unsigned sAh_u = base_u;
    const unsigned sAl_u = base_u + WBYTES;
    const unsigned sWh_u = base_u + 2 * WBYTES;
    const unsigned sWl_u = base_u + 3 * WBYTES;

    const int gbase = blockIdx.x * 128;
    // load A tile (x hi/lo rows gbase..gbase+127; padded arrays so no guard)
    {
        const uint4* hsrc = g_xs_hi + (size_t)gbase * 16;
        const uint4* lsrc = g_xs_lo + (size_t)gbase * 16;
        #pragma unroll
        for (int i = tid; i < 2048; i += 256) {
            int row = i >> 4, ch = i & 15;
            *(uint4*)(sm + row * ROWB + ch * 16)          = hsrc[i];
            *(uint4*)(sm + WBYTES + row * ROWB + ch * 16) = lsrc[i];
        }
    }

    const int laneRow = lane & 15;
    const unsigned laneK = (unsigned)((lane >> 4) << 4);
    const unsigned aoff = (unsigned)((wm * 32 + laneRow) * ROWB) + laneK;
    const unsigned woff = (unsigned)((wn * 64 + laneRow) * ROWB) + laneK;

    #pragma unroll 1
    for (int chunk = 0; chunk < 3; chunk++) {
        // load W chunk rows n = chunk*128 .. +127
        {
            const uint4* whs = g_Wns + (size_t)chunk * 2048;
            const uint4* wls = g_Wns + 6144 + (size_t)chunk * 2048;
            #pragma unroll
            for (int i = tid; i < 2048; i += 256) {
                int row = i >> 4, ch = i & 15;
                *(uint4*)(sm + 2 * WBYTES + row * ROWB + ch * 16) = whs[i];
                *(uint4*)(sm + 3 * WBYTES + row * ROWB + ch * 16) = wls[i];
            }
        }
        __syncthreads();

        float acc[2][8][4];
        #pragma unroll
        for (int t = 0; t < 2; t++)
            #pragma unroll
            for (int n = 0; n < 8; n++)
                #pragma unroll
                for (int q = 0; q < 4; q++) acc[t][n][q] = 0.f;

        #pragma unroll 1
        for (int ks = 0; ks < 8; ks++) {
            unsigned kb = (unsigned)(ks * 32);
            unsigned ah[2][4], al[2][4], bw[4][4];
            LDMX4(ah[0], sAh_u + aoff + kb);
            LDMX4(ah[1], sAh_u + aoff + 16 * ROWB + kb);
            LDMX4(al[0], sAl_u + aoff + kb);
            LDMX4(al[1], sAl_u + aoff + 16 * ROWB + kb);
            #pragma unroll
            for (int p = 0; p < 4; p++)
                LDMX4(bw[p], sWh_u + woff + p * 16 * ROWB + kb);
            #pragma unroll
            for (int t = 0; t < 2; t++)
                #pragma unroll
                for (int p = 0; p < 4; p++) {
                    MMA_BF16(acc[t][2 * p],     ah[t][0], ah[t][1], ah[t][2], ah[t][3], bw[p][0], bw[p][2]);
                    MMA_BF16(acc[t][2 * p + 1], ah[t][0], ah[t][1], ah[t][2], ah[t][3], bw[p][1], bw[p][3]);
                }
            #pragma unroll
            for (int t = 0; t < 2; t++)
                #pragma unroll
                for (int p = 0; p < 4; p++) {
                    MMA_BF16(acc[t][2 * p],     al[t][0], al[t][1], al[t][2], al[t][3], bw[p][0], bw[p][2]);
                    MMA_BF16(acc[t][2 * p + 1], al[t][0], al[t][1], al[t][2], al[t][3], bw[p][1], bw[p][3]);
                }
            #pragma unroll
            for (int p = 0; p < 4; p++)
                LDMX4(bw[p], sWl_u + woff + p * 16 * ROWB + kb);
            #pragma unroll
            for (int t = 0; t < 2; t++)
                #pragma unroll
                for (int p = 0; p < 4; p++) {
                    MMA_BF16(acc[t][2 * p],     ah[t][0], ah[t][1], ah[t][2], ah[t][3], bw[p][0], bw[p][2]);
                    MMA_BF16(acc[t][2 * p + 1], ah[t][0], ah[t][1], ah[t][2], ah[t][3], bw[p][1], bw[p][3]);
                }
        }
        __syncthreads();   // done with W chunk; reuse its smem as fp32 stage

        float* sF = (float*)(sm + 2 * WBYTES);
        {
            int mr = lane >> 2;
            int nc = 2 * (lane & 3);
            #pragma unroll
            for (int t = 0; t < 2; t++) {
                int row = wm * 32 + t * 16 + mr;
                #pragma unroll
                for (int nt = 0; nt < 8; nt++) {
                    int col = wn * 64 + nt * 8 + nc;
                    sF[row * 132 + col]           = acc[t][nt][0];
                    sF[row * 132 + col + 1]       = acc[t][nt][1];
                    sF[(row + 8) * 132 + col]     = acc[t][nt][2];
                    sF[(row + 8) * 132 + col + 1] = acc[t][nt][3];
                }
            }
        }
        __syncthreads();

        {
            int rl = tid >> 1, h = tid & 1;
            int grow = gbase + rl;
            if (grow < NNODE) {
                const float* fr = sF + rl * 132 + h * 64;
                if (chunk == 0) {
                    float* dp = g_xtop + (size_t)grow * 128 + h * 64;
                    #pragma unroll
                    for (int q = 0; q < 16; q++)
                        ((float4*)dp)[q] = make_float4(fr[4*q], fr[4*q+1], fr[4*q+2], fr[4*q+3]);
                } else if (chunk == 1) {
                    float* dp = g_xbot + (size_t)grow * 128 + h * 64;
                    #pragma unroll
                    for (int q = 0; q < 16; q++)
                        ((float4*)dp)[q] = make_float4(fr[4*q], fr[4*q+1], fr[4*q+2], fr[4*q+3]);
                } else {
                    float* dx = g_xd + (size_t)grow * 128 + h * 64;
                    float* dz = g_z  + (size_t)grow * 128 + h * 64;
                    const float* bp = s_bd + h * 64;
                    const float* vp = s_v + h * 64;
                    #pragma unroll
                    for (int q = 0; q < 16; q++) {
                        float x0 = fr[4*q]   + bp[4*q];
                        float x1 = fr[4*q+1] + bp[4*q+1];
                        float x2 = fr[4*q+2] + bp[4*q+2];
                        float x3 = fr[4*q+3] + bp[4*q+3];
                        ((float4*)dx)[q] = make_float4(x0, x1, x2, x3);
                        ((float4*)dz)[q] = make_float4(vp[4*q]*x0, vp[4*q+1]*x1, vp[4*q+2]*x2, vp[4*q+3]*x3);
                    }
                }
            }
        }
        __syncthreads();   // before overwriting W region next chunk
    }
}

// ---------------- persistent bf16 tensor-core edge GEMMs (cp.async double buffer) ----------------
// MODE 0 = E2, MODE 1 = E3
template <int MODE>
__global__ __launch_bounds__(256)
void tc_gemm(const float* __restrict__ ea, const int* __restrict__ eidx) {
    extern __shared__ char sm[];
    __shared__ float s_bias[128];
    const int tid = threadIdx.x;
    const int lane = tid & 31, wid = tid >> 5;
    const int wm = wid & 3, wn = wid >> 2;

    const unsigned base_u = smem_u32(sm);
    const unsigned sWh_u = base_u;
    const unsigned sWl_u = base_u + WBYTES;

    if (tid < 128) s_bias[tid] = (MODE == 0) ? g_b2p[tid] : g_b3p[tid];

    const uint4* Abase = (MODE == 0 ? g_a1split : g_a2split);
    const uint4* Wsrc  = (MODE == 0 ? g_W2s : g_W3s);

    int tile = blockIdx.x;
    {
        const uint4* src = Abase + (size_t)tile * 4096;
        unsigned dst = base_u + 2 * WBYTES;
        #pragma unroll
        for (int i = tid; i < 2048; i += 256) {
            int row = i >> 4, ch = i & 15;
            unsigned d = dst + (unsigned)(row * ROWB + ch * 16);
            CP_ASYNC16(d, src + i);
            CP_ASYNC16(d + WBYTES, src + i + 2048);
        }
        CP_COMMIT();
        #pragma unroll
        for (int i = tid; i < 2048; i += 256) {
            int row = i >> 4, ch = i & 15;
            *(uint4*)(sm + row * ROWB + ch * 16)          = Wsrc[i];
            *(uint4*)(sm + WBYTES + row * ROWB + ch * 16) = Wsrc[i + 2048];
        }
        CP_WAIT0();
    }
    __syncthreads();

    const int laneRow = lane & 15;
    const unsigned laneK = (unsigned)((lane >> 4) << 4);
    const unsigned aoff0 = (unsigned)((wm * 32 + laneRow) * ROWB) + laneK;
    const unsigned woff  = (unsigned)((wn * 64 + laneRow) * ROWB) + laneK;

    int buf = 0;
    for (; tile < NTILE; tile += GRID_TC) {
        int nxt = tile + GRID_TC;
        if (nxt < NTILE) {
            const uint4* src = Abase + (size_t)nxt * 4096;
            unsigned dst = base_u + 2 * WBYTES + (unsigned)((buf ^ 1) * ABUF);
            #pragma unroll
            for (int i = tid; i < 2048; i += 256) {
                int row = i >> 4, ch = i & 15;
                unsigned d = dst + (unsigned)(row * ROWB + ch * 16);
                CP_ASYNC16(d, src + i);
                CP_ASYNC16(d + WBYTES, src + i + 2048);
            }
        }
        CP_COMMIT();

        const unsigned sAh_u = base_u + 2 * WBYTES + (unsigned)(buf * ABUF);
        const unsigned sAl_u = sAh_u + WBYTES;

        float acc[2][8][4];
        #pragma unroll
        for (int t = 0; t < 2; t++)
            #pragma unroll
            for (int n = 0; n < 8; n++)
                #pragma unroll
                for (int q = 0; q < 4; q++) acc[t][n][q] = 0.f;

        #pragma unroll 1
        for (int ks = 0; ks < 8; ks++) {
            unsigned kb = (unsigned)(ks * 32);
            unsigned ah[2][4], al[2][4], bw[4][4];
            LDMX4(ah[0], sAh_u + aoff0 + kb);
            LDMX4(ah[1], sAh_u + aoff0 + 16 * ROWB + kb);
            LDMX4(al[0], sAl_u + aoff0 + kb);
            LDMX4(al[1], sAl_u + aoff0 + 16 * ROWB + kb);
            #pragma unroll
            for (int p = 0; p < 4; p++)
                LDMX4(bw[p], sWh_u + woff + p * 16 * ROWB + kb);
            #pragma unroll
            for (int t = 0; t < 2; t++)
                #pragma unroll
                for (int p = 0; p < 4; p++) {
                    MMA_BF16(acc[t][2 * p],     ah[t][0], ah[t][1], ah[t][2], ah[t][3], bw[p][0], bw[p][2]);
                    MMA_BF16(acc[t][2 * p + 1], ah[t][0], ah[t][1], ah[t][2], ah[t][3], bw[p][1], bw[p][3]);
                }
            #pragma unroll
            for (int t = 0; t < 2; t++)
                #pragma unroll
                for (int p = 0; p < 4; p++) {
                    MMA_BF16(acc[t][2 * p],     al[t][0], al[t][1], al[t][2], al[t][3], bw[p][0], bw[p][2]);
                    MMA_BF16(acc[t][2 * p + 1], al[t][0], al[t][1], al[t][2], al[t][3], bw[p][1], bw[p][3]);
                }
            #pragma unroll
            for (int p = 0; p < 4; p++)
                LDMX4(bw[p], sWl_u + woff + p * 16 * ROWB + kb);
            #pragma unroll
            for (int t = 0; t < 2; t++)
                #pragma unroll
                for (int p = 0; p < 4; p++) {
                    MMA_BF16(acc[t][2 * p],     ah[t][0], ah[t][1], ah[t][2], ah[t][3], bw[p][0], bw[p][2]);
                    MMA_BF16(acc[t][2 * p + 1], ah[t][0], ah[t][1], ah[t][2], ah[t][3], bw[p][1], bw[p][3]);
                }
        }
        __syncthreads();

        float* sF = (float*)(sm + 2 * WBYTES + buf * ABUF);
        {
            int mr = lane >> 2;
            int nc = 2 * (lane & 3);
            #pragma unroll
            for (int t = 0; t < 2; t++) {
                int row = wm * 32 + t * 16 + mr;
                #pragma unroll
                for (int nt = 0; nt < 8; nt++) {
                    int col = wn * 64 + nt * 8 + nc;
                    sF[row * 132 + col]           = acc[t][nt][0];
                    sF[row * 132 + col + 1]       = acc[t][nt][1];
                    sF[(row + 8) * 132 + col]     = acc[t][nt][2];
                    sF[(row + 8) * 132 + col + 1] = acc[t][nt][3];
                }
            }
        }
        __syncthreads();

        if (MODE == 0) {
            int rl = tid >> 1, h = tid & 1;
            long gbase = (long)tile * 128;
            bool valid = (gbase + rl) < NEDGE;
            char* outb = (char*)g_a2split + (size_t)tile * 65536;
            uint4* dh = (uint4*)(outb + rl * 256 + h * 128);
            uint4* dl = (uint4*)(outb + 32768 + rl * 256 + h * 128);
            float* fr = sF + rl * 132 + h * 64;
            const float* bp = s_bias + h * 64;
            #pragma unroll
            for (int q = 0; q < 8; q++) {
                unsigned ph[4], pl[4];
                #pragma unroll
                for (int j = 0; j < 4; j++) {
                    int c = q * 8 + j * 2;
                    float v0 = fr[c]     + bp[c];
                    float v1 = fr[c + 1] + bp[c + 1];
                    v0 = (v0 >= 0.f) ? v0 : 0.01f * v0;
                    v1 = (v1 >= 0.f) ? v1 : 0.01f * v1;
                    if (!valid) { v0 = 0.f; v1 = 0.f; }
                    fr[c] = v0; fr[c + 1] = v1;
                    float h0 = __bfloat162float(__float2bfloat16_rn(v0));
                    float h1 = __bfloat162float(__float2bfloat16_rn(v1));
                    ph[j] = pack2bf(h0, h1);
                    pl[j] = pack2bf(v0 - h0, v1 - h1);
                }
                dh[q] = make_uint4(ph[0], ph[1], ph[2], ph[3]);
                dl[q] = make_uint4(pl[0], pl[1], pl[2], pl[3]);
            }
            __syncthreads();
            {
                int c = tid & 127, h2 = tid >> 7;
                float s0 = 0.f, s1 = 0.f;
                #pragma unroll 8
                for (int r = 0; r < 64; r++) {
                    float v = sF[(h2 * 64 + r) * 132 + c];
                    s0 += v; s1 += v * v;
                }
                atomicAdd(&g_sums[2][c], s0);
                atomicAdd(&g_sums[3][c], s1);
            }
        } else {
            int rt = tid >> 1, h = tid & 1;
            long grow = (long)tile * 128 + rt;
            if (grow < NEDGE) {
                int s_ = eidx[grow], d_ = eidx[NEDGE + grow];
                float coeff = cosf(1.5707963267948966f * ea[grow * 4 + 3]);
                const float4* xp = (const float4*)(g_xd + (size_t)s_ * 128) + h * 16;
                float* zp = g_z + (size_t)d_ * 128 + h * 64;
                const float* fr = sF + rt * 132 + h * 64;
                const float* bp = s_bias + h * 64;
                #pragma unroll
                for (int q = 0; q < 16; q++) {
                    float4 xv = xp[q];
                    float v0 = coeff * (fr[4 * q + 0] + bp[4 * q + 0]) * xv.x;
                    float v1 = coeff * (fr[4 * q + 1] + bp[4 * q + 1]) * xv.y;
                    float v2 = coeff * (fr[4 * q + 2] + bp[4 * q + 2]) * xv.z;
                    float v3 = coeff * (fr[4 * q + 3] + bp[4 * q + 3]) * xv.w;
                    asm volatile("red.global.add.v4.f32 [%0], {%1,%2,%3,%4};"
                                 :: "l"(zp + 4 * q), "f"(v0), "f"(v1), "f"(v2), "f"(v3) : "memory");
                }
            }
        }
        __syncthreads();
        CP_WAIT0();
        __syncthreads();
        buf ^= 1;
    }
}

// ---------------- SIMT node GEMMs (N1 / OUT) ----------------
enum { M_N1 = 4, M_OUT = 5 };

template <int MODE>
__global__ __launch_bounds__(256)
void gemm_kernel(const float* __restrict__ Wparam, const float* __restrict__ biasExt,
                 const float* __restrict__ x, float* __restrict__ outp, int M) {
    __shared__ float As[16][132];
    __shared__ float Ws[16][132];

    const int tid = threadIdx.x;
    const int blockRow = blockIdx.x * 128;
    const int tr = tid >> 4;
    const int tc = tid & 15;
    const int c0 = tc * 8;

    const float* W = (MODE == M_OUT) ? g_Wn2p : Wparam;
    const float* bias = (MODE == M_OUT) ? g_bn2p : biasExt;
    const float* Aeff = (MODE == M_N1) ? g_z : g_an;

    const int lr = tid >> 1;
    const int lh = (tid & 1) * 8;
    const float* arow;
    {
        int r = blockRow + lr;
        if (r > M - 1) r = M - 1;
        arow = Aeff + (size_t)r * 128;
    }

    float acc[8][8];
    #pragma unroll
    for (int i = 0; i < 8; i++)
        #pragma unroll
        for (int j = 0; j < 8; j++) acc[i][j] = 0.f;

    #pragma unroll 1
    for (int k0 = 0; k0 < 128; k0 += 16) {
        const float* ap = arow + k0 + lh;
        float4 a0 = *(const float4*)ap;
        float4 a1 = *(const float4*)(ap + 4);
        int krow = k0 + tr;
        float4 b0 = *(const float4*)(W + (size_t)krow * 128 + c0);
        float4 b1 = *(const float4*)(W + (size_t)krow * 128 + c0 + 4);

        __syncthreads();
        As[lh + 0][lr] = a0.x; As[lh + 1][lr] = a0.y;
        As[lh + 2][lr] = a0.z; As[lh + 3][lr] = a0.w;
        As[lh + 4][lr] = a1.x; As[lh + 5][lr] = a1.y;
        As[lh + 6][lr] = a1.z; As[lh + 7][lr] = a1.w;
        *(float4*)&Ws[tr][c0]     = b0;
        *(float4*)&Ws[tr][c0 + 4] = b1;
        __syncthreads();

        #pragma unroll
        for (int kk = 0; kk < 16; kk++) {
            float af[8], bf[8];
            *(float4*)(af)     = *(const float4*)&As[kk][tr * 8];
            *(float4*)(af + 4) = *(const float4*)&As[kk][tr * 8 + 4];
            *(float4*)(bf)     = *(const float4*)&Ws[kk][c0];
            *(float4*)(bf + 4) = *(const float4*)&Ws[kk][c0 + 4];
            #pragma unroll
            for (int i = 0; i < 8; i++)
                #pragma unroll
                for (int j = 0; j < 8; j++)
                    acc[i][j] += af[i] * bf[j];
        }
    }
    __syncthreads();

    float bj[8];
    #pragma unroll
    for (int j = 0; j < 8; j++) bj[j] = bias[c0 + j];

    if (MODE == M_OUT) {
        #pragma unroll
        for (int i = 0; i < 8; i++) {
            int r = blockRow + tr * 8 + i;
            if (r >= M) break;
            const float* xp = x + (size_t)r * 128 + c0;
            float4 x0 = *(const float4*)xp;
            float4 x1 = *(const float4*)(xp + 4);
            float* dp = outp + (size_t)r * 128 + c0;
            *(float4*)dp = make_float4(acc[i][0] + bj[0] + x0.x, acc[i][1] + bj[1] + x0.y,
                                       acc[i][2] + bj[2] + x0.z, acc[i][3] + bj[3] + x0.w);
            *(float4*)(dp + 4) = make_float4(acc[i][4] + bj[4] + x1.x, acc[i][5] + bj[5] + x1.y,
                                             acc[i][6] + bj[6] + x1.z, acc[i][7] + bj[7] + x1.w);
        }
        return;
    }
    // M_N1: lrelu + store + stats
    {
        float csum[8], csq[8];
        #pragma unroll
        for (int j = 0; j < 8; j++) { csum[j] = 0.f; csq[j] = 0.f; }
        #pragma unroll 1
        for (int i = 0; i < 8; i++) {
            int r = blockRow + tr * 8 + i;
            if (r >= M) break;
            float vals[8];
            #pragma unroll
            for (int j = 0; j < 8; j++) {
                float v_ = acc[i][j] + bj[j];
                v_ = (v_ >= 0.f) ? v_ : 0.01f * v_;
                vals[j] = v_; csum[j] += v_; csq[j] += v_ * v_;
            }
            float* dp = g_an + (size_t)r * 128 + c0;
            *(float4*)dp       = make_float4(vals[0], vals[1], vals[2], vals[3]);
            *(float4*)(dp + 4) = make_float4(vals[4], vals[5], vals[6], vals[7]);
        }
        #pragma unroll
        for (int j = 0; j < 8; j++) As[tr][c0 + j] = csum[j];
        __syncthreads();
        if (tid < 128) {
            float s = 0.f;
            #pragma unroll
            for (int t = 0; t < 16; t++) s += As[t][tid];
            atomicAdd(&g_sums[4][tid], s);
        }
        __syncthreads();
        #pragma unroll
        for (int j = 0; j < 8; j++) As[tr][c0 + j] = csq[j];
        __syncthreads();
        if (tid < 128) {
            float s = 0.f;
            #pragma unroll
            for (int t = 0; t < 16; t++) s += As[t][tid];
            atomicAdd(&g_sums[5][tid], s);
        }
    }
}

// ---------------- launcher ----------------
extern "C" void kernel_launch(void* const* d_in, const int* in_sizes, int n_in,
                              void* d_out, int out_size) {
    const float* x    = (const float*)d_in[0];
    const float* ea   = (const float*)d_in[1];
    const int*   eidx = (const int*)  d_in[2];
    const float* Wb   = (const float*)d_in[3];
    const float* bb   = (const float*)d_in[4];
    const float* We1  = (const float*)d_in[5];
    const float* be1  = (const float*)d_in[6];
    const float* ge1  = (const float*)d_in[7];
    const float* bte1 = (const float*)d_in[8];
    const float* We2  = (const float*)d_in[9];
    const float* be2  = (const float*)d_in[10];
    const float* ge2  = (const float*)d_in[11];
    const float* bte2 = (const float*)d_in[12];
    const float* We3  = (const float*)d_in[13];
    const float* be3  = (const float*)d_in[14];
    const float* Wd   = (const float*)d_in[15];
    const float* bd   = (const float*)d_in[16];
    const float* v    = (const float*)d_in[17];
    const float* Wn1  = (const float*)d_in[18];
    const float* bn1  = (const float*)d_in[19];
    const float* gn   = (const float*)d_in[20];
    const float* btn  = (const float*)d_in[21];
    const float* Wn2  = (const float*)d_in[22];
    const float* bn2  = (const float*)d_in[23];
    float* outp = (float*)d_out;

    const int gridN = NTILEN;

    float* d_W2p;  cudaGetSymbolAddress((void**)&d_W2p, g_W2p);
    float* d_W3p;  cudaGetSymbolAddress((void**)&d_W3p, g_W3p);
    char*  d_W2s;  cudaGetSymbolAddress((void**)&d_W2s, g_W2s);
    char*  d_W3s;  cudaGetSymbolAddress((void**)&d_W3s, g_W3s);

    cudaFuncSetAttribute(tc_gemm<0>, cudaFuncAttributeMaxDynamicSharedMemorySize, TCSM_E);
    cudaFuncSetAttribute(tc_gemm<1>, cudaFuncAttributeMaxDynamicSharedMemorySize, TCSM_E);
    cudaFuncSetAttribute(tc_node, cudaFuncAttributeMaxDynamicSharedMemorySize, TCSM_N);

    zero_stats<<<1, 768>>>();
    wbwe1_kernel<<<200, 128>>>(Wb, We1);
    cvec_kernel<<<1, 128>>>(bb, We1, be1);
    table_kernel<<<4 * GTAB, 128>>>();
    xsplit_kernel<<<NTILEN, 256>>>(x);
    packnode_kernel<<<384, 128>>>(We1, Wd);

    // xtop | xbot | xd,z via tensor cores
    tc_node<<<gridN, 256, TCSM_N>>>(bd, v);

    e1_fuse_kernel<<<NTILE, 128>>>(ea, eidx);
    fold_kernel<<<129, 128>>>(0, 1.0f / NEDGE, ge1, bte1, We2, be2);
    pack_kernel<<<128, 128>>>(d_W2p, d_W2s);

    tc_gemm<0><<<GRID_TC, 256, TCSM_E>>>(ea, eidx);
    fold_kernel<<<129, 128>>>(2, 1.0f / NEDGE, ge2, bte2, We3, be3);
    pack_kernel<<<128, 128>>>(d_W3p, d_W3s);

    tc_gemm<1><<<GRID_TC, 256, TCSM_E>>>(ea, eidx);

    gemm_kernel<M_N1><<<gridN, 256>>>(Wn1, bn1, nullptr, nullptr, NNODE);
    fold_kernel<<<129, 128>>>(4, 1.0f / NNODE, gn, btn, Wn2, bn2);
    gemm_kernel<M_OUT><<<gridN, 256>>>(nullptr, nullptr, x, outp, NNODE);
}

// round 13
// speedup vs baseline: 1.7086x; 1.0593x over previous
#include <cuda_runtime.h>
#include <cuda_bf16.h>
#include <cuda_fp16.h>

#define NNODE 50000
#define NNPAD 50048             // 391 * 128
#define NEDGE 300000
#define GTAB  1024
#define EPSBN 1e-5f
#define NTILE 2344              // ceil(NEDGE/128)
#define NTILEN 391              // ceil(NNODE/128)
#define ROWB  272               // padded smem row bytes (136 bf16)
#define WBYTES 34816            // 128 * ROWB
#define ABUF   69632            // Ah+Al per buffer
#define TCSM_E (3 * 69632)      // persistent edge gemm: W(hi+lo) + 2 A buffers
#define TCSM_N (2 * 69632)      // node gemm: A(hi+lo) + W(hi+lo)
#define GRID_TC 148

// ---------------- scratch (device globals; no allocation) ----------------
__device__ uint4 g_a1split[(size_t)NTILE * 4096];  // per tile: 32KB hi | 32KB lo, [m][k] 256B rows
__device__ uint4 g_a2split[(size_t)NTILE * 4096];
__device__ uint4 g_W2s[4096];                      // 64KB: W^T [n][k] hi | lo
__device__ uint4 g_W3s[4096];
__device__ uint4 g_Wn1s[4096];
__device__ uint4 g_Wn2s[4096];
__device__ uint4 g_xs_hi[(size_t)NNPAD * 16];      // x bf16-hi, [m][k] 256B rows
__device__ uint4 g_xs_lo[(size_t)NNPAD * 16];
__device__ uint4 g_zs_hi[(size_t)NNPAD * 16];
__device__ uint4 g_zs_lo[(size_t)NNPAD * 16];
__device__ uint4 g_ans_hi[(size_t)NNPAD * 16];
__device__ uint4 g_ans_lo[(size_t)NNPAD * 16];
__device__ uint4 g_Wns[12288];                     // 192KB: [384 n][128 k] hi (96KB) | lo (96KB)
__device__ float g_xd[(size_t)NNODE * 128];
__device__ float g_z [(size_t)NNODE * 128];
__device__ float g_xtop[(size_t)NNODE * 128];
__device__ float g_xbot[(size_t)NNODE * 128];
__device__ float g_tab[4 * GTAB * 128];
__device__ __half g_tabh[4 * GTAB * 128];
__device__ float g_WbWe1[200 * 128];
__device__ float g_cvec[128];
__device__ float g_W2p[128 * 128];  __device__ float g_b2p[128];
__device__ float g_W3p[128 * 128];  __device__ float g_b3p[128];
__device__ float g_Wn2p[128 * 128]; __device__ float g_bn2p[128];
__device__ float g_sums[6][128];

// ---------------- helpers ----------------
__device__ __forceinline__ unsigned smem_u32(const void* p) {
    unsigned a;
    asm("{ .reg .u64 t; cvta.to.shared.u64 t, %1; cvt.u32.u64 %0, t; }" : "=r"(a) : "l"(p));
    return a;
}
#define CP_ASYNC16(dst, src)                                                   \
    asm volatile("cp.async.cg.shared.global [%0], [%1], 16;"                   \
                 :: "r"(dst), "l"(src) : "memory")
#define CP_COMMIT() asm volatile("cp.async.commit_group;" ::: "memory")
#define CP_WAIT0()  asm volatile("cp.async.wait_group 0;" ::: "memory")
#define LDMX4(r, addr)                                                         \
    asm volatile("ldmatrix.sync.aligned.m8n8.x4.shared.b16 {%0,%1,%2,%3}, [%4];" \
                 : "=r"((r)[0]), "=r"((r)[1]), "=r"((r)[2]), "=r"((r)[3])      \
                 : "r"(addr))
#define MMA_BF16(d, a0, a1, a2, a3, b0, b1)                                    \
    asm volatile("mma.sync.aligned.m16n8k16.row.col.f32.bf16.bf16.f32 "        \
                 "{%0,%1,%2,%3}, {%4,%5,%6,%7}, {%8,%9}, {%0,%1,%2,%3};"       \
                 : "+f"((d)[0]), "+f"((d)[1]), "+f"((d)[2]), "+f"((d)[3])      \
                 : "r"(a0), "r"(a1), "r"(a2), "r"(a3), "r"(b0), "r"(b1))
static __device__ __forceinline__ unsigned pack2bf(float a, float b) {
    return ((unsigned)__bfloat16_as_ushort(__float2bfloat16_rn(b)) << 16)
         |  (unsigned)__bfloat16_as_ushort(__float2bfloat16_rn(a));
}

// ---------------- tiny prep kernels ----------------
__global__ void zero_stats() { ((float*)g_sums)[threadIdx.x] = 0.0f; }

__global__ void wbwe1_kernel(const float* __restrict__ Wb, const float* __restrict__ We1) {
    int r = blockIdx.x, n = threadIdx.x;
    float acc = 0.f;
    #pragma unroll 8
    for (int k = 0; k < 128; k++) acc += Wb[r * 128 + k] * We1[(128 + k) * 128 + n];
    g_WbWe1[r * 128 + n] = acc;
}

__global__ void cvec_kernel(const float* __restrict__ bb, const float* __restrict__ We1,
                            const float* __restrict__ be1) {
    int n = threadIdx.x;
    float acc = be1[n];
    #pragma unroll 8
    for (int k = 0; k < 128; k++) acc += bb[k] * We1[(128 + k) * 128 + n];
    g_cvec[n] = acc;
}

__global__ void table_kernel() {
    __shared__ float gs[64];
    int b = blockIdx.x;
    int c = b >> 10;
    int gi = b & (GTAB - 1);
    float u = (float)gi * (1.0f / (GTAB - 1));
    int tid = threadIdx.x;
    if (tid < 50) {
        float d = u - (float)tid * (1.0f / 49.0f);
        gs[tid] = __expf(-d * d * 1250.0f);
    }
    __syncthreads();
    float acc = 0.f;
    #pragma unroll
    for (int j = 0; j < 50; j++) acc += gs[j] * g_WbWe1[(c * 50 + j) * 128 + tid];
    g_tab[b * 128 + tid] = acc;
    g_tabh[b * 128 + tid] = __float2half(acc);
}

__global__ void fold_kernel(int sidx, float invM,
                            const float* __restrict__ gamma, const float* __restrict__ beta,
                            const float* __restrict__ Wsrc, const float* __restrict__ be) {
    float* Wdst = (sidx == 0) ? g_W2p : (sidx == 2) ? g_W3p : g_Wn2p;
    float* bdst = (sidx == 0) ? g_b2p : (sidx == 2) ? g_b3p : g_bn2p;
    int n = threadIdx.x;
    if (blockIdx.x < 128) {
        int k = blockIdx.x;
        float m = g_sums[sidx][k] * invM;
        float var = g_sums[sidx + 1][k] * invM - m * m;
        float s = gamma[k] * rsqrtf(var + EPSBN);
        Wdst[k * 128 + n] = s * Wsrc[k * 128 + n];
    } else {
        float acc = be[n];
        for (int k = 0; k < 128; k++) {
            float m = g_sums[sidx][k] * invM;
            float var = g_sums[sidx + 1][k] * invM - m * m;
            float s = gamma[k] * rsqrtf(var + EPSBN);
            acc += (beta[k] - m * s) * Wsrc[k * 128 + n];
        }
        bdst[n] = acc;
    }
}

// Pack W^T ([n][k] row-major, 256B rows) into bf16 hi/lo staging (64KB)
__global__ void pack_kernel(const float* __restrict__ Wp, char* __restrict__ Ws) {
    int n = blockIdx.x, k = threadIdx.x;
    float v = Wp[k * 128 + n];
    float h = __bfloat162float(__float2bfloat16_rn(v));
    int off = n * 256 + 2 * k;
    *(unsigned short*)(Ws + off)         = __bfloat16_as_ushort(__float2bfloat16_rn(h));
    *(unsigned short*)(Ws + 32768 + off) = __bfloat16_as_ushort(__float2bfloat16_rn(v - h));
}

// Pack node weights: n<128 -> We1_top^T, n<256 -> We1_bot^T, else Wd^T
__global__ void packnode_kernel(const float* __restrict__ We1, const float* __restrict__ Wd) {
    int n = blockIdx.x, k = threadIdx.x;
    float v;
    if (n < 128)       v = We1[k * 128 + n];
    else if (n < 256)  v = We1[(256 + k) * 128 + (n - 128)];
    else               v = Wd[k * 128 + (n - 256)];
    float h = __bfloat162float(__float2bfloat16_rn(v));
    char* Ws = (char*)g_Wns;
    int off = n * 256 + 2 * k;
    *(unsigned short*)(Ws + off)         = __bfloat16_as_ushort(__float2bfloat16_rn(h));
    *(unsigned short*)(Ws + 98304 + off) = __bfloat16_as_ushort(__float2bfloat16_rn(v - h));
}

// Split fp32 node array into bf16 hi/lo padded arrays
__global__ __launch_bounds__(256)
void split_kernel(const float* __restrict__ src, char* __restrict__ hb, char* __restrict__ lb) {
    int base = blockIdx.x * 16384;
    #pragma unroll
    for (int i = 0; i < 64; i++) {
        int idx = base + threadIdx.x + i * 256;
        float v = (idx < NNODE * 128) ? __ldg(src + idx) : 0.f;
        float h = __bfloat162float(__float2bfloat16_rn(v));
        *(unsigned short*)(hb + 2 * (size_t)idx) = __bfloat16_as_ushort(__float2bfloat16_rn(h));
        *(unsigned short*)(lb + 2 * (size_t)idx) = __bfloat16_as_ushort(__float2bfloat16_rn(v - h));
    }
}

// ---------------- fused E1 -> bf16 hi/lo tiles (half table, zero smem) ----------------
__global__ __launch_bounds__(128)
void e1_fuse_kernel(const float* __restrict__ ea, const int* __restrict__ eidx) {
    int t = threadIdx.x;
    int e0 = blockIdx.x * 128;
    char* tb = (char*)g_a1split + (size_t)blockIdx.x * 65536;
    float cv = g_cvec[t];
    float csum = 0.f, csq = 0.f;
    int eend = e0 + 128;
    if (eend > NEDGE) eend = NEDGE;
    #pragma unroll 4
    for (int e = e0; e < eend; e++) {
        int s = __ldg(eidx + e);
        int d = __ldg(eidx + NEDGE + e);
        float4 eav = __ldg((const float4*)ea + e);
        float val = g_xtop[(size_t)s * 128 + t] + g_xbot[(size_t)d * 128 + t] + cv;
        float fa[4] = {eav.x, eav.y, eav.z, eav.w};
        #pragma unroll
        for (int c = 0; c < 4; c++) {
            float p = fa[c] * (float)(GTAB - 1);
            int i0 = (int)p;
            if (i0 < 0) i0 = 0;
            if (i0 > GTAB - 2) i0 = GTAB - 2;
            float w = p - (float)i0;
            const __half* t0 = g_tabh + ((size_t)(c * GTAB + i0) * 128 + t);
            float u = __half2float(t0[0]), v2 = __half2float(t0[128]);
            val += u + w * (v2 - u);
        }
        val = (val >= 0.f) ? val : 0.01f * val;
        csum += val; csq += val * val;
        float h = __bfloat162float(__float2bfloat16_rn(val));
        int off = (e - e0) * 256 + 2 * t;
        *(unsigned short*)(tb + off)         = __bfloat16_as_ushort(__float2bfloat16_rn(h));
        *(unsigned short*)(tb + 32768 + off) = __bfloat16_as_ushort(__float2bfloat16_rn(val - h));
    }
    for (int e = eend; e < e0 + 128; e++) {
        int off = (e - e0) * 256 + 2 * t;
        *(unsigned short*)(tb + off) = 0;
        *(unsigned short*)(tb + 32768 + off) = 0;
    }
    atomicAdd(&g_sums[0][t], csum);
    atomicAdd(&g_sums[1][t], csq);
}

// ---------------- tc node GEMM: [xtop | xbot | xd,z] = x @ Wns (3 chunks of N=128) ----------------
__global__ __launch_bounds__(256)
void tc_node(const float* __restrict__ bd, const float* __restrict__ vparam) {
    extern __shared__ char sm[];
    __shared__ float s_bd[128], s_v[128];
    const int tid = threadIdx.x;
    const int lane = tid & 31, wid = tid >> 5;
    const int wm = wid & 3, wn = wid >> 2;

    if (tid < 128) { s_bd[tid] = bd[tid]; s_v[tid] = vparam[tid]; }

    const unsigned base_u = smem_u32(sm);
    const unsigned sAh_u = base_u;
    const unsigned sAl_u = base_u + WBYTES;
    const unsigned sWh_u = base_u + 2 * WBYTES;
    const unsigned sWl_u = base_u + 3 * WBYTES;

    const int gbase = blockIdx.x * 128;
    {
        const uint4* hsrc = g_xs_hi + (size_t)gbase * 16;
        const uint4* lsrc = g_xs_lo + (size_t)gbase * 16;
        #pragma unroll
        for (int i = tid; i < 2048; i += 256) {
            int row = i >> 4, ch = i & 15;
            *(uint4*)(sm + row * ROWB + ch * 16)          = hsrc[i];
            *(uint4*)(sm + WBYTES + row * ROWB + ch * 16) = lsrc[i];
        }
    }

    const int laneRow = lane & 15;
    const unsigned laneK = (unsigned)((lane >> 4) << 4);
    const unsigned aoff = (unsigned)((wm * 32 + laneRow) * ROWB) + laneK;
    const unsigned woff = (unsigned)((wn * 64 + laneRow) * ROWB) + laneK;

    #pragma unroll 1
    for (int chunk = 0; chunk < 3; chunk++) {
        {
            const uint4* whs = g_Wns + (size_t)chunk * 2048;
            const uint4* wls = g_Wns + 6144 + (size_t)chunk * 2048;
            #pragma unroll
            for (int i = tid; i < 2048; i += 256) {
                int row = i >> 4, ch = i & 15;
                *(uint4*)(sm + 2 * WBYTES + row * ROWB + ch * 16) = whs[i];
                *(uint4*)(sm + 3 * WBYTES + row * ROWB + ch * 16) = wls[i];
            }
        }
        __syncthreads();

        float acc[2][8][4];
        #pragma unroll
        for (int t = 0; t < 2; t++)
            #pragma unroll
            for (int n = 0; n < 8; n++)
                #pragma unroll
                for (int q = 0; q < 4; q++) acc[t][n][q] = 0.f;

        #pragma unroll 1
        for (int ks = 0; ks < 8; ks++) {
            unsigned kb = (unsigned)(ks * 32);
            unsigned ah[2][4], al[2][4], bw[4][4];
            LDMX4(ah[0], sAh_u + aoff + kb);
            LDMX4(ah[1], sAh_u + aoff + 16 * ROWB + kb);
            LDMX4(al[0], sAl_u + aoff + kb);
            LDMX4(al[1], sAl_u + aoff + 16 * ROWB + kb);
            #pragma unroll
            for (int p = 0; p < 4; p++)
                LDMX4(bw[p], sWh_u + woff + p * 16 * ROWB + kb);
            #pragma unroll
            for (int t = 0; t < 2; t++)
                #pragma unroll
                for (int p = 0; p < 4; p++) {
                    MMA_BF16(acc[t][2 * p],     ah[t][0], ah[t][1], ah[t][2], ah[t][3], bw[p][0], bw[p][2]);
                    MMA_BF16(acc[t][2 * p + 1], ah[t][0], ah[t][1], ah[t][2], ah[t][3], bw[p][1], bw[p][3]);
                }
            #pragma unroll
            for (int t = 0; t < 2; t++)
                #pragma unroll
                for (int p = 0; p < 4; p++) {
                    MMA_BF16(acc[t][2 * p],     al[t][0], al[t][1], al[t][2], al[t][3], bw[p][0], bw[p][2]);
                    MMA_BF16(acc[t][2 * p + 1], al[t][0], al[t][1], al[t][2], al[t][3], bw[p][1], bw[p][3]);
                }
            #pragma unroll
            for (int p = 0; p < 4; p++)
                LDMX4(bw[p], sWl_u + woff + p * 16 * ROWB + kb);
            #pragma unroll
            for (int t = 0; t < 2; t++)
                #pragma unroll
                for (int p = 0; p < 4; p++) {
                    MMA_BF16(acc[t][2 * p],     ah[t][0], ah[t][1], ah[t][2], ah[t][3], bw[p][0], bw[p][2]);
                    MMA_BF16(acc[t][2 * p + 1], ah[t][0], ah[t][1], ah[t][2], ah[t][3], bw[p][1], bw[p][3]);
                }
        }
        __syncthreads();

        float* sF = (float*)(sm + 2 * WBYTES);
        {
            int mr = lane >> 2;
            int nc = 2 * (lane & 3);
            #pragma unroll
            for (int t = 0; t < 2; t++) {
                int row = wm * 32 + t * 16 + mr;
                #pragma unroll
                for (int nt = 0; nt < 8; nt++) {
                    int col = wn * 64 + nt * 8 + nc;
                    sF[row * 132 + col]           = acc[t][nt][0];
                    sF[row * 132 + col + 1]       = acc[t][nt][1];
                    sF[(row + 8) * 132 + col]     = acc[t][nt][2];
                    sF[(row + 8) * 132 + col + 1] = acc[t][nt][3];
                }
            }
        }
        __syncthreads();

        {
            int rl = tid >> 1, h = tid & 1;
            int grow = gbase + rl;
            if (grow < NNODE) {
                const float* fr = sF + rl * 132 + h * 64;
                if (chunk == 0) {
                    float* dp = g_xtop + (size_t)grow * 128 + h * 64;
                    #pragma unroll
                    for (int q = 0; q < 16; q++)
                        ((float4*)dp)[q] = make_float4(fr[4*q], fr[4*q+1], fr[4*q+2], fr[4*q+3]);
                } else if (chunk == 1) {
                    float* dp = g_xbot + (size_t)grow * 128 + h * 64;
                    #pragma unroll
                    for (int q = 0; q < 16; q++)
                        ((float4*)dp)[q] = make_float4(fr[4*q], fr[4*q+1], fr[4*q+2], fr[4*q+3]);
                } else {
                    float* dx = g_xd + (size_t)grow * 128 + h * 64;
                    float* dz = g_z  + (size_t)grow * 128 + h * 64;
                    const float* bp = s_bd + h * 64;
                    const float* vp = s_v + h * 64;
                    #pragma unroll
                    for (int q = 0; q < 16; q++) {
                        float x0 = fr[4*q]   + bp[4*q];
                        float x1 = fr[4*q+1] + bp[4*q+1];
                        float x2 = fr[4*q+2] + bp[4*q+2];
                        float x3 = fr[4*q+3] + bp[4*q+3];
                        ((float4*)dx)[q] = make_float4(x0, x1, x2, x3);
                        ((float4*)dz)[q] = make_float4(vp[4*q]*x0, vp[4*q+1]*x1, vp[4*q+2]*x2, vp[4*q+3]*x3);
                    }
                }
            }
        }
        __syncthreads();
    }
}

// ---------------- tc node GEMM 2: MODE 0 = N1 (z@Wn1, lrelu, stats, split an), MODE 1 = OUT ----------------
template <int MODE>
__global__ __launch_bounds__(256)
void tc_node2(const float* __restrict__ biasExt, const float* __restrict__ x,
              float* __restrict__ outp) {
    extern __shared__ char sm[];
    __shared__ float s_bias[128];
    const int tid = threadIdx.x;
    const int lane = tid & 31, wid = tid >> 5;
    const int wm = wid & 3, wn = wid >> 2;

    if (tid < 128) s_bias[tid] = (MODE == 0) ? biasExt[tid] : g_bn2p[tid];

    const unsigned base_u = smem_u32(sm);
    const unsigned sAh_u = base_u;
    const unsigned sAl_u = base_u + WBYTES;
    const unsigned sWh_u = base_u + 2 * WBYTES;
    const unsigned sWl_u = base_u + 3 * WBYTES;

    const int gbase = blockIdx.x * 128;
    {
        const uint4* hsrc = (MODE == 0 ? g_zs_hi : g_ans_hi) + (size_t)gbase * 16;
        const uint4* lsrc = (MODE == 0 ? g_zs_lo : g_ans_lo) + (size_t)gbase * 16;
        const uint4* whs  = (MODE == 0 ? g_Wn1s : g_Wn2s);
        #pragma unroll
        for (int i = tid; i < 2048; i += 256) {
            int row = i >> 4, ch = i & 15;
            *(uint4*)(sm + row * ROWB + ch * 16)              = hsrc[i];
            *(uint4*)(sm + WBYTES + row * ROWB + ch * 16)     = lsrc[i];
            *(uint4*)(sm + 2 * WBYTES + row * ROWB + ch * 16) = whs[i];
            *(uint4*)(sm + 3 * WBYTES + row * ROWB + ch * 16) = whs[i + 2048];
        }
    }
    __syncthreads();

    const int laneRow = lane & 15;
    const unsigned laneK = (unsigned)((lane >> 4) << 4);
    const unsigned aoff = (unsigned)((wm * 32 + laneRow) * ROWB) + laneK;
    const unsigned woff = (unsigned)((wn * 64 + laneRow) * ROWB) + laneK;

    float acc[2][8][4];
    #pragma unroll
    for (int t = 0; t < 2; t++)
        #pragma unroll
        for (int n = 0; n < 8; n++)
            #pragma unroll
            for (int q = 0; q < 4; q++) acc[t][n][q] = 0.f;

    #pragma unroll 1
    for (int ks = 0; ks < 8; ks++) {
        unsigned kb = (unsigned)(ks * 32);
        unsigned ah[2][4], al[2][4], bw[4][4];
        LDMX4(ah[0], sAh_u + aoff + kb);
        LDMX4(ah[1], sAh_u + aoff + 16 * ROWB + kb);
        LDMX4(al[0], sAl_u + aoff + kb);
        LDMX4(al[1], sAl_u + aoff + 16 * ROWB + kb);
        #pragma unroll
        for (int p = 0; p < 4; p++)
            LDMX4(bw[p], sWh_u + woff + p * 16 * ROWB + kb);
        #pragma unroll
        for (int t = 0; t < 2; t++)
            #pragma unroll
            for (int p = 0; p < 4; p++) {
                MMA_BF16(acc[t][2 * p],     ah[t][0], ah[t][1], ah[t][2], ah[t][3], bw[p][0], bw[p][2]);
                MMA_BF16(acc[t][2 * p + 1], ah[t][0], ah[t][1], ah[t][2], ah[t][3], bw[p][1], bw[p][3]);
            }
        #pragma unroll
        for (int t = 0; t < 2; t++)
            #pragma unroll
            for (int p = 0; p < 4; p++) {
                MMA_BF16(acc[t][2 * p],     al[t][0], al[t][1], al[t][2], al[t][3], bw[p][0], bw[p][2]);
                MMA_BF16(acc[t][2 * p + 1], al[t][0], al[t][1], al[t][2], al[t][3], bw[p][1], bw[p][3]);
            }
        #pragma unroll
        for (int p = 0; p < 4; p++)
            LDMX4(bw[p], sWl_u + woff + p * 16 * ROWB + kb);
        #pragma unroll
        for (int t = 0; t < 2; t++)
            #pragma unroll
            for (int p = 0; p < 4; p++) {
                MMA_BF16(acc[t][2 * p],     ah[t][0], ah[t][1], ah[t][2], ah[t][3], bw[p][0], bw[p][2]);
                MMA_BF16(acc[t][2 * p + 1], ah[t][0], ah[t][1], ah[t][2], ah[t][3], bw[p][1], bw[p][3]);
            }
    }
    __syncthreads();

    float* sF = (float*)(sm + 2 * WBYTES);
    {
        int mr = lane >> 2;
        int nc = 2 * (lane & 3);
        #pragma unroll
        for (int t = 0; t < 2; t++) {
            int row = wm * 32 + t * 16 + mr;
            #pragma unroll
            for (int nt = 0; nt < 8; nt++) {
                int col = wn * 64 + nt * 8 + nc;
                sF[row * 132 + col]           = acc[t][nt][0];
                sF[row * 132 + col + 1]       = acc[t][nt][1];
                sF[(row + 8) * 132 + col]     = acc[t][nt][2];
                sF[(row + 8) * 132 + col + 1] = acc[t][nt][3];
            }
        }
    }
    __syncthreads();

    if (MODE == 0) {
        // bias + lrelu, write back, split an to hi/lo, stats
        int rl = tid >> 1, h = tid & 1;
        int grow = gbase + rl;
        bool valid = grow < NNODE;
        float* fr = sF + rl * 132 + h * 64;
        const float* bp = s_bias + h * 64;
        uint4* dh = (uint4*)((char*)g_ans_hi + (size_t)grow * 256 + h * 128);
        uint4* dl = (uint4*)((char*)g_ans_lo + (size_t)grow * 256 + h * 128);
        #pragma unroll
        for (int q = 0; q < 8; q++) {
            unsigned ph[4], pl[4];
            #pragma unroll
            for (int j = 0; j < 4; j++) {
                int c = q * 8 + j * 2;
                float v0 = fr[c]     + bp[c];
                float v1 = fr[c + 1] + bp[c + 1];
                v0 = (v0 >= 0.f) ? v0 : 0.01f * v0;
                v1 = (v1 >= 0.f) ? v1 : 0.01f * v1;
                if (!valid) { v0 = 0.f; v1 = 0.f; }
                fr[c] = v0; fr[c + 1] = v1;
                float h0 = __bfloat162float(__float2bfloat16_rn(v0));
                float h1 = __bfloat162float(__float2bfloat16_rn(v1));
                ph[j] = pack2bf(h0, h1);
                pl[j] = pack2bf(v0 - h0, v1 - h1);
            }
            dh[q] = make_uint4(ph[0], ph[1], ph[2], ph[3]);
            dl[q] = make_uint4(pl[0], pl[1], pl[2], pl[3]);
        }
        __syncthreads();
        {
            int c = tid & 127, h2 = tid >> 7;
            float s0 = 0.f, s1 = 0.f;
            #pragma unroll 8
            for (int r = 0; r < 64; r++) {
                float v = sF[(h2 * 64 + r) * 132 + c];
                s0 += v; s1 += v * v;
            }
            atomicAdd(&g_sums[4][c], s0);
            atomicAdd(&g_sums[5][c], s1);
        }
    } else {
        int rl = tid >> 1, h = tid & 1;
        int grow = gbase + rl;
        if (grow < NNODE) {
            const float* fr = sF + rl * 132 + h * 64;
            const float* bp = s_bias + h * 64;
            const float4* xp = (const float4*)(x + (size_t)grow * 128 + h * 64);
            float* dp = outp + (size_t)grow * 128 + h * 64;
            #pragma unroll
            for (int q = 0; q < 16; q++) {
                float4 xv = xp[q];
                ((float4*)dp)[q] = make_float4(fr[4*q]   + bp[4*q]   + xv.x,
                                               fr[4*q+1] + bp[4*q+1] + xv.y,
                                               fr[4*q+2] + bp[4*q+2] + xv.z,
                                               fr[4*q+3] + bp[4*q+3] + xv.w);
            }
        }
    }
}

// ---------------- persistent bf16 tensor-core edge GEMMs (cp.async double buffer) ----------------
// MODE 0 = E2, MODE 1 = E3
template <int MODE>
__global__ __launch_bounds__(256)
void tc_gemm(const float* __restrict__ ea, const int* __restrict__ eidx) {
    extern __shared__ char sm[];
    __shared__ float s_bias[128];
    const int tid = threadIdx.x;
    const int lane = tid & 31, wid = tid >> 5;
    const int wm = wid & 3, wn = wid >> 2;

    const unsigned base_u = smem_u32(sm);
    const unsigned sWh_u = base_u;
    const unsigned sWl_u = base_u + WBYTES;

    if (tid < 128) s_bias[tid] = (MODE == 0) ? g_b2p[tid] : g_b3p[tid];

    const uint4* Abase = (MODE == 0 ? g_a1split : g_a2split);
    const uint4* Wsrc  = (MODE == 0 ? g_W2s : g_W3s);

    int tile = blockIdx.x;
    {
        const uint4* src = Abase + (size_t)tile * 4096;
        unsigned dst = base_u + 2 * WBYTES;
        #pragma unroll
        for (int i = tid; i < 2048; i += 256) {
            int row = i >> 4, ch = i & 15;
            unsigned d = dst + (unsigned)(row * ROWB + ch * 16);
            CP_ASYNC16(d, src + i);
            CP_ASYNC16(d + WBYTES, src + i + 2048);
        }
        CP_COMMIT();
        #pragma unroll
        for (int i = tid; i < 2048; i += 256) {
            int row = i >> 4, ch = i & 15;
            *(uint4*)(sm + row * ROWB + ch * 16)          = Wsrc[i];
            *(uint4*)(sm + WBYTES + row * ROWB + ch * 16) = Wsrc[i + 2048];
        }
        CP_WAIT0();
    }
    __syncthreads();

    const int laneRow = lane & 15;
    const unsigned laneK = (unsigned)((lane >> 4) << 4);
    const unsigned aoff0 = (unsigned)((wm * 32 + laneRow) * ROWB) + laneK;
    const unsigned woff  = (unsigned)((wn * 64 + laneRow) * ROWB) + laneK;

    int buf = 0;
    for (; tile < NTILE; tile += GRID_TC) {
        int nxt = tile + GRID_TC;
        if (nxt < NTILE) {
            const uint4* src = Abase + (size_t)nxt * 4096;
            unsigned dst = base_u + 2 * WBYTES + (unsigned)((buf ^ 1) * ABUF);
            #pragma unroll
            for (int i = tid; i < 2048; i += 256) {
                int row = i >> 4, ch = i & 15;
                unsigned d = dst + (unsigned)(row * ROWB + ch * 16);
                CP_ASYNC16(d, src + i);
                CP_ASYNC16(d + WBYTES, src + i + 2048);
            }
        }
        CP_COMMIT();

        const unsigned sAh_u = base_u + 2 * WBYTES + (unsigned)(buf * ABUF);
        const unsigned sAl_u = sAh_u + WBYTES;

        float acc[2][8][4];
        #pragma unroll
        for (int t = 0; t < 2; t++)
            #pragma unroll
            for (int n = 0; n < 8; n++)
                #pragma unroll
                for (int q = 0; q < 4; q++) acc[t][n][q] = 0.f;

        #pragma unroll 1
        for (int ks = 0; ks < 8; ks++) {
            unsigned kb = (unsigned)(ks * 32);
            unsigned ah[2][4], al[2][4], bw[4][4];
            LDMX4(ah[0], sAh_u + aoff0 + kb);
            LDMX4(ah[1], sAh_u + aoff0 + 16 * ROWB + kb);
            LDMX4(al[0], sAl_u + aoff0 + kb);
            LDMX4(al[1], sAl_u + aoff0 + 16 * ROWB + kb);
            #pragma unroll
            for (int p = 0; p < 4; p++)
                LDMX4(bw[p], sWh_u + woff + p * 16 * ROWB + kb);
            #pragma unroll
            for (int t = 0; t < 2; t++)
                #pragma unroll
                for (int p = 0; p < 4; p++) {
                    MMA_BF16(acc[t][2 * p],     ah[t][0], ah[t][1], ah[t][2], ah[t][3], bw[p][0], bw[p][2]);
                    MMA_BF16(acc[t][2 * p + 1], ah[t][0], ah[t][1], ah[t][2], ah[t][3], bw[p][1], bw[p][3]);
                }
            #pragma unroll
            for (int t = 0; t < 2; t++)
                #pragma unroll
                for (int p = 0; p < 4; p++) {
                    MMA_BF16(acc[t][2 * p],     al[t][0], al[t][1], al[t][2], al[t][3], bw[p][0], bw[p][2]);
                    MMA_BF16(acc[t][2 * p + 1], al[t][0], al[t][1], al[t][2], al[t][3], bw[p][1], bw[p][3]);
                }
            #pragma unroll
            for (int p = 0; p < 4; p++)
                LDMX4(bw[p], sWl_u + woff + p * 16 * ROWB + kb);
            #pragma unroll
            for (int t = 0; t < 2; t++)
                #pragma unroll
                for (int p = 0; p < 4; p++) {
                    MMA_BF16(acc[t][2 * p],     ah[t][0], ah[t][1], ah[t][2], ah[t][3], bw[p][0], bw[p][2]);
                    MMA_BF16(acc[t][2 * p + 1], ah[t][0], ah[t][1], ah[t][2], ah[t][3], bw[p][1], bw[p][3]);
                }
        }
        __syncthreads();

        float* sF = (float*)(sm + 2 * WBYTES + buf * ABUF);
        {
            int mr = lane >> 2;
            int nc = 2 * (lane & 3);
            #pragma unroll
            for (int t = 0; t < 2; t++) {
                int row = wm * 32 + t * 16 + mr;
                #pragma unroll
                for (int nt = 0; nt < 8; nt++) {
                    int col = wn * 64 + nt * 8 + nc;
                    sF[row * 132 + col]           = acc[t][nt][0];
                    sF[row * 132 + col + 1]       = acc[t][nt][1];
                    sF[(row + 8) * 132 + col]     = acc[t][nt][2];
                    sF[(row + 8) * 132 + col + 1] = acc[t][nt][3];
                }
            }
        }
        __syncthreads();

        if (MODE == 0) {
            int rl = tid >> 1, h = tid & 1;
            long gbase = (long)tile * 128;
            bool valid = (gbase + rl) < NEDGE;
            char* outb = (char*)g_a2split + (size_t)tile * 65536;
            uint4* dh = (uint4*)(outb + rl * 256 + h * 128);
            uint4* dl = (uint4*)(outb + 32768 + rl * 256 + h * 128);
            float* fr = sF + rl * 132 + h * 64;
            const float* bp = s_bias + h * 64;
            #pragma unroll
            for (int q = 0; q < 8; q++) {
                unsigned ph[4], pl[4];
                #pragma unroll
                for (int j = 0; j < 4; j++) {
                    int c = q * 8 + j * 2;
                    float v0 = fr[c]     + bp[c];
                    float v1 = fr[c + 1] + bp[c + 1];
                    v0 = (v0 >= 0.f) ? v0 : 0.01f * v0;
                    v1 = (v1 >= 0.f) ? v1 : 0.01f * v1;
                    if (!valid) { v0 = 0.f; v1 = 0.f; }
                    fr[c] = v0; fr[c + 1] = v1;
                    float h0 = __bfloat162float(__float2bfloat16_rn(v0));
                    float h1 = __bfloat162float(__float2bfloat16_rn(v1));
                    ph[j] = pack2bf(h0, h1);
                    pl[j] = pack2bf(v0 - h0, v1 - h1);
                }
                dh[q] = make_uint4(ph[0], ph[1], ph[2], ph[3]);
                dl[q] = make_uint4(pl[0], pl[1], pl[2], pl[3]);
            }
            __syncthreads();
            {
                int c = tid & 127, h2 = tid >> 7;
                float s0 = 0.f, s1 = 0.f;
                #pragma unroll 8
                for (int r = 0; r < 64; r++) {
                    float v = sF[(h2 * 64 + r) * 132 + c];
                    s0 += v; s1 += v * v;
                }
                atomicAdd(&g_sums[2][c], s0);
                atomicAdd(&g_sums[3][c], s1);
            }
        } else {
            int rt = tid >> 1, h = tid & 1;
            long grow = (long)tile * 128 + rt;
            if (grow < NEDGE) {
                int s_ = eidx[grow], d_ = eidx[NEDGE + grow];
                float coeff = cosf(1.5707963267948966f * ea[grow * 4 + 3]);
                const float4* xp = (const float4*)(g_xd + (size_t)s_ * 128) + h * 16;
                float* zp = g_z + (size_t)d_ * 128 + h * 64;
                const float* fr = sF + rt * 132 + h * 64;
                const float* bp = s_bias + h * 64;
                #pragma unroll
                for (int q = 0; q < 16; q++) {
                    float4 xv = xp[q];
                    float v0 = coeff * (fr[4 * q + 0] + bp[4 * q + 0]) * xv.x;
                    float v1 = coeff * (fr[4 * q + 1] + bp[4 * q + 1]) * xv.y;
                    float v2 = coeff * (fr[4 * q + 2] + bp[4 * q + 2]) * xv.z;
                    float v3 = coeff * (fr[4 * q + 3] + bp[4 * q + 3]) * xv.w;
                    asm volatile("red.global.add.v4.f32 [%0], {%1,%2,%3,%4};"
                                 :: "l"(zp + 4 * q), "f"(v0), "f"(v1), "f"(v2), "f"(v3) : "memory");
                }
            }
        }
        __syncthreads();
        CP_WAIT0();
        __syncthreads();
        buf ^= 1;
    }
}

// ---------------- launcher ----------------
extern "C" void kernel_launch(void* const* d_in, const int* in_sizes, int n_in,
                              void* d_out, int out_size) {
    const float* x    = (const float*)d_in[0];
    const float* ea   = (const float*)d_in[1];
    const int*   eidx = (const int*)  d_in[2];
    const float* Wb   = (const float*)d_in[3];
    const float* bb   = (const float*)d_in[4];
    const float* We1  = (const float*)d_in[5];
    const float* be1  = (const float*)d_in[6];
    const float* ge1  = (const float*)d_in[7];
    const float* bte1 = (const float*)d_in[8];
    const float* We2  = (const float*)d_in[9];
    const float* be2  = (const float*)d_in[10];
    const float* ge2  = (const float*)d_in[11];
    const float* bte2 = (const float*)d_in[12];
    const float* We3  = (const float*)d_in[13];
    const float* be3  = (const float*)d_in[14];
    const float* Wd   = (const float*)d_in[15];
    const float* bd   = (const float*)d_in[16];
    const float* v    = (const float*)d_in[17];
    const float* Wn1  = (const float*)d_in[18];
    const float* bn1  = (const float*)d_in[19];
    const float* gn   = (const float*)d_in[20];
    const float* btn  = (const float*)d_in[21];
    const float* Wn2  = (const float*)d_in[22];
    const float* bn2  = (const float*)d_in[23];
    float* outp = (float*)d_out;

    float* d_z;    cudaGetSymbolAddress((void**)&d_z, g_z);
    float* d_W2p;  cudaGetSymbolAddress((void**)&d_W2p, g_W2p);
    float* d_W3p;  cudaGetSymbolAddress((void**)&d_W3p, g_W3p);
    float* d_Wn2p; cudaGetSymbolAddress((void**)&d_Wn2p, g_Wn2p);
    char*  d_W2s;  cudaGetSymbolAddress((void**)&d_W2s, g_W2s);
    char*  d_W3s;  cudaGetSymbolAddress((void**)&d_W3s, g_W3s);
    char*  d_Wn1s; cudaGetSymbolAddress((void**)&d_Wn1s, g_Wn1s);
    char*  d_Wn2s; cudaGetSymbolAddress((void**)&d_Wn2s, g_Wn2s);
    char*  d_xsh;  cudaGetSymbolAddress((void**)&d_xsh, g_xs_hi);
    char*  d_xsl;  cudaGetSymbolAddress((void**)&d_xsl, g_xs_lo);
    char*  d_zsh;  cudaGetSymbolAddress((void**)&d_zsh, g_zs_hi);
    char*  d_zsl;  cudaGetSymbolAddress((void**)&d_zsl, g_zs_lo);

    cudaFuncSetAttribute(tc_gemm<0>, cudaFuncAttributeMaxDynamicSharedMemorySize, TCSM_E);
    cudaFuncSetAttribute(tc_gemm<1>, cudaFuncAttributeMaxDynamicSharedMemorySize, TCSM_E);
    cudaFuncSetAttribute(tc_node, cudaFuncAttributeMaxDynamicSharedMemorySize, TCSM_N);
    cudaFuncSetAttribute(tc_node2<0>, cudaFuncAttributeMaxDynamicSharedMemorySize, TCSM_N);
    cudaFuncSetAttribute(tc_node2<1>, cudaFuncAttributeMaxDynamicSharedMemorySize, TCSM_N);

    zero_stats<<<1, 768>>>();
    wbwe1_kernel<<<200, 128>>>(Wb, We1);
    cvec_kernel<<<1, 128>>>(bb, We1, be1);
    table_kernel<<<4 * GTAB, 128>>>();
    split_kernel<<<NTILEN, 256>>>(x, d_xsh, d_xsl);
    packnode_kernel<<<384, 128>>>(We1, Wd);
    pack_kernel<<<128, 128>>>(Wn1, d_Wn1s);

    tc_node<<<NTILEN, 256, TCSM_N>>>(bd, v);

    e1_fuse_kernel<<<NTILE, 128>>>(ea, eidx);
    fold_kernel<<<129, 128>>>(0, 1.0f / NEDGE, ge1, bte1, We2, be2);
    pack_kernel<<<128, 128>>>(d_W2p, d_W2s);

    tc_gemm<0><<<GRID_TC, 256, TCSM_E>>>(ea, eidx);
    fold_kernel<<<129, 128>>>(2, 1.0f / NEDGE, ge2, bte2, We3, be3);
    pack_kernel<<<128, 128>>>(d_W3p, d_W3s);

    tc_gemm<1><<<GRID_TC, 256, TCSM_E>>>(ea, eidx);

    split_kernel<<<NTILEN, 256>>>(d_z, d_zsh, d_zsl);
    tc_node2<0><<<NTILEN, 256, TCSM_N>>>(bn1, nullptr, nullptr);
    fold_kernel<<<129, 128>>>(4, 1.0f / NNODE, gn, btn, Wn2, bn2);
    pack_kernel<<<128, 128>>>(d_Wn2p, d_Wn2s);
    tc_node2<1><<<NTILEN, 256, TCSM_N>>>(nullptr, x, outp);
}

// round 14
// speedup vs baseline: 1.8593x; 1.0882x over previous
#include <cuda_runtime.h>
#include <cuda_bf16.h>
#include <cuda_fp16.h>

#define NNODE 50000
#define NNPAD 50048             // 391 * 128
#define NEDGE 300000
#define GTAB  1024
#define EPSBN 1e-5f
#define NTILE 2344              // ceil(NEDGE/128)
#define NTILEN 391              // ceil(NNODE/128)
#define ROWB  272               // padded smem row bytes (136 elems)
#define WBYTES 34816            // 128 * ROWB
#define ABUF   69632            // Ah+Al per buffer
#define TCSM_E (WBYTES + 2 * ABUF)   // 174080: W(single fp16) + 2 A buffers
#define TCSM_N (2 * 69632)      // node gemm: A(hi+lo) + W(hi+lo)
#define GRID_TC 148

// ---------------- scratch (device globals; no allocation) ----------------
__device__ uint4 g_a1split[(size_t)NTILE * 4096];  // per tile: 32KB fp16-hi | 32KB fp16-lo, [m][k] 256B rows
__device__ uint4 g_a2split[(size_t)NTILE * 4096];
__device__ uint4 g_W2s[2048];                      // 32KB: W^T [n][k] single fp16
__device__ uint4 g_W3s[2048];
__device__ uint4 g_Wn1s[4096];                     // bf16 hi|lo (node)
__device__ uint4 g_Wn2s[4096];
__device__ uint4 g_xs_hi[(size_t)NNPAD * 16];      // x bf16-hi, [m][k] 256B rows
__device__ uint4 g_xs_lo[(size_t)NNPAD * 16];
__device__ uint4 g_zs_hi[(size_t)NNPAD * 16];
__device__ uint4 g_zs_lo[(size_t)NNPAD * 16];
__device__ uint4 g_ans_hi[(size_t)NNPAD * 16];
__device__ uint4 g_ans_lo[(size_t)NNPAD * 16];
__device__ uint4 g_Wns[12288];                     // 192KB: [384 n][128 k] bf16 hi (96KB) | lo (96KB)
__device__ float g_xd[(size_t)NNODE * 128];
__device__ float g_z [(size_t)NNODE * 128];
__device__ float g_xtop[(size_t)NNODE * 128];
__device__ float g_xbot[(size_t)NNODE * 128];
__device__ float g_tab[4 * GTAB * 128];
__device__ __half g_tabh[4 * GTAB * 128];
__device__ float g_WbWe1[200 * 128];
__device__ float g_cvec[128];
__device__ float g_W2p[128 * 128];  __device__ float g_b2p[128];
__device__ float g_W3p[128 * 128];  __device__ float g_b3p[128];
__device__ float g_Wn2p[128 * 128]; __device__ float g_bn2p[128];
__device__ float g_sums[6][128];

// ---------------- helpers ----------------
__device__ __forceinline__ unsigned smem_u32(const void* p) {
    unsigned a;
    asm("{ .reg .u64 t; cvta.to.shared.u64 t, %1; cvt.u32.u64 %0, t; }" : "=r"(a) : "l"(p));
    return a;
}
#define CP_ASYNC16(dst, src)                                                   \
    asm volatile("cp.async.cg.shared.global [%0], [%1], 16;"                   \
                 :: "r"(dst), "l"(src) : "memory")
#define CP_COMMIT() asm volatile("cp.async.commit_group;" ::: "memory")
#define CP_WAIT0()  asm volatile("cp.async.wait_group 0;" ::: "memory")
#define LDMX4(r, addr)                                                         \
    asm volatile("ldmatrix.sync.aligned.m8n8.x4.shared.b16 {%0,%1,%2,%3}, [%4];" \
                 : "=r"((r)[0]), "=r"((r)[1]), "=r"((r)[2]), "=r"((r)[3])      \
                 : "r"(addr))
#define MMA_BF16(d, a0, a1, a2, a3, b0, b1)                                    \
    asm volatile("mma.sync.aligned.m16n8k16.row.col.f32.bf16.bf16.f32 "        \
                 "{%0,%1,%2,%3}, {%4,%5,%6,%7}, {%8,%9}, {%0,%1,%2,%3};"       \
                 : "+f"((d)[0]), "+f"((d)[1]), "+f"((d)[2]), "+f"((d)[3])      \
                 : "r"(a0), "r"(a1), "r"(a2), "r"(a3), "r"(b0), "r"(b1))
#define MMA_F16(d, a0, a1, a2, a3, b0, b1)                                     \
    asm volatile("mma.sync.aligned.m16n8k16.row.col.f32.f16.f16.f32 "          \
                 "{%0,%1,%2,%3}, {%4,%5,%6,%7}, {%8,%9}, {%0,%1,%2,%3};"       \
                 : "+f"((d)[0]), "+f"((d)[1]), "+f"((d)[2]), "+f"((d)[3])      \
                 : "r"(a0), "r"(a1), "r"(a2), "r"(a3), "r"(b0), "r"(b1))
static __device__ __forceinline__ unsigned pack2bf(float a, float b) {
    return ((unsigned)__bfloat16_as_ushort(__float2bfloat16_rn(b)) << 16)
         |  (unsigned)__bfloat16_as_ushort(__float2bfloat16_rn(a));
}
static __device__ __forceinline__ unsigned pack2h(float a, float b) {
    return ((unsigned)__half_as_ushort(__float2half_rn(b)) << 16)
         |  (unsigned)__half_as_ushort(__float2half_rn(a));
}

// ---------------- tiny prep kernels ----------------
__global__ void zero_stats() { ((float*)g_sums)[threadIdx.x] = 0.0f; }

__global__ void wbwe1_kernel(const float* __restrict__ Wb, const float* __restrict__ We1) {
    int r = blockIdx.x, n = threadIdx.x;
    float acc = 0.f;
    #pragma unroll 8
    for (int k = 0; k < 128; k++) acc += Wb[r * 128 + k] * We1[(128 + k) * 128 + n];
    g_WbWe1[r * 128 + n] = acc;
}

__global__ void cvec_kernel(const float* __restrict__ bb, const float* __restrict__ We1,
                            const float* __restrict__ be1) {
    int n = threadIdx.x;
    float acc = be1[n];
    #pragma unroll 8
    for (int k = 0; k < 128; k++) acc += bb[k] * We1[(128 + k) * 128 + n];
    g_cvec[n] = acc;
}

__global__ void table_kernel() {
    __shared__ float gs[64];
    int b = blockIdx.x;
    int c = b >> 10;
    int gi = b & (GTAB - 1);
    float u = (float)gi * (1.0f / (GTAB - 1));
    int tid = threadIdx.x;
    if (tid < 50) {
        float d = u - (float)tid * (1.0f / 49.0f);
        gs[tid] = __expf(-d * d * 1250.0f);
    }
    __syncthreads();
    float acc = 0.f;
    #pragma unroll
    for (int j = 0; j < 50; j++) acc += gs[j] * g_WbWe1[(c * 50 + j) * 128 + tid];
    g_tab[b * 128 + tid] = acc;
    g_tabh[b * 128 + tid] = __float2half(acc);
}

__global__ void fold_kernel(int sidx, float invM,
                            const float* __restrict__ gamma, const float* __restrict__ beta,
                            const float* __restrict__ Wsrc, const float* __restrict__ be) {
    float* Wdst = (sidx == 0) ? g_W2p : (sidx == 2) ? g_W3p : g_Wn2p;
    float* bdst = (sidx == 0) ? g_b2p : (sidx == 2) ? g_b3p : g_bn2p;
    int n = threadIdx.x;
    if (blockIdx.x < 128) {
        int k = blockIdx.x;
        float m = g_sums[sidx][k] * invM;
        float var = g_sums[sidx + 1][k] * invM - m * m;
        float s = gamma[k] * rsqrtf(var + EPSBN);
        Wdst[k * 128 + n] = s * Wsrc[k * 128 + n];
    } else {
        float acc = be[n];
        for (int k = 0; k < 128; k++) {
            float m = g_sums[sidx][k] * invM;
            float var = g_sums[sidx + 1][k] * invM - m * m;
            float s = gamma[k] * rsqrtf(var + EPSBN);
            acc += (beta[k] - m * s) * Wsrc[k * 128 + n];
        }
        bdst[n] = acc;
    }
}

// Pack W^T into single fp16 (edge GEMMs), 32KB
__global__ void packh_kernel(const float* __restrict__ Wp, char* __restrict__ Ws) {
    int n = blockIdx.x, k = threadIdx.x;
    float v = Wp[k * 128 + n];
    *(unsigned short*)(Ws + n * 256 + 2 * k) = __half_as_ushort(__float2half_rn(v));
}

// Pack W^T into bf16 hi/lo (node GEMMs), 64KB
__global__ void pack_kernel(const float* __restrict__ Wp, char* __restrict__ Ws) {
    int n = blockIdx.x, k = threadIdx.x;
    float v = Wp[k * 128 + n];
    float h = __bfloat162float(__float2bfloat16_rn(v));
    int off = n * 256 + 2 * k;
    *(unsigned short*)(Ws + off)         = __bfloat16_as_ushort(__float2bfloat16_rn(h));
    *(unsigned short*)(Ws + 32768 + off) = __bfloat16_as_ushort(__float2bfloat16_rn(v - h));
}

// Pack node weights: n<128 -> We1_top^T, n<256 -> We1_bot^T, else Wd^T (bf16 hi/lo)
__global__ void packnode_kernel(const float* __restrict__ We1, const float* __restrict__ Wd) {
    int n = blockIdx.x, k = threadIdx.x;
    float v;
    if (n < 128)       v = We1[k * 128 + n];
    else if (n < 256)  v = We1[(256 + k) * 128 + (n - 128)];
    else               v = Wd[k * 128 + (n - 256)];
    float h = __bfloat162float(__float2bfloat16_rn(v));
    char* Ws = (char*)g_Wns;
    int off = n * 256 + 2 * k;
    *(unsigned short*)(Ws + off)         = __bfloat16_as_ushort(__float2bfloat16_rn(h));
    *(unsigned short*)(Ws + 98304 + off) = __bfloat16_as_ushort(__float2bfloat16_rn(v - h));
}

// Split fp32 node array into bf16 hi/lo padded arrays
__global__ __launch_bounds__(256)
void split_kernel(const float* __restrict__ src, char* __restrict__ hb, char* __restrict__ lb) {
    int base = blockIdx.x * 16384;
    #pragma unroll
    for (int i = 0; i < 64; i++) {
        int idx = base + threadIdx.x + i * 256;
        float v = (idx < NNODE * 128) ? __ldg(src + idx) : 0.f;
        float h = __bfloat162float(__float2bfloat16_rn(v));
        *(unsigned short*)(hb + 2 * (size_t)idx) = __bfloat16_as_ushort(__float2bfloat16_rn(h));
        *(unsigned short*)(lb + 2 * (size_t)idx) = __bfloat16_as_ushort(__float2bfloat16_rn(v - h));
    }
}

// ---------------- fused E1 -> fp16 hi/lo tiles (half table, zero smem) ----------------
__global__ __launch_bounds__(128)
void e1_fuse_kernel(const float* __restrict__ ea, const int* __restrict__ eidx) {
    int t = threadIdx.x;
    int e0 = blockIdx.x * 128;
    char* tb = (char*)g_a1split + (size_t)blockIdx.x * 65536;
    float cv = g_cvec[t];
    float csum = 0.f, csq = 0.f;
    int eend = e0 + 128;
    if (eend > NEDGE) eend = NEDGE;
    #pragma unroll 4
    for (int e = e0; e < eend; e++) {
        int s = __ldg(eidx + e);
        int d = __ldg(eidx + NEDGE + e);
        float4 eav = __ldg((const float4*)ea + e);
        float val = g_xtop[(size_t)s * 128 + t] + g_xbot[(size_t)d * 128 + t] + cv;
        float fa[4] = {eav.x, eav.y, eav.z, eav.w};
        #pragma unroll
        for (int c = 0; c < 4; c++) {
            float p = fa[c] * (float)(GTAB - 1);
            int i0 = (int)p;
            if (i0 < 0) i0 = 0;
            if (i0 > GTAB - 2) i0 = GTAB - 2;
            float w = p - (float)i0;
            const __half* t0 = g_tabh + ((size_t)(c * GTAB + i0) * 128 + t);
            float u = __half2float(t0[0]), v2 = __half2float(t0[128]);
            val += u + w * (v2 - u);
        }
        val = (val >= 0.f) ? val : 0.01f * val;
        csum += val; csq += val * val;
        __half hh = __float2half_rn(val);
        int off = (e - e0) * 256 + 2 * t;
        *(unsigned short*)(tb + off)         = __half_as_ushort(hh);
        *(unsigned short*)(tb + 32768 + off) = __half_as_ushort(__float2half_rn(val - __half2float(hh)));
    }
    for (int e = eend; e < e0 + 128; e++) {
        int off = (e - e0) * 256 + 2 * t;
        *(unsigned short*)(tb + off) = 0;
        *(unsigned short*)(tb + 32768 + off) = 0;
    }
    atomicAdd(&g_sums[0][t], csum);
    atomicAdd(&g_sums[1][t], csq);
}

// ---------------- tc node GEMM: [xtop | xbot | xd,z] = x @ Wns (bf16 3-product) ----------------
__global__ __launch_bounds__(256)
void tc_node(const float* __restrict__ bd, const float* __restrict__ vparam) {
    extern __shared__ char sm[];
    __shared__ float s_bd[128], s_v[128];
    const int tid = threadIdx.x;
    const int lane = tid & 31, wid = tid >> 5;
    const int wm = wid & 3, wn = wid >> 2;

    if (tid < 128) { s_bd[tid] = bd[tid]; s_v[tid] = vparam[tid]; }

    const unsigned base_u = smem_u32(sm);
    const unsigned sAh_u = base_u;
    const unsigned sAl_u = base_u + WBYTES;
    const unsigned sWh_u = base_u + 2 * WBYTES;
    const unsigned sWl_u = base_u + 3 * WBYTES;

    const int gbase = blockIdx.x * 128;
    {
        const uint4* hsrc = g_xs_hi + (size_t)gbase * 16;
        const uint4* lsrc = g_xs_lo + (size_t)gbase * 16;
        #pragma unroll
        for (int i = tid; i < 2048; i += 256) {
            int row = i >> 4, ch = i & 15;
            *(uint4*)(sm + row * ROWB + ch * 16)          = hsrc[i];
            *(uint4*)(sm + WBYTES + row * ROWB + ch * 16) = lsrc[i];
        }
    }

    const int laneRow = lane & 15;
    const unsigned laneK = (unsigned)((lane >> 4) << 4);
    const unsigned aoff = (unsigned)((wm * 32 + laneRow) * ROWB) + laneK;
    const unsigned woff = (unsigned)((wn * 64 + laneRow) * ROWB) + laneK;

    #pragma unroll 1
    for (int chunk = 0; chunk < 3; chunk++) {
        {
            const uint4* whs = g_Wns + (size_t)chunk * 2048;
            const uint4* wls = g_Wns + 6144 + (size_t)chunk * 2048;
            #pragma unroll
            for (int i = tid; i < 2048; i += 256) {
                int row = i >> 4, ch = i & 15;
                *(uint4*)(sm + 2 * WBYTES + row * ROWB + ch * 16) = whs[i];
                *(uint4*)(sm + 3 * WBYTES + row * ROWB + ch * 16) = wls[i];
            }
        }
        __syncthreads();

        float acc[2][8][4];
        #pragma unroll
        for (int t = 0; t < 2; t++)
            #pragma unroll
            for (int n = 0; n < 8; n++)
                #pragma unroll
                for (int q = 0; q < 4; q++) acc[t][n][q] = 0.f;

        #pragma unroll 1
        for (int ks = 0; ks < 8; ks++) {
            unsigned kb = (unsigned)(ks * 32);
            unsigned ah[2][4], al[2][4], bw[4][4];
            LDMX4(ah[0], sAh_u + aoff + kb);
            LDMX4(ah[1], sAh_u + aoff + 16 * ROWB + kb);
            LDMX4(al[0], sAl_u + aoff + kb);
            LDMX4(al[1], sAl_u + aoff + 16 * ROWB + kb);
            #pragma unroll
            for (int p = 0; p < 4; p++)
                LDMX4(bw[p], sWh_u + woff + p * 16 * ROWB + kb);
            #pragma unroll
            for (int t = 0; t < 2; t++)
                #pragma unroll
                for (int p = 0; p < 4; p++) {
                    MMA_BF16(acc[t][2 * p],     ah[t][0], ah[t][1], ah[t][2], ah[t][3], bw[p][0], bw[p][2]);
                    MMA_BF16(acc[t][2 * p + 1], ah[t][0], ah[t][1], ah[t][2], ah[t][3], bw[p][1], bw[p][3]);
                    MMA_BF16(acc[t][2 * p],     al[t][0], al[t][1], al[t][2], al[t][3], bw[p][0], bw[p][2]);
                    MMA_BF16(acc[t][2 * p + 1], al[t][0], al[t][1], al[t][2], al[t][3], bw[p][1], bw[p][3]);
                }
            #pragma unroll
            for (int p = 0; p < 4; p++)
                LDMX4(bw[p], sWl_u + woff + p * 16 * ROWB + kb);
            #pragma unroll
            for (int t = 0; t < 2; t++)
                #pragma unroll
                for (int p = 0; p < 4; p++) {
                    MMA_BF16(acc[t][2 * p],     ah[t][0], ah[t][1], ah[t][2], ah[t][3], bw[p][0], bw[p][2]);
                    MMA_BF16(acc[t][2 * p + 1], ah[t][0], ah[t][1], ah[t][2], ah[t][3], bw[p][1], bw[p][3]);
                }
        }
        __syncthreads();

        float* sF = (float*)(sm + 2 * WBYTES);
        {
            int mr = lane >> 2;
            int nc = 2 * (lane & 3);
            #pragma unroll
            for (int t = 0; t < 2; t++) {
                int row = wm * 32 + t * 16 + mr;
                #pragma unroll
                for (int nt = 0; nt < 8; nt++) {
                    int col = wn * 64 + nt * 8 + nc;
                    sF[row * 132 + col]           = acc[t][nt][0];
                    sF[row * 132 + col + 1]       = acc[t][nt][1];
                    sF[(row + 8) * 132 + col]     = acc[t][nt][2];
                    sF[(row + 8) * 132 + col + 1] = acc[t][nt][3];
                }
            }
        }
        __syncthreads();

        {
            int rl = tid >> 1, h = tid & 1;
            int grow = gbase + rl;
            if (grow < NNODE) {
                const float* fr = sF + rl * 132 + h * 64;
                if (chunk == 0) {
                    float* dp = g_xtop + (size_t)grow * 128 + h * 64;
                    #pragma unroll
                    for (int q = 0; q < 16; q++)
                        ((float4*)dp)[q] = make_float4(fr[4*q], fr[4*q+1], fr[4*q+2], fr[4*q+3]);
                } else if (chunk == 1) {
                    float* dp = g_xbot + (size_t)grow * 128 + h * 64;
                    #pragma unroll
                    for (int q = 0; q < 16; q++)
                        ((float4*)dp)[q] = make_float4(fr[4*q], fr[4*q+1], fr[4*q+2], fr[4*q+3]);
                } else {
                    float* dx = g_xd + (size_t)grow * 128 + h * 64;
                    float* dz = g_z  + (size_t)grow * 128 + h * 64;
                    const float* bp = s_bd + h * 64;
                    const float* vp = s_v + h * 64;
                    #pragma unroll
                    for (int q = 0; q < 16; q++) {
                        float x0 = fr[4*q]   + bp[4*q];
                        float x1 = fr[4*q+1] + bp[4*q+1];
                        float x2 = fr[4*q+2] + bp[4*q+2];
                        float x3 = fr[4*q+3] + bp[4*q+3];
                        ((float4*)dx)[q] = make_float4(x0, x1, x2, x3);
                        ((float4*)dz)[q] = make_float4(vp[4*q]*x0, vp[4*q+1]*x1, vp[4*q+2]*x2, vp[4*q+3]*x3);
                    }
                }
            }
        }
        __syncthreads();
    }
}

// ---------------- tc node GEMM 2: MODE 0 = N1, MODE 1 = OUT (bf16 3-product) ----------------
template <int MODE>
__global__ __launch_bounds__(256)
void tc_node2(const float* __restrict__ biasExt, const float* __restrict__ x,
              float* __restrict__ outp) {
    extern __shared__ char sm[];
    __shared__ float s_bias[128];
    const int tid = threadIdx.x;
    const int lane = tid & 31, wid = tid >> 5;
    const int wm = wid & 3, wn = wid >> 2;

    if (tid < 128) s_bias[tid] = (MODE == 0) ? biasExt[tid] : g_bn2p[tid];

    const unsigned base_u = smem_u32(sm);
    const unsigned sAh_u = base_u;
    const unsigned sAl_u = base_u + WBYTES;
    const unsigned sWh_u = base_u + 2 * WBYTES;
    const unsigned sWl_u = base_u + 3 * WBYTES;

    const int gbase = blockIdx.x * 128;
    {
        const uint4* hsrc = (MODE == 0 ? g_zs_hi : g_ans_hi) + (size_t)gbase * 16;
        const uint4* lsrc = (MODE == 0 ? g_zs_lo : g_ans_lo) + (size_t)gbase * 16;
        const uint4* whs  = (MODE == 0 ? g_Wn1s : g_Wn2s);
        #pragma unroll
        for (int i = tid; i < 2048; i += 256) {
            int row = i >> 4, ch = i & 15;
            *(uint4*)(sm + row * ROWB + ch * 16)              = hsrc[i];
            *(uint4*)(sm + WBYTES + row * ROWB + ch * 16)     = lsrc[i];
            *(uint4*)(sm + 2 * WBYTES + row * ROWB + ch * 16) = whs[i];
            *(uint4*)(sm + 3 * WBYTES + row * ROWB + ch * 16) = whs[i + 2048];
        }
    }
    __syncthreads();

    const int laneRow = lane & 15;
    const unsigned laneK = (unsigned)((lane >> 4) << 4);
    const unsigned aoff = (unsigned)((wm * 32 + laneRow) * ROWB) + laneK;
    const unsigned woff = (unsigned)((wn * 64 + laneRow) * ROWB) + laneK;

    float acc[2][8][4];
    #pragma unroll
    for (int t = 0; t < 2; t++)
        #pragma unroll
        for (int n = 0; n < 8; n++)
            #pragma unroll
            for (int q = 0; q < 4; q++) acc[t][n][q] = 0.f;

    #pragma unroll 1
    for (int ks = 0; ks < 8; ks++) {
        unsigned kb = (unsigned)(ks * 32);
        unsigned ah[2][4], al[2][4], bw[4][4];
        LDMX4(ah[0], sAh_u + aoff + kb);
        LDMX4(ah[1], sAh_u + aoff + 16 * ROWB + kb);
        LDMX4(al[0], sAl_u + aoff + kb);
        LDMX4(al[1], sAl_u + aoff + 16 * ROWB + kb);
        #pragma unroll
        for (int p = 0; p < 4; p++)
            LDMX4(bw[p], sWh_u + woff + p * 16 * ROWB + kb);
        #pragma unroll
        for (int t = 0; t < 2; t++)
            #pragma unroll
            for (int p = 0; p < 4; p++) {
                MMA_BF16(acc[t][2 * p],     ah[t][0], ah[t][1], ah[t][2], ah[t][3], bw[p][0], bw[p][2]);
                MMA_BF16(acc[t][2 * p + 1], ah[t][0], ah[t][1], ah[t][2], ah[t][3], bw[p][1], bw[p][3]);
                MMA_BF16(acc[t][2 * p],     al[t][0], al[t][1], al[t][2], al[t][3], bw[p][0], bw[p][2]);
                MMA_BF16(acc[t][2 * p + 1], al[t][0], al[t][1], al[t][2], al[t][3], bw[p][1], bw[p][3]);
            }
        #pragma unroll
        for (int p = 0; p < 4; p++)
            LDMX4(bw[p], sWl_u + woff + p * 16 * ROWB + kb);
        #pragma unroll
        for (int t = 0; t < 2; t++)
            #pragma unroll
            for (int p = 0; p < 4; p++) {
                MMA_BF16(acc[t][2 * p],     ah[t][0], ah[t][1], ah[t][2], ah[t][3], bw[p][0], bw[p][2]);
                MMA_BF16(acc[t][2 * p + 1], ah[t][0], ah[t][1], ah[t][2], ah[t][3], bw[p][1], bw[p][3]);
            }
    }
    __syncthreads();

    float* sF = (float*)(sm + 2 * WBYTES);
    {
        int mr = lane >> 2;
        int nc = 2 * (lane & 3);
        #pragma unroll
        for (int t = 0; t < 2; t++) {
            int row = wm * 32 + t * 16 + mr;
            #pragma unroll
            for (int nt = 0; nt < 8; nt++) {
                int col = wn * 64 + nt * 8 + nc;
                sF[row * 132 + col]           = acc[t][nt][0];
                sF[row * 132 + col + 1]       = acc[t][nt][1];
                sF[(row + 8) * 132 + col]     = acc[t][nt][2];
                sF[(row + 8) * 132 + col + 1] = acc[t][nt][3];
            }
        }
    }
    __syncthreads();

    if (MODE == 0) {
        int rl = tid >> 1, h = tid & 1;
        int grow = gbase + rl;
        bool valid = grow < NNODE;
        float* fr = sF + rl * 132 + h * 64;
        const float* bp = s_bias + h * 64;
        uint4* dh = (uint4*)((char*)g_ans_hi + (size_t)grow * 256 + h * 128);
        uint4* dl = (uint4*)((char*)g_ans_lo + (size_t)grow * 256 + h * 128);
        #pragma unroll
        for (int q = 0; q < 8; q++) {
            unsigned ph[4], pl[4];
            #pragma unroll
            for (int j = 0; j < 4; j++) {
                int c = q * 8 + j * 2;
                float v0 = fr[c]     + bp[c];
                float v1 = fr[c + 1] + bp[c + 1];
                v0 = (v0 >= 0.f) ? v0 : 0.01f * v0;
                v1 = (v1 >= 0.f) ? v1 : 0.01f * v1;
                if (!valid) { v0 = 0.f; v1 = 0.f; }
                fr[c] = v0; fr[c + 1] = v1;
                float h0 = __bfloat162float(__float2bfloat16_rn(v0));
                float h1 = __bfloat162float(__float2bfloat16_rn(v1));
                ph[j] = pack2bf(h0, h1);
                pl[j] = pack2bf(v0 - h0, v1 - h1);
            }
            dh[q] = make_uint4(ph[0], ph[1], ph[2], ph[3]);
            dl[q] = make_uint4(pl[0], pl[1], pl[2], pl[3]);
        }
        __syncthreads();
        {
            int c = tid & 127, h2 = tid >> 7;
            float s0 = 0.f, s1 = 0.f;
            #pragma unroll 8
            for (int r = 0; r < 64; r++) {
                float v = sF[(h2 * 64 + r) * 132 + c];
                s0 += v; s1 += v * v;
            }
            atomicAdd(&g_sums[4][c], s0);
            atomicAdd(&g_sums[5][c], s1);
        }
    } else {
        int rl = tid >> 1, h = tid & 1;
        int grow = gbase + rl;
        if (grow < NNODE) {
            const float* fr = sF + rl * 132 + h * 64;
            const float* bp = s_bias + h * 64;
            const float4* xp = (const float4*)(x + (size_t)grow * 128 + h * 64);
            float* dp = outp + (size_t)grow * 128 + h * 64;
            #pragma unroll
            for (int q = 0; q < 16; q++) {
                float4 xv = xp[q];
                ((float4*)dp)[q] = make_float4(fr[4*q]   + bp[4*q]   + xv.x,
                                               fr[4*q+1] + bp[4*q+1] + xv.y,
                                               fr[4*q+2] + bp[4*q+2] + xv.z,
                                               fr[4*q+3] + bp[4*q+3] + xv.w);
            }
        }
    }
}

// ---------------- persistent fp16 2-product edge GEMMs (cp.async double buffer) ----------------
// MODE 0 = E2, MODE 1 = E3
template <int MODE>
__global__ __launch_bounds__(256)
void tc_gemm(const float* __restrict__ ea, const int* __restrict__ eidx) {
    extern __shared__ char sm[];
    __shared__ float s_bias[128];
    const int tid = threadIdx.x;
    const int lane = tid & 31, wid = tid >> 5;
    const int wm = wid & 3, wn = wid >> 2;

    const unsigned base_u = smem_u32(sm);
    const unsigned sW_u = base_u;           // single fp16 W, 34816

    if (tid < 128) s_bias[tid] = (MODE == 0) ? g_b2p[tid] : g_b3p[tid];

    const uint4* Abase = (MODE == 0 ? g_a1split : g_a2split);
    const uint4* Wsrc  = (MODE == 0 ? g_W2s : g_W3s);

    int tile = blockIdx.x;
    {
        const uint4* src = Abase + (size_t)tile * 4096;
        unsigned dst = base_u + WBYTES;     // A buf0
        #pragma unroll
        for (int i = tid; i < 2048; i += 256) {
            int row = i >> 4, ch = i & 15;
            unsigned d = dst + (unsigned)(row * ROWB + ch * 16);
            CP_ASYNC16(d, src + i);
            CP_ASYNC16(d + WBYTES, src + i + 2048);
        }
        CP_COMMIT();
        #pragma unroll
        for (int i = tid; i < 2048; i += 256) {
            int row = i >> 4, ch = i & 15;
            *(uint4*)(sm + row * ROWB + ch * 16) = Wsrc[i];
        }
        CP_WAIT0();
    }
    __syncthreads();

    const int laneRow = lane & 15;
    const unsigned laneK = (unsigned)((lane >> 4) << 4);
    const unsigned aoff0 = (unsigned)((wm * 32 + laneRow) * ROWB) + laneK;
    const unsigned woff  = (unsigned)((wn * 64 + laneRow) * ROWB) + laneK;

    int buf = 0;
    for (; tile < NTILE; tile += GRID_TC) {
        int nxt = tile + GRID_TC;
        if (nxt < NTILE) {
            const uint4* src = Abase + (size_t)nxt * 4096;
            unsigned dst = base_u + WBYTES + (unsigned)((buf ^ 1) * ABUF);
            #pragma unroll
            for (int i = tid; i < 2048; i += 256) {
                int row = i >> 4, ch = i & 15;
                unsigned d = dst + (unsigned)(row * ROWB + ch * 16);
                CP_ASYNC16(d, src + i);
                CP_ASYNC16(d + WBYTES, src + i + 2048);
            }
        }
        CP_COMMIT();

        const unsigned sAh_u = base_u + WBYTES + (unsigned)(buf * ABUF);
        const unsigned sAl_u = sAh_u + WBYTES;

        float acc[2][8][4];
        #pragma unroll
        for (int t = 0; t < 2; t++)
            #pragma unroll
            for (int n = 0; n < 8; n++)
                #pragma unroll
                for (int q = 0; q < 4; q++) acc[t][n][q] = 0.f;

        #pragma unroll 1
        for (int ks = 0; ks < 8; ks++) {
            unsigned kb = (unsigned)(ks * 32);
            unsigned ah[2][4], al[2][4], bw[4][4];
            LDMX4(ah[0], sAh_u + aoff0 + kb);
            LDMX4(ah[1], sAh_u + aoff0 + 16 * ROWB + kb);
            LDMX4(al[0], sAl_u + aoff0 + kb);
            LDMX4(al[1], sAl_u + aoff0 + 16 * ROWB + kb);
            #pragma unroll
            for (int p = 0; p < 4; p++)
                LDMX4(bw[p], sW_u + woff + p * 16 * ROWB + kb);
            #pragma unroll
            for (int t = 0; t < 2; t++)
                #pragma unroll
                for (int p = 0; p < 4; p++) {
                    MMA_F16(acc[t][2 * p],     ah[t][0], ah[t][1], ah[t][2], ah[t][3], bw[p][0], bw[p][2]);
                    MMA_F16(acc[t][2 * p + 1], ah[t][0], ah[t][1], ah[t][2], ah[t][3], bw[p][1], bw[p][3]);
                    MMA_F16(acc[t][2 * p],     al[t][0], al[t][1], al[t][2], al[t][3], bw[p][0], bw[p][2]);
                    MMA_F16(acc[t][2 * p + 1], al[t][0], al[t][1], al[t][2], al[t][3], bw[p][1], bw[p][3]);
                }
        }
        __syncthreads();

        float* sF = (float*)(sm + WBYTES + buf * ABUF);
        {
            int mr = lane >> 2;
            int nc = 2 * (lane & 3);
            #pragma unroll
            for (int t = 0; t < 2; t++) {
                int row = wm * 32 + t * 16 + mr;
                #pragma unroll
                for (int nt = 0; nt < 8; nt++) {
                    int col = wn * 64 + nt * 8 + nc;
                    sF[row * 132 + col]           = acc[t][nt][0];
                    sF[row * 132 + col + 1]       = acc[t][nt][1];
                    sF[(row + 8) * 132 + col]     = acc[t][nt][2];
                    sF[(row + 8) * 132 + col + 1] = acc[t][nt][3];
                }
            }
        }
        __syncthreads();

        if (MODE == 0) {
            int rl = tid >> 1, h = tid & 1;
            long gbase = (long)tile * 128;
            bool valid = (gbase + rl) < NEDGE;
            char* outb = (char*)g_a2split + (size_t)tile * 65536;
            uint4* dh = (uint4*)(outb + rl * 256 + h * 128);
            uint4* dl = (uint4*)(outb + 32768 + rl * 256 + h * 128);
            float* fr = sF + rl * 132 + h * 64;
            const float* bp = s_bias + h * 64;
            #pragma unroll
            for (int q = 0; q < 8; q++) {
                unsigned ph[4], pl[4];
                #pragma unroll
                for (int j = 0; j < 4; j++) {
                    int c = q * 8 + j * 2;
                    float v0 = fr[c]     + bp[c];
                    float v1 = fr[c + 1] + bp[c + 1];
                    v0 = (v0 >= 0.f) ? v0 : 0.01f * v0;
                    v1 = (v1 >= 0.f) ? v1 : 0.01f * v1;
                    if (!valid) { v0 = 0.f; v1 = 0.f; }
                    fr[c] = v0; fr[c + 1] = v1;
                    float h0 = __half2float(__float2half_rn(v0));
                    float h1 = __half2float(__float2half_rn(v1));
                    ph[j] = pack2h(h0, h1);
                    pl[j] = pack2h(v0 - h0, v1 - h1);
                }
                dh[q] = make_uint4(ph[0], ph[1], ph[2], ph[3]);
                dl[q] = make_uint4(pl[0], pl[1], pl[2], pl[3]);
            }
            __syncthreads();
            {
                int c = tid & 127, h2 = tid >> 7;
                float s0 = 0.f, s1 = 0.f;
                #pragma unroll 8
                for (int r = 0; r < 64; r++) {
                    float v = sF[(h2 * 64 + r) * 132 + c];
                    s0 += v; s1 += v * v;
                }
                atomicAdd(&g_sums[2][c], s0);
                atomicAdd(&g_sums[3][c], s1);
            }
        } else {
            int rt = tid >> 1, h = tid & 1;
            long grow = (long)tile * 128 + rt;
            if (grow < NEDGE) {
                int s_ = eidx[grow], d_ = eidx[NEDGE + grow];
                float coeff = cosf(1.5707963267948966f * ea[grow * 4 + 3]);
                const float4* xp = (const float4*)(g_xd + (size_t)s_ * 128) + h * 16;
                float* zp = g_z + (size_t)d_ * 128 + h * 64;
                const float* fr = sF + rt * 132 + h * 64;
                const float* bp = s_bias + h * 64;
                #pragma unroll
                for (int q = 0; q < 16; q++) {
                    float4 xv = xp[q];
                    float v0 = coeff * (fr[4 * q + 0] + bp[4 * q + 0]) * xv.x;
                    float v1 = coeff * (fr[4 * q + 1] + bp[4 * q + 1]) * xv.y;
                    float v2 = coeff * (fr[4 * q + 2] + bp[4 * q + 2]) * xv.z;
                    float v3 = coeff * (fr[4 * q + 3] + bp[4 * q + 3]) * xv.w;
                    asm volatile("red.global.add.v4.f32 [%0], {%1,%2,%3,%4};"
                                 :: "l"(zp + 4 * q), "f"(v0), "f"(v1), "f"(v2), "f"(v3) : "memory");
                }
            }
        }
        __syncthreads();
        CP_WAIT0();
        __syncthreads();
        buf ^= 1;
    }
}

// ---------------- launcher ----------------
extern "C" void kernel_launch(void* const* d_in, const int* in_sizes, int n_in,
                              void* d_out, int out_size) {
    const float* x    = (const float*)d_in[0];
    const float* ea   = (const float*)d_in[1];
    const int*   eidx = (const int*)  d_in[2];
    const float* Wb   = (const float*)d_in[3];
    const float* bb   = (const float*)d_in[4];
    const float* We1  = (const float*)d_in[5];
    const float* be1  = (const float*)d_in[6];
    const float* ge1  = (const float*)d_in[7];
    const float* bte1 = (const float*)d_in[8];
    const float* We2  = (const float*)d_in[9];
    const float* be2  = (const float*)d_in[10];
    const float* ge2  = (const float*)d_in[11];
    const float* bte2 = (const float*)d_in[12];
    const float* We3  = (const float*)d_in[13];
    const float* be3  = (const float*)d_in[14];
    const float* Wd   = (const float*)d_in[15];
    const float* bd   = (const float*)d_in[16];
    const float* v    = (const float*)d_in[17];
    const float* Wn1  = (const float*)d_in[18];
    const float* bn1  = (const float*)d_in[19];
    const float* gn   = (const float*)d_in[20];
    const float* btn  = (const float*)d_in[21];
    const float* Wn2  = (const float*)d_in[22];
    const float* bn2  = (const float*)d_in[23];
    float* outp = (float*)d_out;

    float* d_z;    cudaGetSymbolAddress((void**)&d_z, g_z);
    float* d_W2p;  cudaGetSymbolAddress((void**)&d_W2p, g_W2p);
    float* d_W3p;  cudaGetSymbolAddress((void**)&d_W3p, g_W3p);
    float* d_Wn2p; cudaGetSymbolAddress((void**)&d_Wn2p, g_Wn2p);
    char*  d_W2s;  cudaGetSymbolAddress((void**)&d_W2s, g_W2s);
    char*  d_W3s;  cudaGetSymbolAddress((void**)&d_W3s, g_W3s);
    char*  d_Wn1s; cudaGetSymbolAddress((void**)&d_Wn1s, g_Wn1s);
    char*  d_Wn2s; cudaGetSymbolAddress((void**)&d_Wn2s, g_Wn2s);
    char*  d_xsh;  cudaGetSymbolAddress((void**)&d_xsh, g_xs_hi);
    char*  d_xsl;  cudaGetSymbolAddress((void**)&d_xsl, g_xs_lo);
    char*  d_zsh;  cudaGetSymbolAddress((void**)&d_zsh, g_zs_hi);
    char*  d_zsl;  cudaGetSymbolAddress((void**)&d_zsl, g_zs_lo);

    cudaFuncSetAttribute(tc_gemm<0>, cudaFuncAttributeMaxDynamicSharedMemorySize, TCSM_E);
    cudaFuncSetAttribute(tc_gemm<1>, cudaFuncAttributeMaxDynamicSharedMemorySize, TCSM_E);
    cudaFuncSetAttribute(tc_node, cudaFuncAttributeMaxDynamicSharedMemorySize, TCSM_N);
    cudaFuncSetAttribute(tc_node2<0>, cudaFuncAttributeMaxDynamicSharedMemorySize, TCSM_N);
    cudaFuncSetAttribute(tc_node2<1>, cudaFuncAttributeMaxDynamicSharedMemorySize, TCSM_N);

    zero_stats<<<1, 768>>>();
    wbwe1_kernel<<<200, 128>>>(Wb, We1);
    cvec_kernel<<<1, 128>>>(bb, We1, be1);
    table_kernel<<<4 * GTAB, 128>>>();
    split_kernel<<<NTILEN, 256>>>(x, d_xsh, d_xsl);
    packnode_kernel<<<384, 128>>>(We1, Wd);
    pack_kernel<<<128, 128>>>(Wn1, d_Wn1s);

    tc_node<<<NTILEN, 256, TCSM_N>>>(bd, v);

    e1_fuse_kernel<<<NTILE, 128>>>(ea, eidx);
    fold_kernel<<<129, 128>>>(0, 1.0f / NEDGE, ge1, bte1, We2, be2);
    packh_kernel<<<128, 128>>>(d_W2p, d_W2s);

    tc_gemm<0><<<GRID_TC, 256, TCSM_E>>>(ea, eidx);
    fold_kernel<<<129, 128>>>(2, 1.0f / NEDGE, ge2, bte2, We3, be3);
    packh_kernel<<<128, 128>>>(d_W3p, d_W3s);

    tc_gemm<1><<<GRID_TC, 256, TCSM_E>>>(ea, eidx);

    split_kernel<<<NTILEN, 256>>>(d_z, d_zsh, d_zsl);
    tc_node2<0><<<NTILEN, 256, TCSM_N>>>(bn1, nullptr, nullptr);
    fold_kernel<<<129, 128>>>(4, 1.0f / NNODE, gn, btn, Wn2, bn2);
    pack_kernel<<<128, 128>>>(d_Wn2p, d_Wn2s);
    tc_node2<1><<<NTILEN, 256, TCSM_N>>>(nullptr, x, outp);
}

// round 15
// speedup vs baseline: 1.9200x; 1.0326x over previous
#include <cuda_runtime.h>
#include <cuda_bf16.h>
#include <cuda_fp16.h>

#define NNODE 50000
#define NNPAD 50048             // 391 * 128
#define NEDGE 300000
#define GTAB  1024
#define EPSBN 1e-5f
#define NTILE 2344              // ceil(NEDGE/128)
#define NTILEN 391              // ceil(NNODE/128)
#define ROWB  272               // padded smem row bytes (136 elems)
#define WBYTES 34816            // 128 * ROWB
#define ABUF   69632            // Ah+Al per buffer
#define TCSM_E (WBYTES + 2 * ABUF)   // 174080: W(single fp16) + 2 A buffers
#define TCSM_N (2 * WBYTES + 69632)  // 139264: A hi/lo + W/stage region
#define GRID_TC 148

// ---------------- scratch (device globals; no allocation) ----------------
__device__ uint4 g_a1split[(size_t)NTILE * 4096];  // per tile: 32KB fp16-hi | 32KB fp16-lo, [m][k] 256B rows
__device__ uint4 g_a2split[(size_t)NTILE * 4096];
__device__ uint4 g_W2s[2048];                      // 32KB: W^T [n][k] single fp16
__device__ uint4 g_W3s[2048];
__device__ uint4 g_Wn1s[2048];
__device__ uint4 g_Wn2s[2048];
__device__ uint4 g_xs_hi[(size_t)NNPAD * 16];      // x fp16-hi, [m][k] 256B rows
__device__ uint4 g_xs_lo[(size_t)NNPAD * 16];
__device__ uint4 g_zs_hi[(size_t)NNPAD * 16];
__device__ uint4 g_zs_lo[(size_t)NNPAD * 16];
__device__ uint4 g_ans_hi[(size_t)NNPAD * 16];
__device__ uint4 g_ans_lo[(size_t)NNPAD * 16];
__device__ uint4 g_Wns[6144];                      // 96KB: [384 n][128 k] single fp16
__device__ float g_xd[(size_t)NNODE * 128];
__device__ float g_z [(size_t)NNODE * 128];
__device__ float g_xtop[(size_t)NNODE * 128];
__device__ float g_xbot[(size_t)NNODE * 128];
__device__ float g_tab[4 * GTAB * 128];
__device__ __half g_tabh[4 * GTAB * 128];
__device__ float g_WbWe1[200 * 128];
__device__ float g_cvec[128];
__device__ float g_W2p[128 * 128];  __device__ float g_b2p[128];
__device__ float g_W3p[128 * 128];  __device__ float g_b3p[128];
__device__ float g_Wn2p[128 * 128]; __device__ float g_bn2p[128];
__device__ float g_sums[6][128];

// ---------------- helpers ----------------
__device__ __forceinline__ unsigned smem_u32(const void* p) {
    unsigned a;
    asm("{ .reg .u64 t; cvta.to.shared.u64 t, %1; cvt.u32.u64 %0, t; }" : "=r"(a) : "l"(p));
    return a;
}
#define CP_ASYNC16(dst, src)                                                   \
    asm volatile("cp.async.cg.shared.global [%0], [%1], 16;"                   \
                 :: "r"(dst), "l"(src) : "memory")
#define CP_COMMIT() asm volatile("cp.async.commit_group;" ::: "memory")
#define CP_WAIT0()  asm volatile("cp.async.wait_group 0;" ::: "memory")
#define LDMX4(r, addr)                                                         \
    asm volatile("ldmatrix.sync.aligned.m8n8.x4.shared.b16 {%0,%1,%2,%3}, [%4];" \
                 : "=r"((r)[0]), "=r"((r)[1]), "=r"((r)[2]), "=r"((r)[3])      \
                 : "r"(addr))
#define MMA_F16(d, a0, a1, a2, a3, b0, b1)                                     \
    asm volatile("mma.sync.aligned.m16n8k16.row.col.f32.f16.f16.f32 "          \
                 "{%0,%1,%2,%3}, {%4,%5,%6,%7}, {%8,%9}, {%0,%1,%2,%3};"       \
                 : "+f"((d)[0]), "+f"((d)[1]), "+f"((d)[2]), "+f"((d)[3])      \
                 : "r"(a0), "r"(a1), "r"(a2), "r"(a3), "r"(b0), "r"(b1))
static __device__ __forceinline__ unsigned pack2h(float a, float b) {
    return ((unsigned)__half_as_ushort(__float2half_rn(b)) << 16)
         |  (unsigned)__half_as_ushort(__float2half_rn(a));
}

// ---------------- tiny prep kernels ----------------
__global__ void zero_stats() { ((float*)g_sums)[threadIdx.x] = 0.0f; }

__global__ void wbwe1_kernel(const float* __restrict__ Wb, const float* __restrict__ We1) {
    int r = blockIdx.x, n = threadIdx.x;
    float acc = 0.f;
    #pragma unroll 8
    for (int k = 0; k < 128; k++) acc += Wb[r * 128 + k] * We1[(128 + k) * 128 + n];
    g_WbWe1[r * 128 + n] = acc;
}

__global__ void cvec_kernel(const float* __restrict__ bb, const float* __restrict__ We1,
                            const float* __restrict__ be1) {
    int n = threadIdx.x;
    float acc = be1[n];
    #pragma unroll 8
    for (int k = 0; k < 128; k++) acc += bb[k] * We1[(128 + k) * 128 + n];
    g_cvec[n] = acc;
}

__global__ void table_kernel() {
    __shared__ float gs[64];
    int b = blockIdx.x;
    int c = b >> 10;
    int gi = b & (GTAB - 1);
    float u = (float)gi * (1.0f / (GTAB - 1));
    int tid = threadIdx.x;
    if (tid < 50) {
        float d = u - (float)tid * (1.0f / 49.0f);
        gs[tid] = __expf(-d * d * 1250.0f);
    }
    __syncthreads();
    float acc = 0.f;
    #pragma unroll
    for (int j = 0; j < 50; j++) acc += gs[j] * g_WbWe1[(c * 50 + j) * 128 + tid];
    g_tab[b * 128 + tid] = acc;
    g_tabh[b * 128 + tid] = __float2half(acc);
}

__global__ void fold_kernel(int sidx, float invM,
                            const float* __restrict__ gamma, const float* __restrict__ beta,
                            const float* __restrict__ Wsrc, const float* __restrict__ be) {
    float* Wdst = (sidx == 0) ? g_W2p : (sidx == 2) ? g_W3p : g_Wn2p;
    float* bdst = (sidx == 0) ? g_b2p : (sidx == 2) ? g_b3p : g_bn2p;
    int n = threadIdx.x;
    if (blockIdx.x < 128) {
        int k = blockIdx.x;
        float m = g_sums[sidx][k] * invM;
        float var = g_sums[sidx + 1][k] * invM - m * m;
        float s = gamma[k] * rsqrtf(var + EPSBN);
        Wdst[k * 128 + n] = s * Wsrc[k * 128 + n];
    } else {
        float acc = be[n];
        for (int k = 0; k < 128; k++) {
            float m = g_sums[sidx][k] * invM;
            float var = g_sums[sidx + 1][k] * invM - m * m;
            float s = gamma[k] * rsqrtf(var + EPSBN);
            acc += (beta[k] - m * s) * Wsrc[k * 128 + n];
        }
        bdst[n] = acc;
    }
}

// Pack W^T into single fp16, 32KB
__global__ void packh_kernel(const float* __restrict__ Wp, char* __restrict__ Ws) {
    int n = blockIdx.x, k = threadIdx.x;
    float v = Wp[k * 128 + n];
    *(unsigned short*)(Ws + n * 256 + 2 * k) = __half_as_ushort(__float2half_rn(v));
}

// Pack node weights: n<128 -> We1_top^T, n<256 -> We1_bot^T, else Wd^T (single fp16)
__global__ void packnode_kernel(const float* __restrict__ We1, const float* __restrict__ Wd) {
    int n = blockIdx.x, k = threadIdx.x;
    float v;
    if (n < 128)       v = We1[k * 128 + n];
    else if (n < 256)  v = We1[(256 + k) * 128 + (n - 128)];
    else               v = Wd[k * 128 + (n - 256)];
    *(unsigned short*)((char*)g_Wns + n * 256 + 2 * k) = __half_as_ushort(__float2half_rn(v));
}

// Split fp32 node array into fp16 hi/lo padded arrays
__global__ __launch_bounds__(256)
void split_kernel(const float* __restrict__ src, char* __restrict__ hb, char* __restrict__ lb) {
    int base = blockIdx.x * 16384;
    #pragma unroll
    for (int i = 0; i < 64; i++) {
        int idx = base + threadIdx.x + i * 256;
        float v = (idx < NNODE * 128) ? __ldg(src + idx) : 0.f;
        __half hh = __float2half_rn(v);
        *(unsigned short*)(hb + 2 * (size_t)idx) = __half_as_ushort(hh);
        *(unsigned short*)(lb + 2 * (size_t)idx) = __half_as_ushort(__float2half_rn(v - __half2float(hh)));
    }
}

// ---------------- fused E1 -> fp16 hi/lo tiles (half table, zero smem) ----------------
__global__ __launch_bounds__(128)
void e1_fuse_kernel(const float* __restrict__ ea, const int* __restrict__ eidx) {
    int t = threadIdx.x;
    int e0 = blockIdx.x * 128;
    char* tb = (char*)g_a1split + (size_t)blockIdx.x * 65536;
    float cv = g_cvec[t];
    float csum = 0.f, csq = 0.f;
    int eend = e0 + 128;
    if (eend > NEDGE) eend = NEDGE;
    #pragma unroll 4
    for (int e = e0; e < eend; e++) {
        int s = __ldg(eidx + e);
        int d = __ldg(eidx + NEDGE + e);
        float4 eav = __ldg((const float4*)ea + e);
        float val = g_xtop[(size_t)s * 128 + t] + g_xbot[(size_t)d * 128 + t] + cv;
        float fa[4] = {eav.x, eav.y, eav.z, eav.w};
        #pragma unroll
        for (int c = 0; c < 4; c++) {
            float p = fa[c] * (float)(GTAB - 1);
            int i0 = (int)p;
            if (i0 < 0) i0 = 0;
            if (i0 > GTAB - 2) i0 = GTAB - 2;
            float w = p - (float)i0;
            const __half* t0 = g_tabh + ((size_t)(c * GTAB + i0) * 128 + t);
            float u = __half2float(t0[0]), v2 = __half2float(t0[128]);
            val += u + w * (v2 - u);
        }
        val = (val >= 0.f) ? val : 0.01f * val;
        csum += val; csq += val * val;
        __half hh = __float2half_rn(val);
        int off = (e - e0) * 256 + 2 * t;
        *(unsigned short*)(tb + off)         = __half_as_ushort(hh);
        *(unsigned short*)(tb + 32768 + off) = __half_as_ushort(__float2half_rn(val - __half2float(hh)));
    }
    for (int e = eend; e < e0 + 128; e++) {
        int off = (e - e0) * 256 + 2 * t;
        *(unsigned short*)(tb + off) = 0;
        *(unsigned short*)(tb + 32768 + off) = 0;
    }
    atomicAdd(&g_sums[0][t], csum);
    atomicAdd(&g_sums[1][t], csq);
}

// ---------------- tc node GEMM: [xtop | xbot | xd,z] = x @ Wns (fp16 2-product, 3 chunks) ----------------
__global__ __launch_bounds__(256)
void tc_node(const float* __restrict__ bd, const float* __restrict__ vparam) {
    extern __shared__ char sm[];
    __shared__ float s_bd[128], s_v[128];
    const int tid = threadIdx.x;
    const int lane = tid & 31, wid = tid >> 5;
    const int wm = wid & 3, wn = wid >> 2;

    if (tid < 128) { s_bd[tid] = bd[tid]; s_v[tid] = vparam[tid]; }

    const unsigned base_u = smem_u32(sm);
    const unsigned sAh_u = base_u;
    const unsigned sAl_u = base_u + WBYTES;
    const unsigned sW_u  = base_u + 2 * WBYTES;

    const int gbase = blockIdx.x * 128;
    {
        const uint4* hsrc = g_xs_hi + (size_t)gbase * 16;
        const uint4* lsrc = g_xs_lo + (size_t)gbase * 16;
        #pragma unroll
        for (int i = tid; i < 2048; i += 256) {
            int row = i >> 4, ch = i & 15;
            *(uint4*)(sm + row * ROWB + ch * 16)          = hsrc[i];
            *(uint4*)(sm + WBYTES + row * ROWB + ch * 16) = lsrc[i];
        }
    }

    const int laneRow = lane & 15;
    const unsigned laneK = (unsigned)((lane >> 4) << 4);
    const unsigned aoff = (unsigned)((wm * 32 + laneRow) * ROWB) + laneK;
    const unsigned woff = (unsigned)((wn * 64 + laneRow) * ROWB) + laneK;

    #pragma unroll 1
    for (int chunk = 0; chunk < 3; chunk++) {
        {
            const uint4* whs = g_Wns + (size_t)chunk * 2048;
            #pragma unroll
            for (int i = tid; i < 2048; i += 256) {
                int row = i >> 4, ch = i & 15;
                *(uint4*)(sm + 2 * WBYTES + row * ROWB + ch * 16) = whs[i];
            }
        }
        __syncthreads();

        float acc[2][8][4];
        #pragma unroll
        for (int t = 0; t < 2; t++)
            #pragma unroll
            for (int n = 0; n < 8; n++)
                #pragma unroll
                for (int q = 0; q < 4; q++) acc[t][n][q] = 0.f;

        #pragma unroll 1
        for (int ks = 0; ks < 8; ks++) {
            unsigned kb = (unsigned)(ks * 32);
            unsigned ah[2][4], al[2][4], bw[4][4];
            LDMX4(ah[0], sAh_u + aoff + kb);
            LDMX4(ah[1], sAh_u + aoff + 16 * ROWB + kb);
            LDMX4(al[0], sAl_u + aoff + kb);
            LDMX4(al[1], sAl_u + aoff + 16 * ROWB + kb);
            #pragma unroll
            for (int p = 0; p < 4; p++)
                LDMX4(bw[p], sW_u + woff + p * 16 * ROWB + kb);
            #pragma unroll
            for (int t = 0; t < 2; t++)
                #pragma unroll
                for (int p = 0; p < 4; p++) {
                    MMA_F16(acc[t][2 * p],     ah[t][0], ah[t][1], ah[t][2], ah[t][3], bw[p][0], bw[p][2]);
                    MMA_F16(acc[t][2 * p + 1], ah[t][0], ah[t][1], ah[t][2], ah[t][3], bw[p][1], bw[p][3]);
                    MMA_F16(acc[t][2 * p],     al[t][0], al[t][1], al[t][2], al[t][3], bw[p][0], bw[p][2]);
                    MMA_F16(acc[t][2 * p + 1], al[t][0], al[t][1], al[t][2], al[t][3], bw[p][1], bw[p][3]);
                }
        }
        __syncthreads();

        float* sF = (float*)(sm + 2 * WBYTES);
        {
            int mr = lane >> 2;
            int nc = 2 * (lane & 3);
            #pragma unroll
            for (int t = 0; t < 2; t++) {
                int row = wm * 32 + t * 16 + mr;
                #pragma unroll
                for (int nt = 0; nt < 8; nt++) {
                    int col = wn * 64 + nt * 8 + nc;
                    sF[row * 132 + col]           = acc[t][nt][0];
                    sF[row * 132 + col + 1]       = acc[t][nt][1];
                    sF[(row + 8) * 132 + col]     = acc[t][nt][2];
                    sF[(row + 8) * 132 + col + 1] = acc[t][nt][3];
                }
            }
        }
        __syncthreads();

        {
            int rl = tid >> 1, h = tid & 1;
            int grow = gbase + rl;
            if (grow < NNODE) {
                const float* fr = sF + rl * 132 + h * 64;
                if (chunk == 0) {
                    float* dp = g_xtop + (size_t)grow * 128 + h * 64;
                    #pragma unroll
                    for (int q = 0; q < 16; q++)
                        ((float4*)dp)[q] = make_float4(fr[4*q], fr[4*q+1], fr[4*q+2], fr[4*q+3]);
                } else if (chunk == 1) {
                    float* dp = g_xbot + (size_t)grow * 128 + h * 64;
                    #pragma unroll
                    for (int q = 0; q < 16; q++)
                        ((float4*)dp)[q] = make_float4(fr[4*q], fr[4*q+1], fr[4*q+2], fr[4*q+3]);
                } else {
                    float* dx = g_xd + (size_t)grow * 128 + h * 64;
                    float* dz = g_z  + (size_t)grow * 128 + h * 64;
                    const float* bp = s_bd + h * 64;
                    const float* vp = s_v + h * 64;
                    #pragma unroll
                    for (int q = 0; q < 16; q++) {
                        float x0 = fr[4*q]   + bp[4*q];
                        float x1 = fr[4*q+1] + bp[4*q+1];
                        float x2 = fr[4*q+2] + bp[4*q+2];
                        float x3 = fr[4*q+3] + bp[4*q+3];
                        ((float4*)dx)[q] = make_float4(x0, x1, x2, x3);
                        ((float4*)dz)[q] = make_float4(vp[4*q]*x0, vp[4*q+1]*x1, vp[4*q+2]*x2, vp[4*q+3]*x3);
                    }
                }
            }
        }
        __syncthreads();
    }
}

// ---------------- tc node GEMM 2: MODE 0 = N1, MODE 1 = OUT (fp16 2-product) ----------------
template <int MODE>
__global__ __launch_bounds__(256)
void tc_node2(const float* __restrict__ biasExt, const float* __restrict__ x,
              float* __restrict__ outp) {
    extern __shared__ char sm[];
    __shared__ float s_bias[128];
    const int tid = threadIdx.x;
    const int lane = tid & 31, wid = tid >> 5;
    const int wm = wid & 3, wn = wid >> 2;

    if (tid < 128) s_bias[tid] = (MODE == 0) ? biasExt[tid] : g_bn2p[tid];

    const unsigned base_u = smem_u32(sm);
    const unsigned sAh_u = base_u;
    const unsigned sAl_u = base_u + WBYTES;
    const unsigned sW_u  = base_u + 2 * WBYTES;

    const int gbase = blockIdx.x * 128;
    {
        const uint4* hsrc = (MODE == 0 ? g_zs_hi : g_ans_hi) + (size_t)gbase * 16;
        const uint4* lsrc = (MODE == 0 ? g_zs_lo : g_ans_lo) + (size_t)gbase * 16;
        const uint4* whs  = (MODE == 0 ? g_Wn1s : g_Wn2s);
        #pragma unroll
        for (int i = tid; i < 2048; i += 256) {
            int row = i >> 4, ch = i & 15;
            *(uint4*)(sm + row * ROWB + ch * 16)              = hsrc[i];
            *(uint4*)(sm + WBYTES + row * ROWB + ch * 16)     = lsrc[i];
            *(uint4*)(sm + 2 * WBYTES + row * ROWB + ch * 16) = whs[i];
        }
    }
    __syncthreads();

    const int laneRow = lane & 15;
    const unsigned laneK = (unsigned)((lane >> 4) << 4);
    const unsigned aoff = (unsigned)((wm * 32 + laneRow) * ROWB) + laneK;
    const unsigned woff = (unsigned)((wn * 64 + laneRow) * ROWB) + laneK;

    float acc[2][8][4];
    #pragma unroll
    for (int t = 0; t < 2; t++)
        #pragma unroll
        for (int n = 0; n < 8; n++)
            #pragma unroll
            for (int q = 0; q < 4; q++) acc[t][n][q] = 0.f;

    #pragma unroll 1
    for (int ks = 0; ks < 8; ks++) {
        unsigned kb = (unsigned)(ks * 32);
        unsigned ah[2][4], al[2][4], bw[4][4];
        LDMX4(ah[0], sAh_u + aoff + kb);
        LDMX4(ah[1], sAh_u + aoff + 16 * ROWB + kb);
        LDMX4(al[0], sAl_u + aoff + kb);
        LDMX4(al[1], sAl_u + aoff + 16 * ROWB + kb);
        #pragma unroll
        for (int p = 0; p < 4; p++)
            LDMX4(bw[p], sW_u + woff + p * 16 * ROWB + kb);
        #pragma unroll
        for (int t = 0; t < 2; t++)
            #pragma unroll
            for (int p = 0; p < 4; p++) {
                MMA_F16(acc[t][2 * p],     ah[t][0], ah[t][1], ah[t][2], ah[t][3], bw[p][0], bw[p][2]);
                MMA_F16(acc[t][2 * p + 1], ah[t][0], ah[t][1], ah[t][2], ah[t][3], bw[p][1], bw[p][3]);
                MMA_F16(acc[t][2 * p],     al[t][0], al[t][1], al[t][2], al[t][3], bw[p][0], bw[p][2]);
                MMA_F16(acc[t][2 * p + 1], al[t][0], al[t][1], al[t][2], al[t][3], bw[p][1], bw[p][3]);
            }
    }
    __syncthreads();

    float* sF = (float*)(sm + 2 * WBYTES);
    {
        int mr = lane >> 2;
        int nc = 2 * (lane & 3);
        #pragma unroll
        for (int t = 0; t < 2; t++) {
            int row = wm * 32 + t * 16 + mr;
            #pragma unroll
            for (int nt = 0; nt < 8; nt++) {
                int col = wn * 64 + nt * 8 + nc;
                sF[row * 132 + col]           = acc[t][nt][0];
                sF[row * 132 + col + 1]       = acc[t][nt][1];
                sF[(row + 8) * 132 + col]     = acc[t][nt][2];
                sF[(row + 8) * 132 + col + 1] = acc[t][nt][3];
            }
        }
    }
    __syncthreads();

    if (MODE == 0) {
        int rl = tid >> 1, h = tid & 1;
        int grow = gbase + rl;
        bool valid = grow < NNODE;
        float* fr = sF + rl * 132 + h * 64;
        const float* bp = s_bias + h * 64;
        uint4* dh = (uint4*)((char*)g_ans_hi + (size_t)grow * 256 + h * 128);
        uint4* dl = (uint4*)((char*)g_ans_lo + (size_t)grow * 256 + h * 128);
        #pragma unroll
        for (int q = 0; q < 8; q++) {
            unsigned ph[4], pl[4];
            #pragma unroll
            for (int j = 0; j < 4; j++) {
                int c = q * 8 + j * 2;
                float v0 = fr[c]     + bp[c];
                float v1 = fr[c + 1] + bp[c + 1];
                v0 = (v0 >= 0.f) ? v0 : 0.01f * v0;
                v1 = (v1 >= 0.f) ? v1 : 0.01f * v1;
                if (!valid) { v0 = 0.f; v1 = 0.f; }
                fr[c] = v0; fr[c + 1] = v1;
                float h0 = __half2float(__float2half_rn(v0));
                float h1 = __half2float(__float2half_rn(v1));
                ph[j] = pack2h(h0, h1);
                pl[j] = pack2h(v0 - h0, v1 - h1);
            }
            dh[q] = make_uint4(ph[0], ph[1], ph[2], ph[3]);
            dl[q] = make_uint4(pl[0], pl[1], pl[2], pl[3]);
        }
        __syncthreads();
        {
            int c = tid & 127, h2 = tid >> 7;
            float s0 = 0.f, s1 = 0.f;
            #pragma unroll 8
            for (int r = 0; r < 64; r++) {
                float v = sF[(h2 * 64 + r) * 132 + c];
                s0 += v; s1 += v * v;
            }
            atomicAdd(&g_sums[4][c], s0);
            atomicAdd(&g_sums[5][c], s1);
        }
    } else {
        int rl = tid >> 1, h = tid & 1;
        int grow = gbase + rl;
        if (grow < NNODE) {
            const float* fr = sF + rl * 132 + h * 64;
            const float* bp = s_bias + h * 64;
            const float4* xp = (const float4*)(x + (size_t)grow * 128 + h * 64);
            float* dp = outp + (size_t)grow * 128 + h * 64;
            #pragma unroll
            for (int q = 0; q < 16; q++) {
                float4 xv = xp[q];
                ((float4*)dp)[q] = make_float4(fr[4*q]   + bp[4*q]   + xv.x,
                                               fr[4*q+1] + bp[4*q+1] + xv.y,
                                               fr[4*q+2] + bp[4*q+2] + xv.z,
                                               fr[4*q+3] + bp[4*q+3] + xv.w);
            }
        }
    }
}

// ---------------- persistent fp16 2-product edge GEMMs (cp.async double buffer) ----------------
// MODE 0 = E2, MODE 1 = E3
template <int MODE>
__global__ __launch_bounds__(256)
void tc_gemm(const float* __restrict__ ea, const int* __restrict__ eidx) {
    extern __shared__ char sm[];
    __shared__ float s_bias[128];
    const int tid = threadIdx.x;
    const int lane = tid & 31, wid = tid >> 5;
    const int wm = wid & 3, wn = wid >> 2;

    const unsigned base_u = smem_u32(sm);
    const unsigned sW_u = base_u;

    if (tid < 128) s_bias[tid] = (MODE == 0) ? g_b2p[tid] : g_b3p[tid];

    const uint4* Abase = (MODE == 0 ? g_a1split : g_a2split);
    const uint4* Wsrc  = (MODE == 0 ? g_W2s : g_W3s);

    int tile = blockIdx.x;
    {
        const uint4* src = Abase + (size_t)tile * 4096;
        unsigned dst = base_u + WBYTES;
        #pragma unroll
        for (int i = tid; i < 2048; i += 256) {
            int row = i >> 4, ch = i & 15;
            unsigned d = dst + (unsigned)(row * ROWB + ch * 16);
            CP_ASYNC16(d, src + i);
            CP_ASYNC16(d + WBYTES, src + i + 2048);
        }
        CP_COMMIT();
        #pragma unroll
        for (int i = tid; i < 2048; i += 256) {
            int row = i >> 4, ch = i & 15;
            *(uint4*)(sm + row * ROWB + ch * 16) = Wsrc[i];
        }
        CP_WAIT0();
    }
    __syncthreads();

    const int laneRow = lane & 15;
    const unsigned laneK = (unsigned)((lane >> 4) << 4);
    const unsigned aoff0 = (unsigned)((wm * 32 + laneRow) * ROWB) + laneK;
    const unsigned woff  = (unsigned)((wn * 64 + laneRow) * ROWB) + laneK;

    int buf = 0;
    for (; tile < NTILE; tile += GRID_TC) {
        int nxt = tile + GRID_TC;
        if (nxt < NTILE) {
            const uint4* src = Abase + (size_t)nxt * 4096;
            unsigned dst = base_u + WBYTES + (unsigned)((buf ^ 1) * ABUF);
            #pragma unroll
            for (int i = tid; i < 2048; i += 256) {
                int row = i >> 4, ch = i & 15;
                unsigned d = dst + (unsigned)(row * ROWB + ch * 16);
                CP_ASYNC16(d, src + i);
                CP_ASYNC16(d + WBYTES, src + i + 2048);
            }
        }
        CP_COMMIT();

        const unsigned sAh_u = base_u + WBYTES + (unsigned)(buf * ABUF);
        const unsigned sAl_u = sAh_u + WBYTES;

        float acc[2][8][4];
        #pragma unroll
        for (int t = 0; t < 2; t++)
            #pragma unroll
            for (int n = 0; n < 8; n++)
                #pragma unroll
                for (int q = 0; q < 4; q++) acc[t][n][q] = 0.f;

        #pragma unroll 1
        for (int ks = 0; ks < 8; ks++) {
            unsigned kb = (unsigned)(ks * 32);
            unsigned ah[2][4], al[2][4], bw[4][4];
            LDMX4(ah[0], sAh_u + aoff0 + kb);
            LDMX4(ah[1], sAh_u + aoff0 + 16 * ROWB + kb);
            LDMX4(al[0], sAl_u + aoff0 + kb);
            LDMX4(al[1], sAl_u + aoff0 + 16 * ROWB + kb);
            #pragma unroll
            for (int p = 0; p < 4; p++)
                LDMX4(bw[p], sW_u + woff + p * 16 * ROWB + kb);
            #pragma unroll
            for (int t = 0; t < 2; t++)
                #pragma unroll
                for (int p = 0; p < 4; p++) {
                    MMA_F16(acc[t][2 * p],     ah[t][0], ah[t][1], ah[t][2], ah[t][3], bw[p][0], bw[p][2]);
                    MMA_F16(acc[t][2 * p + 1], ah[t][0], ah[t][1], ah[t][2], ah[t][3], bw[p][1], bw[p][3]);
                    MMA_F16(acc[t][2 * p],     al[t][0], al[t][1], al[t][2], al[t][3], bw[p][0], bw[p][2]);
                    MMA_F16(acc[t][2 * p + 1], al[t][0], al[t][1], al[t][2], al[t][3], bw[p][1], bw[p][3]);
                }
        }
        __syncthreads();

        float* sF = (float*)(sm + WBYTES + buf * ABUF);
        {
            int mr = lane >> 2;
            int nc = 2 * (lane & 3);
            #pragma unroll
            for (int t = 0; t < 2; t++) {
                int row = wm * 32 + t * 16 + mr;
                #pragma unroll
                for (int nt = 0; nt < 8; nt++) {
                    int col = wn * 64 + nt * 8 + nc;
                    sF[row * 132 + col]           = acc[t][nt][0];
                    sF[row * 132 + col + 1]       = acc[t][nt][1];
                    sF[(row + 8) * 132 + col]     = acc[t][nt][2];
                    sF[(row + 8) * 132 + col + 1] = acc[t][nt][3];
                }
            }
        }
        __syncthreads();

        if (MODE == 0) {
            int rl = tid >> 1, h = tid & 1;
            long gbase = (long)tile * 128;
            bool valid = (gbase + rl) < NEDGE;
            char* outb = (char*)g_a2split + (size_t)tile * 65536;
            uint4* dh = (uint4*)(outb + rl * 256 + h * 128);
            uint4* dl = (uint4*)(outb + 32768 + rl * 256 + h * 128);
            float* fr = sF + rl * 132 + h * 64;
            const float* bp = s_bias + h * 64;
            #pragma unroll
            for (int q = 0; q < 8; q++) {
                unsigned ph[4], pl[4];
                #pragma unroll
                for (int j = 0; j < 4; j++) {
                    int c = q * 8 + j * 2;
                    float v0 = fr[c]     + bp[c];
                    float v1 = fr[c + 1] + bp[c + 1];
                    v0 = (v0 >= 0.f) ? v0 : 0.01f * v0;
                    v1 = (v1 >= 0.f) ? v1 : 0.01f * v1;
                    if (!valid) { v0 = 0.f; v1 = 0.f; }
                    fr[c] = v0; fr[c + 1] = v1;
                    float h0 = __half2float(__float2half_rn(v0));
                    float h1 = __half2float(__float2half_rn(v1));
                    ph[j] = pack2h(h0, h1);
                    pl[j] = pack2h(v0 - h0, v1 - h1);
                }
                dh[q] = make_uint4(ph[0], ph[1], ph[2], ph[3]);
                dl[q] = make_uint4(pl[0], pl[1], pl[2], pl[3]);
            }
            __syncthreads();
            {
                int c = tid & 127, h2 = tid >> 7;
                float s0 = 0.f, s1 = 0.f;
                #pragma unroll 8
                for (int r = 0; r < 64; r++) {
                    float v = sF[(h2 * 64 + r) * 132 + c];
                    s0 += v; s1 += v * v;
                }
                atomicAdd(&g_sums[2][c], s0);
                atomicAdd(&g_sums[3][c], s1);
            }
        } else {
            int rt = tid >> 1, h = tid & 1;
            long grow = (long)tile * 128 + rt;
            if (grow < NEDGE) {
                int s_ = eidx[grow], d_ = eidx[NEDGE + grow];
                float coeff = cosf(1.5707963267948966f * ea[grow * 4 + 3]);
                const float4* xp = (const float4*)(g_xd + (size_t)s_ * 128) + h * 16;
                float* zp = g_z + (size_t)d_ * 128 + h * 64;
                const float* fr = sF + rt * 132 + h * 64;
                const float* bp = s_bias + h * 64;
                #pragma unroll
                for (int q = 0; q < 16; q++) {
                    float4 xv = xp[q];
                    float v0 = coeff * (fr[4 * q + 0] + bp[4 * q + 0]) * xv.x;
                    float v1 = coeff * (fr[4 * q + 1] + bp[4 * q + 1]) * xv.y;
                    float v2 = coeff * (fr[4 * q + 2] + bp[4 * q + 2]) * xv.z;
                    float v3 = coeff * (fr[4 * q + 3] + bp[4 * q + 3]) * xv.w;
                    asm volatile("red.global.add.v4.f32 [%0], {%1,%2,%3,%4};"
                                 :: "l"(zp + 4 * q), "f"(v0), "f"(v1), "f"(v2), "f"(v3) : "memory");
                }
            }
        }
        __syncthreads();
        CP_WAIT0();
        __syncthreads();
        buf ^= 1;
    }
}

// ---------------- launcher ----------------
extern "C" void kernel_launch(void* const* d_in, const int* in_sizes, int n_in,
                              void* d_out, int out_size) {
    const float* x    = (const float*)d_in[0];
    const float* ea   = (const float*)d_in[1];
    const int*   eidx = (const int*)  d_in[2];
    const float* Wb   = (const float*)d_in[3];
    const float* bb   = (const float*)d_in[4];
    const float* We1  = (const float*)d_in[5];
    const float* be1  = (const float*)d_in[6];
    const float* ge1  = (const float*)d_in[7];
    const float* bte1 = (const float*)d_in[8];
    const float* We2  = (const float*)d_in[9];
    const float* be2  = (const float*)d_in[10];
    const float* ge2  = (const float*)d_in[11];
    const float* bte2 = (const float*)d_in[12];
    const float* We3  = (const float*)d_in[13];
    const float* be3  = (const float*)d_in[14];
    const float* Wd   = (const float*)d_in[15];
    const float* bd   = (const float*)d_in[16];
    const float* v    = (const float*)d_in[17];
    const float* Wn1  = (const float*)d_in[18];
    const float* bn1  = (const float*)d_in[19];
    const float* gn   = (const float*)d_in[20];
    const float* btn  = (const float*)d_in[21];
    const float* Wn2  = (const float*)d_in[22];
    const float* bn2  = (const float*)d_in[23];
    float* outp = (float*)d_out;

    float* d_z;    cudaGetSymbolAddress((void**)&d_z, g_z);
    float* d_W2p;  cudaGetSymbolAddress((void**)&d_W2p, g_W2p);
    float* d_W3p;  cudaGetSymbolAddress((void**)&d_W3p, g_W3p);
    float* d_Wn2p; cudaGetSymbolAddress((void**)&d_Wn2p, g_Wn2p);
    char*  d_W2s;  cudaGetSymbolAddress((void**)&d_W2s, g_W2s);
    char*  d_W3s;  cudaGetSymbolAddress((void**)&d_W3s, g_W3s);
    char*  d_Wn1s; cudaGetSymbolAddress((void**)&d_Wn1s, g_Wn1s);
    char*  d_Wn2s; cudaGetSymbolAddress((void**)&d_Wn2s, g_Wn2s);
    char*  d_xsh;  cudaGetSymbolAddress((void**)&d_xsh, g_xs_hi);
    char*  d_xsl;  cudaGetSymbolAddress((void**)&d_xsl, g_xs_lo);
    char*  d_zsh;  cudaGetSymbolAddress((void**)&d_zsh, g_zs_hi);
    char*  d_zsl;  cudaGetSymbolAddress((void**)&d_zsl, g_zs_lo);

    cudaFuncSetAttribute(tc_gemm<0>, cudaFuncAttributeMaxDynamicSharedMemorySize, TCSM_E);
    cudaFuncSetAttribute(tc_gemm<1>, cudaFuncAttributeMaxDynamicSharedMemorySize, TCSM_E);
    cudaFuncSetAttribute(tc_node, cudaFuncAttributeMaxDynamicSharedMemorySize, TCSM_N);
    cudaFuncSetAttribute(tc_node2<0>, cudaFuncAttributeMaxDynamicSharedMemorySize, TCSM_N);
    cudaFuncSetAttribute(tc_node2<1>, cudaFuncAttributeMaxDynamicSharedMemorySize, TCSM_N);

    zero_stats<<<1, 768>>>();
    wbwe1_kernel<<<200, 128>>>(Wb, We1);
    cvec_kernel<<<1, 128>>>(bb, We1, be1);
    table_kernel<<<4 * GTAB, 128>>>();
    split_kernel<<<NTILEN, 256>>>(x, d_xsh, d_xsl);
    packnode_kernel<<<384, 128>>>(We1, Wd);
    packh_kernel<<<128, 128>>>(Wn1, d_Wn1s);

    tc_node<<<NTILEN, 256, TCSM_N>>>(bd, v);

    e1_fuse_kernel<<<NTILE, 128>>>(ea, eidx);
    fold_kernel<<<129, 128>>>(0, 1.0f / NEDGE, ge1, bte1, We2, be2);
    packh_kernel<<<128, 128>>>(d_W2p, d_W2s);

    tc_gemm<0><<<GRID_TC, 256, TCSM_E>>>(ea, eidx);
    fold_kernel<<<129, 128>>>(2, 1.0f / NEDGE, ge2, bte2, We3, be3);
    packh_kernel<<<128, 128>>>(d_W3p, d_W3s);

    tc_gemm<1><<<GRID_TC, 256, TCSM_E>>>(ea, eidx);

    split_kernel<<<NTILEN, 256>>>(d_z, d_zsh, d_zsl);
    tc_node2<0><<<NTILEN, 256, TCSM_N>>>(bn1, nullptr, nullptr);
    fold_kernel<<<129, 128>>>(4, 1.0f / NNODE, gn, btn, Wn2, bn2);
    packh_kernel<<<128, 128>>>(d_Wn2p, d_Wn2s);
    tc_node2<1><<<NTILEN, 256, TCSM_N>>>(nullptr, x, outp);
}

// round 16
// speedup vs baseline: 2.1828x; 1.1369x over previous
#include <cuda_runtime.h>
#include <cuda_bf16.h>
#include <cuda_fp16.h>

#define NNODE 50000
#define NNPAD 50048             // 391 * 128
#define NEDGE 300000
#define GTAB  1024
#define EPSBN 1e-5f
#define NTILE 2344              // ceil(NEDGE/128)
#define NTILEN 391              // ceil(NNODE/128)
#define ROWB  272               // padded smem row bytes (136 elems)
#define WBYTES 34816            // 128 * ROWB
#define ABUF   69632            // buffer region (A fp16 single uses first half; fp32 stage uses all)
#define TCSM_E (WBYTES + 2 * ABUF)   // 174080
#define TCSM_N (2 * WBYTES + 69632)  // 139264: A hi/lo + W/stage region
#define GRID_TC 148

// ---------------- scratch (device globals; no allocation) ----------------
__device__ uint4 g_a1split[(size_t)NTILE * 2048];  // per tile: 32KB single fp16, [m][k] 256B rows
__device__ uint4 g_a2split[(size_t)NTILE * 2048];
__device__ uint4 g_W2s[2048];                      // 32KB: W^T [n][k] single fp16
__device__ uint4 g_W3s[2048];
__device__ uint4 g_Wn1s[2048];
__device__ uint4 g_Wn2s[2048];
__device__ uint4 g_xs_hi[(size_t)NNPAD * 16];      // x fp16-hi, [m][k] 256B rows
__device__ uint4 g_xs_lo[(size_t)NNPAD * 16];
__device__ uint4 g_zs_hi[(size_t)NNPAD * 16];
__device__ uint4 g_zs_lo[(size_t)NNPAD * 16];
__device__ uint4 g_ans_hi[(size_t)NNPAD * 16];
__device__ uint4 g_ans_lo[(size_t)NNPAD * 16];
__device__ uint4 g_Wns[6144];                      // 96KB: [384 n][128 k] single fp16
__device__ float g_xd[(size_t)NNODE * 128];
__device__ float g_z [(size_t)NNODE * 128];
__device__ float g_xtop[(size_t)NNODE * 128];
__device__ float g_xbot[(size_t)NNODE * 128];
__device__ float g_tab[4 * GTAB * 128];
__device__ __half g_tabh[4 * GTAB * 128];
__device__ float g_WbWe1[200 * 128];
__device__ float g_cvec[128];
__device__ float g_W2p[128 * 128];  __device__ float g_b2p[128];
__device__ float g_W3p[128 * 128];  __device__ float g_b3p[128];
__device__ float g_Wn2p[128 * 128]; __device__ float g_bn2p[128];
__device__ float g_sums[6][128];

// ---------------- helpers ----------------
__device__ __forceinline__ unsigned smem_u32(const void* p) {
    unsigned a;
    asm("{ .reg .u64 t; cvta.to.shared.u64 t, %1; cvt.u32.u64 %0, t; }" : "=r"(a) : "l"(p));
    return a;
}
#define CP_ASYNC16(dst, src)                                                   \
    asm volatile("cp.async.cg.shared.global [%0], [%1], 16;"                   \
                 :: "r"(dst), "l"(src) : "memory")
#define CP_COMMIT() asm volatile("cp.async.commit_group;" ::: "memory")
#define CP_WAIT0()  asm volatile("cp.async.wait_group 0;" ::: "memory")
#define LDMX4(r, addr)                                                         \
    asm volatile("ldmatrix.sync.aligned.m8n8.x4.shared.b16 {%0,%1,%2,%3}, [%4];" \
                 : "=r"((r)[0]), "=r"((r)[1]), "=r"((r)[2]), "=r"((r)[3])      \
                 : "r"(addr))
#define MMA_F16(d, a0, a1, a2, a3, b0, b1)                                     \
    asm volatile("mma.sync.aligned.m16n8k16.row.col.f32.f16.f16.f32 "          \
                 "{%0,%1,%2,%3}, {%4,%5,%6,%7}, {%8,%9}, {%0,%1,%2,%3};"       \
                 : "+f"((d)[0]), "+f"((d)[1]), "+f"((d)[2]), "+f"((d)[3])      \
                 : "r"(a0), "r"(a1), "r"(a2), "r"(a3), "r"(b0), "r"(b1))
static __device__ __forceinline__ unsigned pack2h(float a, float b) {
    return ((unsigned)__half_as_ushort(__float2half_rn(b)) << 16)
         |  (unsigned)__half_as_ushort(__float2half_rn(a));
}

// ---------------- tiny prep kernels ----------------
__global__ void zero_stats() { ((float*)g_sums)[threadIdx.x] = 0.0f; }

__global__ void wbwe1_kernel(const float* __restrict__ Wb, const float* __restrict__ We1) {
    int r = blockIdx.x, n = threadIdx.x;
    float acc = 0.f;
    #pragma unroll 8
    for (int k = 0; k < 128; k++) acc += Wb[r * 128 + k] * We1[(128 + k) * 128 + n];
    g_WbWe1[r * 128 + n] = acc;
}

__global__ void cvec_kernel(const float* __restrict__ bb, const float* __restrict__ We1,
                            const float* __restrict__ be1) {
    int n = threadIdx.x;
    float acc = be1[n];
    #pragma unroll 8
    for (int k = 0; k < 128; k++) acc += bb[k] * We1[(128 + k) * 128 + n];
    g_cvec[n] = acc;
}

__global__ void table_kernel() {
    __shared__ float gs[64];
    int b = blockIdx.x;
    int c = b >> 10;
    int gi = b & (GTAB - 1);
    float u = (float)gi * (1.0f / (GTAB - 1));
    int tid = threadIdx.x;
    if (tid < 50) {
        float d = u - (float)tid * (1.0f / 49.0f);
        gs[tid] = __expf(-d * d * 1250.0f);
    }
    __syncthreads();
    float acc = 0.f;
    #pragma unroll
    for (int j = 0; j < 50; j++) acc += gs[j] * g_WbWe1[(c * 50 + j) * 128 + tid];
    g_tab[b * 128 + tid] = acc;
    g_tabh[b * 128 + tid] = __float2half(acc);
}

__global__ void fold_kernel(int sidx, float invM,
                            const float* __restrict__ gamma, const float* __restrict__ beta,
                            const float* __restrict__ Wsrc, const float* __restrict__ be) {
    float* Wdst = (sidx == 0) ? g_W2p : (sidx == 2) ? g_W3p : g_Wn2p;
    float* bdst = (sidx == 0) ? g_b2p : (sidx == 2) ? g_b3p : g_bn2p;
    int n = threadIdx.x;
    if (blockIdx.x < 128) {
        int k = blockIdx.x;
        float m = g_sums[sidx][k] * invM;
        float var = g_sums[sidx + 1][k] * invM - m * m;
        float s = gamma[k] * rsqrtf(var + EPSBN);
        Wdst[k * 128 + n] = s * Wsrc[k * 128 + n];
    } else {
        float acc = be[n];
        for (int k = 0; k < 128; k++) {
            float m = g_sums[sidx][k] * invM;
            float var = g_sums[sidx + 1][k] * invM - m * m;
            float s = gamma[k] * rsqrtf(var + EPSBN);
            acc += (beta[k] - m * s) * Wsrc[k * 128 + n];
        }
        bdst[n] = acc;
    }
}

// Pack W^T into single fp16, 32KB
__global__ void packh_kernel(const float* __restrict__ Wp, char* __restrict__ Ws) {
    int n = blockIdx.x, k = threadIdx.x;
    float v = Wp[k * 128 + n];
    *(unsigned short*)(Ws + n * 256 + 2 * k) = __half_as_ushort(__float2half_rn(v));
}

// Pack node weights: n<128 -> We1_top^T, n<256 -> We1_bot^T, else Wd^T (single fp16)
__global__ void packnode_kernel(const float* __restrict__ We1, const float* __restrict__ Wd) {
    int n = blockIdx.x, k = threadIdx.x;
    float v;
    if (n < 128)       v = We1[k * 128 + n];
    else if (n < 256)  v = We1[(256 + k) * 128 + (n - 128)];
    else               v = Wd[k * 128 + (n - 256)];
    *(unsigned short*)((char*)g_Wns + n * 256 + 2 * k) = __half_as_ushort(__float2half_rn(v));
}

// Split fp32 node array into fp16 hi/lo padded arrays
__global__ __launch_bounds__(256)
void split_kernel(const float* __restrict__ src, char* __restrict__ hb, char* __restrict__ lb) {
    int base = blockIdx.x * 16384;
    #pragma unroll
    for (int i = 0; i < 64; i++) {
        int idx = base + threadIdx.x + i * 256;
        float v = (idx < NNODE * 128) ? __ldg(src + idx) : 0.f;
        __half hh = __float2half_rn(v);
        *(unsigned short*)(hb + 2 * (size_t)idx) = __half_as_ushort(hh);
        *(unsigned short*)(lb + 2 * (size_t)idx) = __half_as_ushort(__float2half_rn(v - __half2float(hh)));
    }
}

// ---------------- fused E1 -> single fp16 tiles (half table, zero smem) ----------------
__global__ __launch_bounds__(128)
void e1_fuse_kernel(const float* __restrict__ ea, const int* __restrict__ eidx) {
    int t = threadIdx.x;
    int e0 = blockIdx.x * 128;
    char* tb = (char*)g_a1split + (size_t)blockIdx.x * 32768;
    float cv = g_cvec[t];
    float csum = 0.f, csq = 0.f;
    int eend = e0 + 128;
    if (eend > NEDGE) eend = NEDGE;
    #pragma unroll 4
    for (int e = e0; e < eend; e++) {
        int s = __ldg(eidx + e);
        int d = __ldg(eidx + NEDGE + e);
        float4 eav = __ldg((const float4*)ea + e);
        float val = g_xtop[(size_t)s * 128 + t] + g_xbot[(size_t)d * 128 + t] + cv;
        float fa[4] = {eav.x, eav.y, eav.z, eav.w};
        #pragma unroll
        for (int c = 0; c < 4; c++) {
            float p = fa[c] * (float)(GTAB - 1);
            int i0 = (int)p;
            if (i0 < 0) i0 = 0;
            if (i0 > GTAB - 2) i0 = GTAB - 2;
            float w = p - (float)i0;
            const __half* t0 = g_tabh + ((size_t)(c * GTAB + i0) * 128 + t);
            float u = __half2float(t0[0]), v2 = __half2float(t0[128]);
            val += u + w * (v2 - u);
        }
        val = (val >= 0.f) ? val : 0.01f * val;
        csum += val; csq += val * val;
        *(unsigned short*)(tb + (e - e0) * 256 + 2 * t) = __half_as_ushort(__float2half_rn(val));
    }
    for (int e = eend; e < e0 + 128; e++)
        *(unsigned short*)(tb + (e - e0) * 256 + 2 * t) = 0;
    atomicAdd(&g_sums[0][t], csum);
    atomicAdd(&g_sums[1][t], csq);
}

// ---------------- tc node GEMM: [xtop | xbot | xd,z] = x @ Wns (fp16 2-product, 3 chunks) ----------------
__global__ __launch_bounds__(256)
void tc_node(const float* __restrict__ bd, const float* __restrict__ vparam) {
    extern __shared__ char sm[];
    __shared__ float s_bd[128], s_v[128];
    const int tid = threadIdx.x;
    const int lane = tid & 31, wid = tid >> 5;
    const int wm = wid & 3, wn = wid >> 2;

    if (tid < 128) { s_bd[tid] = bd[tid]; s_v[tid] = vparam[tid]; }

    const unsigned base_u = smem_u32(sm);
    const unsigned sAh_u = base_u;
    const unsigned sAl_u = base_u + WBYTES;
    const unsigned sW_u  = base_u + 2 * WBYTES;

    const int gbase = blockIdx.x * 128;
    {
        const uint4* hsrc = g_xs_hi + (size_t)gbase * 16;
        const uint4* lsrc = g_xs_lo + (size_t)gbase * 16;
        #pragma unroll
        for (int i = tid; i < 2048; i += 256) {
            int row = i >> 4, ch = i & 15;
            *(uint4*)(sm + row * ROWB + ch * 16)          = hsrc[i];
            *(uint4*)(sm + WBYTES + row * ROWB + ch * 16) = lsrc[i];
        }
    }

    const int laneRow = lane & 15;
    const unsigned laneK = (unsigned)((lane >> 4) << 4);
    const unsigned aoff = (unsigned)((wm * 32 + laneRow) * ROWB) + laneK;
    const unsigned woff = (unsigned)((wn * 64 + laneRow) * ROWB) + laneK;

    #pragma unroll 1
    for (int chunk = 0; chunk < 3; chunk++) {
        {
            const uint4* whs = g_Wns + (size_t)chunk * 2048;
            #pragma unroll
            for (int i = tid; i < 2048; i += 256) {
                int row = i >> 4, ch = i & 15;
                *(uint4*)(sm + 2 * WBYTES + row * ROWB + ch * 16) = whs[i];
            }
        }
        __syncthreads();

        float acc[2][8][4];
        #pragma unroll
        for (int t = 0; t < 2; t++)
            #pragma unroll
            for (int n = 0; n < 8; n++)
                #pragma unroll
                for (int q = 0; q < 4; q++) acc[t][n][q] = 0.f;

        #pragma unroll 1
        for (int ks = 0; ks < 8; ks++) {
            unsigned kb = (unsigned)(ks * 32);
            unsigned ah[2][4], al[2][4], bw[4][4];
            LDMX4(ah[0], sAh_u + aoff + kb);
            LDMX4(ah[1], sAh_u + aoff + 16 * ROWB + kb);
            LDMX4(al[0], sAl_u + aoff + kb);
            LDMX4(al[1], sAl_u + aoff + 16 * ROWB + kb);
            #pragma unroll
            for (int p = 0; p < 4; p++)
                LDMX4(bw[p], sW_u + woff + p * 16 * ROWB + kb);
            #pragma unroll
            for (int t = 0; t < 2; t++)
                #pragma unroll
                for (int p = 0; p < 4; p++) {
                    MMA_F16(acc[t][2 * p],     ah[t][0], ah[t][1], ah[t][2], ah[t][3], bw[p][0], bw[p][2]);
                    MMA_F16(acc[t][2 * p + 1], ah[t][0], ah[t][1], ah[t][2], ah[t][3], bw[p][1], bw[p][3]);
                    MMA_F16(acc[t][2 * p],     al[t][0], al[t][1], al[t][2], al[t][3], bw[p][0], bw[p][2]);
                    MMA_F16(acc[t][2 * p + 1], al[t][0], al[t][1], al[t][2], al[t][3], bw[p][1], bw[p][3]);
                }
        }
        __syncthreads();

        float* sF = (float*)(sm + 2 * WBYTES);
        {
            int mr = lane >> 2;
            int nc = 2 * (lane & 3);
            #pragma unroll
            for (int t = 0; t < 2; t++) {
                int row = wm * 32 + t * 16 + mr;
                #pragma unroll
                for (int nt = 0; nt < 8; nt++) {
                    int col = wn * 64 + nt * 8 + nc;
                    sF[row * 132 + col]           = acc[t][nt][0];
                    sF[row * 132 + col + 1]       = acc[t][nt][1];
                    sF[(row + 8) * 132 + col]     = acc[t][nt][2];
                    sF[(row + 8) * 132 + col + 1] = acc[t][nt][3];
                }
            }
        }
        __syncthreads();

        {
            int rl = tid >> 1, h = tid & 1;
            int grow = gbase + rl;
            if (grow < NNODE) {
                const float* fr = sF + rl * 132 + h * 64;
                if (chunk == 0) {
                    float* dp = g_xtop + (size_t)grow * 128 + h * 64;
                    #pragma unroll
                    for (int q = 0; q < 16; q++)
                        ((float4*)dp)[q] = make_float4(fr[4*q], fr[4*q+1], fr[4*q+2], fr[4*q+3]);
                } else if (chunk == 1) {
                    float* dp = g_xbot + (size_t)grow * 128 + h * 64;
                    #pragma unroll
                    for (int q = 0; q < 16; q++)
                        ((float4*)dp)[q] = make_float4(fr[4*q], fr[4*q+1], fr[4*q+2], fr[4*q+3]);
                } else {
                    float* dx = g_xd + (size_t)grow * 128 + h * 64;
                    float* dz = g_z  + (size_t)grow * 128 + h * 64;
                    const float* bp = s_bd + h * 64;
                    const float* vp = s_v + h * 64;
                    #pragma unroll
                    for (int q = 0; q < 16; q++) {
                        float x0 = fr[4*q]   + bp[4*q];
                        float x1 = fr[4*q+1] + bp[4*q+1];
                        float x2 = fr[4*q+2] + bp[4*q+2];
                        float x3 = fr[4*q+3] + bp[4*q+3];
                        ((float4*)dx)[q] = make_float4(x0, x1, x2, x3);
                        ((float4*)dz)[q] = make_float4(vp[4*q]*x0, vp[4*q+1]*x1, vp[4*q+2]*x2, vp[4*q+3]*x3);
                    }
                }
            }
        }
        __syncthreads();
    }
}

// ---------------- tc node GEMM 2: MODE 0 = N1, MODE 1 = OUT (fp16 2-product) ----------------
template <int MODE>
__global__ __launch_bounds__(256)
void tc_node2(const float* __restrict__ biasExt, const float* __restrict__ x,
              float* __restrict__ outp) {
    extern __shared__ char sm[];
    __shared__ float s_bias[128];
    const int tid = threadIdx.x;
    const int lane = tid & 31, wid = tid >> 5;
    const int wm = wid & 3, wn = wid >> 2;

    if (tid < 128) s_bias[tid] = (MODE == 0) ? biasExt[tid] : g_bn2p[tid];

    const unsigned base_u = smem_u32(sm);
    const unsigned sAh_u = base_u;
    const unsigned sAl_u = base_u + WBYTES;
    const unsigned sW_u  = base_u + 2 * WBYTES;

    const int gbase = blockIdx.x * 128;
    {
        const uint4* hsrc = (MODE == 0 ? g_zs_hi : g_ans_hi) + (size_t)gbase * 16;
        const uint4* lsrc = (MODE == 0 ? g_zs_lo : g_ans_lo) + (size_t)gbase * 16;
        const uint4* whs  = (MODE == 0 ? g_Wn1s : g_Wn2s);
        #pragma unroll
        for (int i = tid; i < 2048; i += 256) {
            int row = i >> 4, ch = i & 15;
            *(uint4*)(sm + row * ROWB + ch * 16)              = hsrc[i];
            *(uint4*)(sm + WBYTES + row * ROWB + ch * 16)     = lsrc[i];
            *(uint4*)(sm + 2 * WBYTES + row * ROWB + ch * 16) = whs[i];
        }
    }
    __syncthreads();

    const int laneRow = lane & 15;
    const unsigned laneK = (unsigned)((lane >> 4) << 4);
    const unsigned aoff = (unsigned)((wm * 32 + laneRow) * ROWB) + laneK;
    const unsigned woff = (unsigned)((wn * 64 + laneRow) * ROWB) + laneK;

    float acc[2][8][4];
    #pragma unroll
    for (int t = 0; t < 2; t++)
        #pragma unroll
        for (int n = 0; n < 8; n++)
            #pragma unroll
            for (int q = 0; q < 4; q++) acc[t][n][q] = 0.f;

    #pragma unroll 1
    for (int ks = 0; ks < 8; ks++) {
        unsigned kb = (unsigned)(ks * 32);
        unsigned ah[2][4], al[2][4], bw[4][4];
        LDMX4(ah[0], sAh_u + aoff + kb);
        LDMX4(ah[1], sAh_u + aoff + 16 * ROWB + kb);
        LDMX4(al[0], sAl_u + aoff + kb);
        LDMX4(al[1], sAl_u + aoff + 16 * ROWB + kb);
        #pragma unroll
        for (int p = 0; p < 4; p++)
            LDMX4(bw[p], sW_u + woff + p * 16 * ROWB + kb);
        #pragma unroll
        for (int t = 0; t < 2; t++)
            #pragma unroll
            for (int p = 0; p < 4; p++) {
                MMA_F16(acc[t][2 * p],     ah[t][0], ah[t][1], ah[t][2], ah[t][3], bw[p][0], bw[p][2]);
                MMA_F16(acc[t][2 * p + 1], ah[t][0], ah[t][1], ah[t][2], ah[t][3], bw[p][1], bw[p][3]);
                MMA_F16(acc[t][2 * p],     al[t][0], al[t][1], al[t][2], al[t][3], bw[p][0], bw[p][2]);
                MMA_F16(acc[t][2 * p + 1], al[t][0], al[t][1], al[t][2], al[t][3], bw[p][1], bw[p][3]);
            }
    }
    __syncthreads();

    float* sF = (float*)(sm + 2 * WBYTES);
    {
        int mr = lane >> 2;
        int nc = 2 * (lane & 3);
        #pragma unroll
        for (int t = 0; t < 2; t++) {
            int row = wm * 32 + t * 16 + mr;
            #pragma unroll
            for (int nt = 0; nt < 8; nt++) {
                int col = wn * 64 + nt * 8 + nc;
                sF[row * 132 + col]           = acc[t][nt][0];
                sF[row * 132 + col + 1]       = acc[t][nt][1];
                sF[(row + 8) * 132 + col]     = acc[t][nt][2];
                sF[(row + 8) * 132 + col + 1] = acc[t][nt][3];
            }
        }
    }
    __syncthreads();

    if (MODE == 0) {
        int rl = tid >> 1, h = tid & 1;
        int grow = gbase + rl;
        bool valid = grow < NNODE;
        float* fr = sF + rl * 132 + h * 64;
        const float* bp = s_bias + h * 64;
        uint4* dh = (uint4*)((char*)g_ans_hi + (size_t)grow * 256 + h * 128);
        uint4* dl = (uint4*)((char*)g_ans_lo + (size_t)grow * 256 + h * 128);
        #pragma unroll
        for (int q = 0; q < 8; q++) {
            unsigned ph[4], pl[4];
            #pragma unroll
            for (int j = 0; j < 4; j++) {
                int c = q * 8 + j * 2;
                float v0 = fr[c]     + bp[c];
                float v1 = fr[c + 1] + bp[c + 1];
                v0 = (v0 >= 0.f) ? v0 : 0.01f * v0;
                v1 = (v1 >= 0.f) ? v1 : 0.01f * v1;
                if (!valid) { v0 = 0.f; v1 = 0.f; }
                fr[c] = v0; fr[c + 1] = v1;
                float h0 = __half2float(__float2half_rn(v0));
                float h1 = __half2float(__float2half_rn(v1));
                ph[j] = pack2h(h0, h1);
                pl[j] = pack2h(v0 - h0, v1 - h1);
            }
            dh[q] = make_uint4(ph[0], ph[1], ph[2], ph[3]);
            dl[q] = make_uint4(pl[0], pl[1], pl[2], pl[3]);
        }
        __syncthreads();
        {
            int c = tid & 127, h2 = tid >> 7;
            float s0 = 0.f, s1 = 0.f;
            #pragma unroll 8
            for (int r = 0; r < 64; r++) {
                float v = sF[(h2 * 64 + r) * 132 + c];
                s0 += v; s1 += v * v;
            }
            atomicAdd(&g_sums[4][c], s0);
            atomicAdd(&g_sums[5][c], s1);
        }
    } else {
        int rl = tid >> 1, h = tid & 1;
        int grow = gbase + rl;
        if (grow < NNODE) {
            const float* fr = sF + rl * 132 + h * 64;
            const float* bp = s_bias + h * 64;
            const float4* xp = (const float4*)(x + (size_t)grow * 128 + h * 64);
            float* dp = outp + (size_t)grow * 128 + h * 64;
            #pragma unroll
            for (int q = 0; q < 16; q++) {
                float4 xv = xp[q];
                ((float4*)dp)[q] = make_float4(fr[4*q]   + bp[4*q]   + xv.x,
                                               fr[4*q+1] + bp[4*q+1] + xv.y,
                                               fr[4*q+2] + bp[4*q+2] + xv.z,
                                               fr[4*q+3] + bp[4*q+3] + xv.w);
            }
        }
    }
}

// ---------------- persistent fp16 1-product edge GEMMs (cp.async double buffer) ----------------
// MODE 0 = E2, MODE 1 = E3
template <int MODE>
__global__ __launch_bounds__(256)
void tc_gemm(const float* __restrict__ ea, const int* __restrict__ eidx) {
    extern __shared__ char sm[];
    __shared__ float s_bias[128];
    const int tid = threadIdx.x;
    const int lane = tid & 31, wid = tid >> 5;
    const int wm = wid & 3, wn = wid >> 2;

    const unsigned base_u = smem_u32(sm);
    const unsigned sW_u = base_u;

    if (tid < 128) s_bias[tid] = (MODE == 0) ? g_b2p[tid] : g_b3p[tid];

    const uint4* Abase = (MODE == 0 ? g_a1split : g_a2split);
    const uint4* Wsrc  = (MODE == 0 ? g_W2s : g_W3s);

    int tile = blockIdx.x;
    {
        const uint4* src = Abase + (size_t)tile * 2048;
        unsigned dst = base_u + WBYTES;
        #pragma unroll
        for (int i = tid; i < 2048; i += 256) {
            int row = i >> 4, ch = i & 15;
            CP_ASYNC16(dst + (unsigned)(row * ROWB + ch * 16), src + i);
        }
        CP_COMMIT();
        #pragma unroll
        for (int i = tid; i < 2048; i += 256) {
            int row = i >> 4, ch = i & 15;
            *(uint4*)(sm + row * ROWB + ch * 16) = Wsrc[i];
        }
        CP_WAIT0();
    }
    __syncthreads();

    const int laneRow = lane & 15;
    const unsigned laneK = (unsigned)((lane >> 4) << 4);
    const unsigned aoff0 = (unsigned)((wm * 32 + laneRow) * ROWB) + laneK;
    const unsigned woff  = (unsigned)((wn * 64 + laneRow) * ROWB) + laneK;

    int buf = 0;
    for (; tile < NTILE; tile += GRID_TC) {
        int nxt = tile + GRID_TC;
        if (nxt < NTILE) {
            const uint4* src = Abase + (size_t)nxt * 2048;
            unsigned dst = base_u + WBYTES + (unsigned)((buf ^ 1) * ABUF);
            #pragma unroll
            for (int i = tid; i < 2048; i += 256) {
                int row = i >> 4, ch = i & 15;
                CP_ASYNC16(dst + (unsigned)(row * ROWB + ch * 16), src + i);
            }
        }
        CP_COMMIT();

        const unsigned sA_u = base_u + WBYTES + (unsigned)(buf * ABUF);

        float acc[2][8][4];
        #pragma unroll
        for (int t = 0; t < 2; t++)
            #pragma unroll
            for (int n = 0; n < 8; n++)
                #pragma unroll
                for (int q = 0; q < 4; q++) acc[t][n][q] = 0.f;

        #pragma unroll 1
        for (int ks = 0; ks < 8; ks++) {
            unsigned kb = (unsigned)(ks * 32);
            unsigned ah[2][4], bw[4][4];
            LDMX4(ah[0], sA_u + aoff0 + kb);
            LDMX4(ah[1], sA_u + aoff0 + 16 * ROWB + kb);
            #pragma unroll
            for (int p = 0; p < 4; p++)
                LDMX4(bw[p], sW_u + woff + p * 16 * ROWB + kb);
            #pragma unroll
            for (int t = 0; t < 2; t++)
                #pragma unroll
                for (int p = 0; p < 4; p++) {
                    MMA_F16(acc[t][2 * p],     ah[t][0], ah[t][1], ah[t][2], ah[t][3], bw[p][0], bw[p][2]);
                    MMA_F16(acc[t][2 * p + 1], ah[t][0], ah[t][1], ah[t][2], ah[t][3], bw[p][1], bw[p][3]);
                }
        }
        __syncthreads();

        float* sF = (float*)(sm + WBYTES + buf * ABUF);
        {
            int mr = lane >> 2;
            int nc = 2 * (lane & 3);
            #pragma unroll
            for (int t = 0; t < 2; t++) {
                int row = wm * 32 + t * 16 + mr;
                #pragma unroll
                for (int nt = 0; nt < 8; nt++) {
                    int col = wn * 64 + nt * 8 + nc;
                    sF[row * 132 + col]           = acc[t][nt][0];
                    sF[row * 132 + col + 1]       = acc[t][nt][1];
                    sF[(row + 8) * 132 + col]     = acc[t][nt][2];
                    sF[(row + 8) * 132 + col + 1] = acc[t][nt][3];
                }
            }
        }
        __syncthreads();

        if (MODE == 0) {
            int rl = tid >> 1, h = tid & 1;
            long gbase = (long)tile * 128;
            bool valid = (gbase + rl) < NEDGE;
            char* outb = (char*)g_a2split + (size_t)tile * 32768;
            uint4* dh = (uint4*)(outb + rl * 256 + h * 128);
            float* fr = sF + rl * 132 + h * 64;
            const float* bp = s_bias + h * 64;
            #pragma unroll
            for (int q = 0; q < 8; q++) {
                unsigned ph[4];
                #pragma unroll
                for (int j = 0; j < 4; j++) {
                    int c = q * 8 + j * 2;
                    float v0 = fr[c]     + bp[c];
                    float v1 = fr[c + 1] + bp[c + 1];
                    v0 = (v0 >= 0.f) ? v0 : 0.01f * v0;
                    v1 = (v1 >= 0.f) ? v1 : 0.01f * v1;
                    if (!valid) { v0 = 0.f; v1 = 0.f; }
                    fr[c] = v0; fr[c + 1] = v1;
                    ph[j] = pack2h(v0, v1);
                }
                dh[q] = make_uint4(ph[0], ph[1], ph[2], ph[3]);
            }
            __syncthreads();
            {
                int c = tid & 127, h2 = tid >> 7;
                float s0 = 0.f, s1 = 0.f;
                #pragma unroll 8
                for (int r = 0; r < 64; r++) {
                    float v = sF[(h2 * 64 + r) * 132 + c];
                    s0 += v; s1 += v * v;
                }
                atomicAdd(&g_sums[2][c], s0);
                atomicAdd(&g_sums[3][c], s1);
            }
        } else {
            int rt = tid >> 1, h = tid & 1;
            long grow = (long)tile * 128 + rt;
            if (grow < NEDGE) {
                int s_ = eidx[grow], d_ = eidx[NEDGE + grow];
                float coeff = cosf(1.5707963267948966f * ea[grow * 4 + 3]);
                const float4* xp = (const float4*)(g_xd + (size_t)s_ * 128) + h * 16;
                float* zp = g_z + (size_t)d_ * 128 + h * 64;
                const float* fr = sF + rt * 132 + h * 64;
                const float* bp = s_bias + h * 64;
                #pragma unroll
                for (int q = 0; q < 16; q++) {
                    float4 xv = xp[q];
                    float v0 = coeff * (fr[4 * q + 0] + bp[4 * q + 0]) * xv.x;
                    float v1 = coeff * (fr[4 * q + 1] + bp[4 * q + 1]) * xv.y;
                    float v2 = coeff * (fr[4 * q + 2] + bp[4 * q + 2]) * xv.z;
                    float v3 = coeff * (fr[4 * q + 3] + bp[4 * q + 3]) * xv.w;
                    asm volatile("red.global.add.v4.f32 [%0], {%1,%2,%3,%4};"
                                 :: "l"(zp + 4 * q), "f"(v0), "f"(v1), "f"(v2), "f"(v3) : "memory");
                }
            }
        }
        __syncthreads();
        CP_WAIT0();
        __syncthreads();
        buf ^= 1;
    }
}

// ---------------- launcher ----------------
extern "C" void kernel_launch(void* const* d_in, const int* in_sizes, int n_in,
                              void* d_out, int out_size) {
    const float* x    = (const float*)d_in[0];
    const float* ea   = (const float*)d_in[1];
    const int*   eidx = (const int*)  d_in[2];
    const float* Wb   = (const float*)d_in[3];
    const float* bb   = (const float*)d_in[4];
    const float* We1  = (const float*)d_in[5];
    const float* be1  = (const float*)d_in[6];
    const float* ge1  = (const float*)d_in[7];
    const float* bte1 = (const float*)d_in[8];
    const float* We2  = (const float*)d_in[9];
    const float* be2  = (const float*)d_in[10];
    const float* ge2  = (const float*)d_in[11];
    const float* bte2 = (const float*)d_in[12];
    const float* We3  = (const float*)d_in[13];
    const float* be3  = (const float*)d_in[14];
    const float* Wd   = (const float*)d_in[15];
    const float* bd   = (const float*)d_in[16];
    const float* v    = (const float*)d_in[17];
    const float* Wn1  = (const float*)d_in[18];
    const float* bn1  = (const float*)d_in[19];
    const float* gn   = (const float*)d_in[20];
    const float* btn  = (const float*)d_in[21];
    const float* Wn2  = (const float*)d_in[22];
    const float* bn2  = (const float*)d_in[23];
    float* outp = (float*)d_out;

    float* d_z;    cudaGetSymbolAddress((void**)&d_z, g_z);
    float* d_W2p;  cudaGetSymbolAddress((void**)&d_W2p, g_W2p);
    float* d_W3p;  cudaGetSymbolAddress((void**)&d_W3p, g_W3p);
    float* d_Wn2p; cudaGetSymbolAddress((void**)&d_Wn2p, g_Wn2p);
    char*  d_W2s;  cudaGetSymbolAddress((void**)&d_W2s, g_W2s);
    char*  d_W3s;  cudaGetSymbolAddress((void**)&d_W3s, g_W3s);
    char*  d_Wn1s; cudaGetSymbolAddress((void**)&d_Wn1s, g_Wn1s);
    char*  d_Wn2s; cudaGetSymbolAddress((void**)&d_Wn2s, g_Wn2s);
    char*  d_xsh;  cudaGetSymbolAddress((void**)&d_xsh, g_xs_hi);
    char*  d_xsl;  cudaGetSymbolAddress((void**)&d_xsl, g_xs_lo);
    char*  d_zsh;  cudaGetSymbolAddress((void**)&d_zsh, g_zs_hi);
    char*  d_zsl;  cudaGetSymbolAddress((void**)&d_zsl, g_zs_lo);

    cudaFuncSetAttribute(tc_gemm<0>, cudaFuncAttributeMaxDynamicSharedMemorySize, TCSM_E);
    cudaFuncSetAttribute(tc_gemm<1>, cudaFuncAttributeMaxDynamicSharedMemorySize, TCSM_E);
    cudaFuncSetAttribute(tc_node, cudaFuncAttributeMaxDynamicSharedMemorySize, TCSM_N);
    cudaFuncSetAttribute(tc_node2<0>, cudaFuncAttributeMaxDynamicSharedMemorySize, TCSM_N);
    cudaFuncSetAttribute(tc_node2<1>, cudaFuncAttributeMaxDynamicSharedMemorySize, TCSM_N);

    zero_stats<<<1, 768>>>();
    wbwe1_kernel<<<200, 128>>>(Wb, We1);
    cvec_kernel<<<1, 128>>>(bb, We1, be1);
    table_kernel<<<4 * GTAB, 128>>>();
    split_kernel<<<NTILEN, 256>>>(x, d_xsh, d_xsl);
    packnode_kernel<<<384, 128>>>(We1, Wd);
    packh_kernel<<<128, 128>>>(Wn1, d_Wn1s);

    tc_node<<<NTILEN, 256, TCSM_N>>>(bd, v);

    e1_fuse_kernel<<<NTILE, 128>>>(ea, eidx);
    fold_kernel<<<129, 128>>>(0, 1.0f / NEDGE, ge1, bte1, We2, be2);
    packh_kernel<<<128, 128>>>(d_W2p, d_W2s);

    tc_gemm<0><<<GRID_TC, 256, TCSM_E>>>(ea, eidx);
    fold_kernel<<<129, 128>>>(2, 1.0f / NEDGE, ge2, bte2, We3, be3);
    packh_kernel<<<128, 128>>>(d_W3p, d_W3s);

    tc_gemm<1><<<GRID_TC, 256, TCSM_E>>>(ea, eidx);

    split_kernel<<<NTILEN, 256>>>(d_z, d_zsh, d_zsl);
    tc_node2<0><<<NTILEN, 256, TCSM_N>>>(bn1, nullptr, nullptr);
    fold_kernel<<<129, 128>>>(4, 1.0f / NNODE, gn, btn, Wn2, bn2);
    packh_kernel<<<128, 128>>>(d_Wn2p, d_Wn2s);
    tc_node2<1><<<NTILEN, 256, TCSM_N>>>(nullptr, x, outp);
}

// round 17
// speedup vs baseline: 2.2953x; 1.0515x over previous
#include <cuda_runtime.h>
#include <cuda_bf16.h>
#include <cuda_fp16.h>

#define NNODE 50000
#define NNPAD 50048             // 391 * 128
#define NEDGE 300000
#define GTAB  1024
#define EPSBN 1e-5f
#define NTILE 2344              // ceil(NEDGE/128)
#define NTILEN 391              // ceil(NNODE/128)
#define ROWB  272               // padded smem row bytes (136 elems)
#define WBYTES 34816            // 128 * ROWB
#define ABUF   69632            // buffer region (A fp16 single uses first half; fp32 stage uses all)
#define TCSM_E (WBYTES + 2 * ABUF)   // 174080
#define TCSM_N (WBYTES + 69632)      // 104448: A single + W/stage region
#define GRID_TC 148

// ---------------- scratch (device globals; no allocation) ----------------
__device__ uint4 g_a1split[(size_t)NTILE * 2048];  // per tile: 32KB single fp16, [m][k] 256B rows
__device__ uint4 g_a2split[(size_t)NTILE * 2048];
__device__ uint4 g_W2s[2048];                      // 32KB: W^T [n][k] single fp16
__device__ uint4 g_W3s[2048];
__device__ uint4 g_Wn1s[2048];
__device__ uint4 g_Wn2s[2048];
__device__ uint4 g_xs [(size_t)NNPAD * 16];        // x fp16, [m][k] 256B rows
__device__ uint4 g_zs [(size_t)NNPAD * 16];
__device__ uint4 g_ans[(size_t)NNPAD * 16];
__device__ __half g_xtoph[(size_t)NNPAD * 128];
__device__ __half g_xboth[(size_t)NNPAD * 128];
__device__ uint4 g_Wns[6144];                      // 96KB: [384 n][128 k] single fp16
__device__ float g_xd[(size_t)NNODE * 128];
__device__ float g_z [(size_t)NNODE * 128];
__device__ float g_tab[4 * GTAB * 128];
__device__ __half g_tabh[4 * GTAB * 128];
__device__ float g_WbWe1[200 * 128];
__device__ float g_cvec[128];
__device__ float g_W2p[128 * 128];  __device__ float g_b2p[128];
__device__ float g_W3p[128 * 128];  __device__ float g_b3p[128];
__device__ float g_Wn2p[128 * 128]; __device__ float g_bn2p[128];
__device__ float g_sums[6][128];

// ---------------- helpers ----------------
__device__ __forceinline__ unsigned smem_u32(const void* p) {
    unsigned a;
    asm("{ .reg .u64 t; cvta.to.shared.u64 t, %1; cvt.u32.u64 %0, t; }" : "=r"(a) : "l"(p));
    return a;
}
#define CP_ASYNC16(dst, src)                                                   \
    asm volatile("cp.async.cg.shared.global [%0], [%1], 16;"                   \
                 :: "r"(dst), "l"(src) : "memory")
#define CP_COMMIT() asm volatile("cp.async.commit_group;" ::: "memory")
#define CP_WAIT0()  asm volatile("cp.async.wait_group 0;" ::: "memory")
#define LDMX4(r, addr)                                                         \
    asm volatile("ldmatrix.sync.aligned.m8n8.x4.shared.b16 {%0,%1,%2,%3}, [%4];" \
                 : "=r"((r)[0]), "=r"((r)[1]), "=r"((r)[2]), "=r"((r)[3])      \
                 : "r"(addr))
#define MMA_F16(d, a0, a1, a2, a3, b0, b1)                                     \
    asm volatile("mma.sync.aligned.m16n8k16.row.col.f32.f16.f16.f32 "          \
                 "{%0,%1,%2,%3}, {%4,%5,%6,%7}, {%8,%9}, {%0,%1,%2,%3};"       \
                 : "+f"((d)[0]), "+f"((d)[1]), "+f"((d)[2]), "+f"((d)[3])      \
                 : "r"(a0), "r"(a1), "r"(a2), "r"(a3), "r"(b0), "r"(b1))
static __device__ __forceinline__ unsigned pack2h(float a, float b) {
    return ((unsigned)__half_as_ushort(__float2half_rn(b)) << 16)
         |  (unsigned)__half_as_ushort(__float2half_rn(a));
}

// ---------------- tiny prep kernels ----------------
__global__ void zero_stats() { ((float*)g_sums)[threadIdx.x] = 0.0f; }

__global__ void wbwe1_kernel(const float* __restrict__ Wb, const float* __restrict__ We1) {
    int r = blockIdx.x, n = threadIdx.x;
    float acc = 0.f;
    #pragma unroll 8
    for (int k = 0; k < 128; k++) acc += Wb[r * 128 + k] * We1[(128 + k) * 128 + n];
    g_WbWe1[r * 128 + n] = acc;
}

__global__ void cvec_kernel(const float* __restrict__ bb, const float* __restrict__ We1,
                            const float* __restrict__ be1) {
    int n = threadIdx.x;
    float acc = be1[n];
    #pragma unroll 8
    for (int k = 0; k < 128; k++) acc += bb[k] * We1[(128 + k) * 128 + n];
    g_cvec[n] = acc;
}

__global__ void table_kernel() {
    __shared__ float gs[64];
    int b = blockIdx.x;
    int c = b >> 10;
    int gi = b & (GTAB - 1);
    float u = (float)gi * (1.0f / (GTAB - 1));
    int tid = threadIdx.x;
    if (tid < 50) {
        float d = u - (float)tid * (1.0f / 49.0f);
        gs[tid] = __expf(-d * d * 1250.0f);
    }
    __syncthreads();
    float acc = 0.f;
    #pragma unroll
    for (int j = 0; j < 50; j++) acc += gs[j] * g_WbWe1[(c * 50 + j) * 128 + tid];
    g_tab[b * 128 + tid] = acc;
    g_tabh[b * 128 + tid] = __float2half(acc);
}

__global__ void fold_kernel(int sidx, float invM,
                            const float* __restrict__ gamma, const float* __restrict__ beta,
                            const float* __restrict__ Wsrc, const float* __restrict__ be) {
    float* Wdst = (sidx == 0) ? g_W2p : (sidx == 2) ? g_W3p : g_Wn2p;
    float* bdst = (sidx == 0) ? g_b2p : (sidx == 2) ? g_b3p : g_bn2p;
    int n = threadIdx.x;
    if (blockIdx.x < 128) {
        int k = blockIdx.x;
        float m = g_sums[sidx][k] * invM;
        float var = g_sums[sidx + 1][k] * invM - m * m;
        float s = gamma[k] * rsqrtf(var + EPSBN);
        Wdst[k * 128 + n] = s * Wsrc[k * 128 + n];
    } else {
        float acc = be[n];
        for (int k = 0; k < 128; k++) {
            float m = g_sums[sidx][k] * invM;
            float var = g_sums[sidx + 1][k] * invM - m * m;
            float s = gamma[k] * rsqrtf(var + EPSBN);
            acc += (beta[k] - m * s) * Wsrc[k * 128 + n];
        }
        bdst[n] = acc;
    }
}

// Pack W^T into single fp16, 32KB
__global__ void packh_kernel(const float* __restrict__ Wp, char* __restrict__ Ws) {
    int n = blockIdx.x, k = threadIdx.x;
    float v = Wp[k * 128 + n];
    *(unsigned short*)(Ws + n * 256 + 2 * k) = __half_as_ushort(__float2half_rn(v));
}

// Pack node weights: n<128 -> We1_top^T, n<256 -> We1_bot^T, else Wd^T (single fp16)
__global__ void packnode_kernel(const float* __restrict__ We1, const float* __restrict__ Wd) {
    int n = blockIdx.x, k = threadIdx.x;
    float v;
    if (n < 128)       v = We1[k * 128 + n];
    else if (n < 256)  v = We1[(256 + k) * 128 + (n - 128)];
    else               v = Wd[k * 128 + (n - 256)];
    *(unsigned short*)((char*)g_Wns + n * 256 + 2 * k) = __half_as_ushort(__float2half_rn(v));
}

// Split fp32 node array into single fp16 padded array
__global__ __launch_bounds__(256)
void split_kernel(const float* __restrict__ src, char* __restrict__ hb) {
    int base = blockIdx.x * 16384;
    #pragma unroll
    for (int i = 0; i < 64; i++) {
        int idx = base + threadIdx.x + i * 256;
        float v = (idx < NNODE * 128) ? __ldg(src + idx) : 0.f;
        *(unsigned short*)(hb + 2 * (size_t)idx) = __half_as_ushort(__float2half_rn(v));
    }
}

// ---------------- fused E1 -> single fp16 tiles (half table + half xtop/xbot) ----------------
__global__ __launch_bounds__(128)
void e1_fuse_kernel(const float* __restrict__ ea, const int* __restrict__ eidx) {
    int t = threadIdx.x;
    int e0 = blockIdx.x * 128;
    char* tb = (char*)g_a1split + (size_t)blockIdx.x * 32768;
    float cv = g_cvec[t];
    float csum = 0.f, csq = 0.f;
    int eend = e0 + 128;
    if (eend > NEDGE) eend = NEDGE;
    #pragma unroll 4
    for (int e = e0; e < eend; e++) {
        int s = __ldg(eidx + e);
        int d = __ldg(eidx + NEDGE + e);
        float4 eav = __ldg((const float4*)ea + e);
        float val = __half2float(g_xtoph[(size_t)s * 128 + t])
                  + __half2float(g_xboth[(size_t)d * 128 + t]) + cv;
        float fa[4] = {eav.x, eav.y, eav.z, eav.w};
        #pragma unroll
        for (int c = 0; c < 4; c++) {
            float p = fa[c] * (float)(GTAB - 1);
            int i0 = (int)p;
            if (i0 < 0) i0 = 0;
            if (i0 > GTAB - 2) i0 = GTAB - 2;
            float w = p - (float)i0;
            const __half* t0 = g_tabh + ((size_t)(c * GTAB + i0) * 128 + t);
            float u = __half2float(t0[0]), v2 = __half2float(t0[128]);
            val += u + w * (v2 - u);
        }
        val = (val >= 0.f) ? val : 0.01f * val;
        csum += val; csq += val * val;
        *(unsigned short*)(tb + (e - e0) * 256 + 2 * t) = __half_as_ushort(__float2half_rn(val));
    }
    for (int e = eend; e < e0 + 128; e++)
        *(unsigned short*)(tb + (e - e0) * 256 + 2 * t) = 0;
    atomicAdd(&g_sums[0][t], csum);
    atomicAdd(&g_sums[1][t], csq);
}

// ---------------- tc node GEMM: [xtop | xbot | xd,z] = x @ Wns (fp16 1-product, 3 chunks) ----------------
__global__ __launch_bounds__(256)
void tc_node(const float* __restrict__ bd, const float* __restrict__ vparam) {
    extern __shared__ char sm[];
    __shared__ float s_bd[128], s_v[128];
    const int tid = threadIdx.x;
    const int lane = tid & 31, wid = tid >> 5;
    const int wm = wid & 3, wn = wid >> 2;

    if (tid < 128) { s_bd[tid] = bd[tid]; s_v[tid] = vparam[tid]; }

    const unsigned base_u = smem_u32(sm);
    const unsigned sA_u = base_u;
    const unsigned sW_u = base_u + WBYTES;

    const int gbase = blockIdx.x * 128;
    {
        const uint4* hsrc = g_xs + (size_t)gbase * 16;
        #pragma unroll
        for (int i = tid; i < 2048; i += 256) {
            int row = i >> 4, ch = i & 15;
            *(uint4*)(sm + row * ROWB + ch * 16) = hsrc[i];
        }
    }

    const int laneRow = lane & 15;
    const unsigned laneK = (unsigned)((lane >> 4) << 4);
    const unsigned aoff = (unsigned)((wm * 32 + laneRow) * ROWB) + laneK;
    const unsigned woff = (unsigned)((wn * 64 + laneRow) * ROWB) + laneK;

    #pragma unroll 1
    for (int chunk = 0; chunk < 3; chunk++) {
        {
            const uint4* whs = g_Wns + (size_t)chunk * 2048;
            #pragma unroll
            for (int i = tid; i < 2048; i += 256) {
                int row = i >> 4, ch = i & 15;
                *(uint4*)(sm + WBYTES + row * ROWB + ch * 16) = whs[i];
            }
        }
        __syncthreads();

        float acc[2][8][4];
        #pragma unroll
        for (int t = 0; t < 2; t++)
            #pragma unroll
            for (int n = 0; n < 8; n++)
                #pragma unroll
                for (int q = 0; q < 4; q++) acc[t][n][q] = 0.f;

        #pragma unroll 1
        for (int ks = 0; ks < 8; ks++) {
            unsigned kb = (unsigned)(ks * 32);
            unsigned ah[2][4], bw[4][4];
            LDMX4(ah[0], sA_u + aoff + kb);
            LDMX4(ah[1], sA_u + aoff + 16 * ROWB + kb);
            #pragma unroll
            for (int p = 0; p < 4; p++)
                LDMX4(bw[p], sW_u + woff + p * 16 * ROWB + kb);
            #pragma unroll
            for (int t = 0; t < 2; t++)
                #pragma unroll
                for (int p = 0; p < 4; p++) {
                    MMA_F16(acc[t][2 * p],     ah[t][0], ah[t][1], ah[t][2], ah[t][3], bw[p][0], bw[p][2]);
                    MMA_F16(acc[t][2 * p + 1], ah[t][0], ah[t][1], ah[t][2], ah[t][3], bw[p][1], bw[p][3]);
                }
        }
        __syncthreads();

        float* sF = (float*)(sm + WBYTES);
        {
            int mr = lane >> 2;
            int nc = 2 * (lane & 3);
            #pragma unroll
            for (int t = 0; t < 2; t++) {
                int row = wm * 32 + t * 16 + mr;
                #pragma unroll
                for (int nt = 0; nt < 8; nt++) {
                    int col = wn * 64 + nt * 8 + nc;
                    sF[row * 132 + col]           = acc[t][nt][0];
                    sF[row * 132 + col + 1]       = acc[t][nt][1];
                    sF[(row + 8) * 132 + col]     = acc[t][nt][2];
                    sF[(row + 8) * 132 + col + 1] = acc[t][nt][3];
                }
            }
        }
        __syncthreads();

        {
            int rl = tid >> 1, h = tid & 1;
            int grow = gbase + rl;
            if (grow < NNODE) {
                const float* fr = sF + rl * 132 + h * 64;
                if (chunk < 2) {
                    __half* dsth = (chunk == 0 ? g_xtoph : g_xboth);
                    uint4* dp = (uint4*)((char*)dsth + (size_t)grow * 256 + h * 128);
                    #pragma unroll
                    for (int q = 0; q < 8; q++) {
                        unsigned p0 = pack2h(fr[8*q],   fr[8*q+1]);
                        unsigned p1 = pack2h(fr[8*q+2], fr[8*q+3]);
                        unsigned p2 = pack2h(fr[8*q+4], fr[8*q+5]);
                        unsigned p3 = pack2h(fr[8*q+6], fr[8*q+7]);
                        dp[q] = make_uint4(p0, p1, p2, p3);
                    }
                } else {
                    float* dx = g_xd + (size_t)grow * 128 + h * 64;
                    float* dz = g_z  + (size_t)grow * 128 + h * 64;
                    const float* bp = s_bd + h * 64;
                    const float* vp = s_v + h * 64;
                    #pragma unroll
                    for (int q = 0; q < 16; q++) {
                        float x0 = fr[4*q]   + bp[4*q];
                        float x1 = fr[4*q+1] + bp[4*q+1];
                        float x2 = fr[4*q+2] + bp[4*q+2];
                        float x3 = fr[4*q+3] + bp[4*q+3];
                        ((float4*)dx)[q] = make_float4(x0, x1, x2, x3);
                        ((float4*)dz)[q] = make_float4(vp[4*q]*x0, vp[4*q+1]*x1, vp[4*q+2]*x2, vp[4*q+3]*x3);
                    }
                }
            }
        }
        __syncthreads();
    }
}

// ---------------- tc node GEMM 2: MODE 0 = N1, MODE 1 = OUT (fp16 1-product) ----------------
template <int MODE>
__global__ __launch_bounds__(256)
void tc_node2(const float* __restrict__ biasExt, const float* __restrict__ x,
              float* __restrict__ outp) {
    extern __shared__ char sm[];
    __shared__ float s_bias[128];
    const int tid = threadIdx.x;
    const int lane = tid & 31, wid = tid >> 5;
    const int wm = wid & 3, wn = wid >> 2;

    if (tid < 128) s_bias[tid] = (MODE == 0) ? biasExt[tid] : g_bn2p[tid];

    const unsigned base_u = smem_u32(sm);
    const unsigned sA_u = base_u;
    const unsigned sW_u = base_u + WBYTES;

    const int gbase = blockIdx.x * 128;
    {
        const uint4* hsrc = (MODE == 0 ? g_zs : g_ans) + (size_t)gbase * 16;
        const uint4* whs  = (MODE == 0 ? g_Wn1s : g_Wn2s);
        #pragma unroll
        for (int i = tid; i < 2048; i += 256) {
            int row = i >> 4, ch = i & 15;
            *(uint4*)(sm + row * ROWB + ch * 16)          = hsrc[i];
            *(uint4*)(sm + WBYTES + row * ROWB + ch * 16) = whs[i];
        }
    }
    __syncthreads();

    const int laneRow = lane & 15;
    const unsigned laneK = (unsigned)((lane >> 4) << 4);
    const unsigned aoff = (unsigned)((wm * 32 + laneRow) * ROWB) + laneK;
    const unsigned woff = (unsigned)((wn * 64 + laneRow) * ROWB) + laneK;

    float acc[2][8][4];
    #pragma unroll
    for (int t = 0; t < 2; t++)
        #pragma unroll
        for (int n = 0; n < 8; n++)
            #pragma unroll
            for (int q = 0; q < 4; q++) acc[t][n][q] = 0.f;

    #pragma unroll 1
    for (int ks = 0; ks < 8; ks++) {
        unsigned kb = (unsigned)(ks * 32);
        unsigned ah[2][4], bw[4][4];
        LDMX4(ah[0], sA_u + aoff + kb);
        LDMX4(ah[1], sA_u + aoff + 16 * ROWB + kb);
        #pragma unroll
        for (int p = 0; p < 4; p++)
            LDMX4(bw[p], sW_u + woff + p * 16 * ROWB + kb);
        #pragma unroll
        for (int t = 0; t < 2; t++)
            #pragma unroll
            for (int p = 0; p < 4; p++) {
                MMA_F16(acc[t][2 * p],     ah[t][0], ah[t][1], ah[t][2], ah[t][3], bw[p][0], bw[p][2]);
                MMA_F16(acc[t][2 * p + 1], ah[t][0], ah[t][1], ah[t][2], ah[t][3], bw[p][1], bw[p][3]);
            }
    }
    __syncthreads();

    float* sF = (float*)(sm + WBYTES);
    {
        int mr = lane >> 2;
        int nc = 2 * (lane & 3);
        #pragma unroll
        for (int t = 0; t < 2; t++) {
            int row = wm * 32 + t * 16 + mr;
            #pragma unroll
            for (int nt = 0; nt < 8; nt++) {
                int col = wn * 64 + nt * 8 + nc;
                sF[row * 132 + col]           = acc[t][nt][0];
                sF[row * 132 + col + 1]       = acc[t][nt][1];
                sF[(row + 8) * 132 + col]     = acc[t][nt][2];
                sF[(row + 8) * 132 + col + 1] = acc[t][nt][3];
            }
        }
    }
    __syncthreads();

    if (MODE == 0) {
        int rl = tid >> 1, h = tid & 1;
        int grow = gbase + rl;
        bool valid = grow < NNODE;
        float* fr = sF + rl * 132 + h * 64;
        const float* bp = s_bias + h * 64;
        uint4* dh = (uint4*)((char*)g_ans + (size_t)grow * 256 + h * 128);
        #pragma unroll
        for (int q = 0; q < 8; q++) {
            unsigned ph[4];
            #pragma unroll
            for (int j = 0; j < 4; j++) {
                int c = q * 8 + j * 2;
                float v0 = fr[c]     + bp[c];
                float v1 = fr[c + 1] + bp[c + 1];
                v0 = (v0 >= 0.f) ? v0 : 0.01f * v0;
                v1 = (v1 >= 0.f) ? v1 : 0.01f * v1;
                if (!valid) { v0 = 0.f; v1 = 0.f; }
                fr[c] = v0; fr[c + 1] = v1;
                ph[j] = pack2h(v0, v1);
            }
            dh[q] = make_uint4(ph[0], ph[1], ph[2], ph[3]);
        }
        __syncthreads();
        {
            int c = tid & 127, h2 = tid >> 7;
            float s0 = 0.f, s1 = 0.f;
            #pragma unroll 8
            for (int r = 0; r < 64; r++) {
                float v = sF[(h2 * 64 + r) * 132 + c];
                s0 += v; s1 += v * v;
            }
            atomicAdd(&g_sums[4][c], s0);
            atomicAdd(&g_sums[5][c], s1);
        }
    } else {
        int rl = tid >> 1, h = tid & 1;
        int grow = gbase + rl;
        if (grow < NNODE) {
            const float* fr = sF + rl * 132 + h * 64;
            const float* bp = s_bias + h * 64;
            const float4* xp = (const float4*)(x + (size_t)grow * 128 + h * 64);
            float* dp = outp + (size_t)grow * 128 + h * 64;
            #pragma unroll
            for (int q = 0; q < 16; q++) {
                float4 xv = xp[q];
                ((float4*)dp)[q] = make_float4(fr[4*q]   + bp[4*q]   + xv.x,
                                               fr[4*q+1] + bp[4*q+1] + xv.y,
                                               fr[4*q+2] + bp[4*q+2] + xv.z,
                                               fr[4*q+3] + bp[4*q+3] + xv.w);
            }
        }
    }
}

// ---------------- persistent fp16 1-product edge GEMMs (cp.async double buffer) ----------------
// MODE 0 = E2, MODE 1 = E3
template <int MODE>
__global__ __launch_bounds__(256)
void tc_gemm(const float* __restrict__ ea, const int* __restrict__ eidx) {
    extern __shared__ char sm[];
    __shared__ float s_bias[128];
    const int tid = threadIdx.x;
    const int lane = tid & 31, wid = tid >> 5;
    const int wm = wid & 3, wn = wid >> 2;

    const unsigned base_u = smem_u32(sm);
    const unsigned sW_u = base_u;

    if (tid < 128) s_bias[tid] = (MODE == 0) ? g_b2p[tid] : g_b3p[tid];

    const uint4* Abase = (MODE == 0 ? g_a1split : g_a2split);
    const uint4* Wsrc  = (MODE == 0 ? g_W2s : g_W3s);

    int tile = blockIdx.x;
    {
        const uint4* src = Abase + (size_t)tile * 2048;
        unsigned dst = base_u + WBYTES;
        #pragma unroll
        for (int i = tid; i < 2048; i += 256) {
            int row = i >> 4, ch = i & 15;
            CP_ASYNC16(dst + (unsigned)(row * ROWB + ch * 16), src + i);
        }
        CP_COMMIT();
        #pragma unroll
        for (int i = tid; i < 2048; i += 256) {
            int row = i >> 4, ch = i & 15;
            *(uint4*)(sm + row * ROWB + ch * 16) = Wsrc[i];
        }
        CP_WAIT0();
    }
    __syncthreads();

    const int laneRow = lane & 15;
    const unsigned laneK = (unsigned)((lane >> 4) << 4);
    const unsigned aoff0 = (unsigned)((wm * 32 + laneRow) * ROWB) + laneK;
    const unsigned woff  = (unsigned)((wn * 64 + laneRow) * ROWB) + laneK;

    int buf = 0;
    for (; tile < NTILE; tile += GRID_TC) {
        int nxt = tile + GRID_TC;
        if (nxt < NTILE) {
            const uint4* src = Abase + (size_t)nxt * 2048;
            unsigned dst = base_u + WBYTES + (unsigned)((buf ^ 1) * ABUF);
            #pragma unroll
            for (int i = tid; i < 2048; i += 256) {
                int row = i >> 4, ch = i & 15;
                CP_ASYNC16(dst + (unsigned)(row * ROWB + ch * 16), src + i);
            }
        }
        CP_COMMIT();

        const unsigned sA_u = base_u + WBYTES + (unsigned)(buf * ABUF);

        float acc[2][8][4];
        #pragma unroll
        for (int t = 0; t < 2; t++)
            #pragma unroll
            for (int n = 0; n < 8; n++)
                #pragma unroll
                for (int q = 0; q < 4; q++) acc[t][n][q] = 0.f;

        #pragma unroll 1
        for (int ks = 0; ks < 8; ks++) {
            unsigned kb = (unsigned)(ks * 32);
            unsigned ah[2][4], bw[4][4];
            LDMX4(ah[0], sA_u + aoff0 + kb);
            LDMX4(ah[1], sA_u + aoff0 + 16 * ROWB + kb);
            #pragma unroll
            for (int p = 0; p < 4; p++)
                LDMX4(bw[p], sW_u + woff + p * 16 * ROWB + kb);
            #pragma unroll
            for (int t = 0; t < 2; t++)
                #pragma unroll
                for (int p = 0; p < 4; p++) {
                    MMA_F16(acc[t][2 * p],     ah[t][0], ah[t][1], ah[t][2], ah[t][3], bw[p][0], bw[p][2]);
                    MMA_F16(acc[t][2 * p + 1], ah[t][0], ah[t][1], ah[t][2], ah[t][3], bw[p][1], bw[p][3]);
                }
        }
        __syncthreads();

        float* sF = (float*)(sm + WBYTES + buf * ABUF);
        {
            int mr = lane >> 2;
            int nc = 2 * (lane & 3);
            #pragma unroll
            for (int t = 0; t < 2; t++) {
                int row = wm * 32 + t * 16 + mr;
                #pragma unroll
                for (int nt = 0; nt < 8; nt++) {
                    int col = wn * 64 + nt * 8 + nc;
                    sF[row * 132 + col]           = acc[t][nt][0];
                    sF[row * 132 + col + 1]       = acc[t][nt][1];
                    sF[(row + 8) * 132 + col]     = acc[t][nt][2];
                    sF[(row + 8) * 132 + col + 1] = acc[t][nt][3];
                }
            }
        }
        __syncthreads();

        if (MODE == 0) {
            int rl = tid >> 1, h = tid & 1;
            long gbase = (long)tile * 128;
            bool valid = (gbase + rl) < NEDGE;
            char* outb = (char*)g_a2split + (size_t)tile * 32768;
            uint4* dh = (uint4*)(outb + rl * 256 + h * 128);
            float* fr = sF + rl * 132 + h * 64;
            const float* bp = s_bias + h * 64;
            #pragma unroll
            for (int q = 0; q < 8; q++) {
                unsigned ph[4];
                #pragma unroll
                for (int j = 0; j < 4; j++) {
                    int c = q * 8 + j * 2;
                    float v0 = fr[c]     + bp[c];
                    float v1 = fr[c + 1] + bp[c + 1];
                    v0 = (v0 >= 0.f) ? v0 : 0.01f * v0;
                    v1 = (v1 >= 0.f) ? v1 : 0.01f * v1;
                    if (!valid) { v0 = 0.f; v1 = 0.f; }
                    fr[c] = v0; fr[c + 1] = v1;
                    ph[j] = pack2h(v0, v1);
                }
                dh[q] = make_uint4(ph[0], ph[1], ph[2], ph[3]);
            }
            __syncthreads();
            {
                int c = tid & 127, h2 = tid >> 7;
                float s0 = 0.f, s1 = 0.f;
                #pragma unroll 8
                for (int r = 0; r < 64; r++) {
                    float v = sF[(h2 * 64 + r) * 132 + c];
                    s0 += v; s1 += v * v;
                }
                atomicAdd(&g_sums[2][c], s0);
                atomicAdd(&g_sums[3][c], s1);
            }
        } else {
            int rt = tid >> 1, h = tid & 1;
            long grow = (long)tile * 128 + rt;
            if (grow < NEDGE) {
                int s_ = eidx[grow], d_ = eidx[NEDGE + grow];
                float coeff = cosf(1.5707963267948966f * ea[grow * 4 + 3]);
                const float4* xp = (const float4*)(g_xd + (size_t)s_ * 128) + h * 16;
                float* zp = g_z + (size_t)d_ * 128 + h * 64;
                const float* fr = sF + rt * 132 + h * 64;
                const float* bp = s_bias + h * 64;
                #pragma unroll
                for (int q = 0; q < 16; q++) {
                    float4 xv = xp[q];
                    float v0 = coeff * (fr[4 * q + 0] + bp[4 * q + 0]) * xv.x;
                    float v1 = coeff * (fr[4 * q + 1] + bp[4 * q + 1]) * xv.y;
                    float v2 = coeff * (fr[4 * q + 2] + bp[4 * q + 2]) * xv.z;
                    float v3 = coeff * (fr[4 * q + 3] + bp[4 * q + 3]) * xv.w;
                    asm volatile("red.global.add.v4.f32 [%0], {%1,%2,%3,%4};"
                                 :: "l"(zp + 4 * q), "f"(v0), "f"(v1), "f"(v2), "f"(v3) : "memory");
                }
            }
        }
        __syncthreads();
        CP_WAIT0();
        __syncthreads();
        buf ^= 1;
    }
}

// ---------------- launcher ----------------
extern "C" void kernel_launch(void* const* d_in, const int* in_sizes, int n_in,
                              void* d_out, int out_size) {
    const float* x    = (const float*)d_in[0];
    const float* ea   = (const float*)d_in[1];
    const int*   eidx = (const int*)  d_in[2];
    const float* Wb   = (const float*)d_in[3];
    const float* bb   = (const float*)d_in[4];
    const float* We1  = (const float*)d_in[5];
    const float* be1  = (const float*)d_in[6];
    const float* ge1  = (const float*)d_in[7];
    const float* bte1 = (const float*)d_in[8];
    const float* We2  = (const float*)d_in[9];
    const float* be2  = (const float*)d_in[10];
    const float* ge2  = (const float*)d_in[11];
    const float* bte2 = (const float*)d_in[12];
    const float* We3  = (const float*)d_in[13];
    const float* be3  = (const float*)d_in[14];
    const float* Wd   = (const float*)d_in[15];
    const float* bd   = (const float*)d_in[16];
    const float* v    = (const float*)d_in[17];
    const float* Wn1  = (const float*)d_in[18];
    const float* bn1  = (const float*)d_in[19];
    const float* gn   = (const float*)d_in[20];
    const float* btn  = (const float*)d_in[21];
    const float* Wn2  = (const float*)d_in[22];
    const float* bn2  = (const float*)d_in[23];
    float* outp = (float*)d_out;

    float* d_z;    cudaGetSymbolAddress((void**)&d_z, g_z);
    float* d_W2p;  cudaGetSymbolAddress((void**)&d_W2p, g_W2p);
    float* d_W3p;  cudaGetSymbolAddress((void**)&d_W3p, g_W3p);
    float* d_Wn2p; cudaGetSymbolAddress((void**)&d_Wn2p, g_Wn2p);
    char*  d_W2s;  cudaGetSymbolAddress((void**)&d_W2s, g_W2s);
    char*  d_W3s;  cudaGetSymbolAddress((void**)&d_W3s, g_W3s);
    char*  d_Wn1s; cudaGetSymbolAddress((void**)&d_Wn1s, g_Wn1s);
    char*  d_Wn2s; cudaGetSymbolAddress((void**)&d_Wn2s, g_Wn2s);
    char*  d_xs;   cudaGetSymbolAddress((void**)&d_xs, g_xs);
    char*  d_zs;   cudaGetSymbolAddress((void**)&d_zs, g_zs);

    cudaFuncSetAttribute(tc_gemm<0>, cudaFuncAttributeMaxDynamicSharedMemorySize, TCSM_E);
    cudaFuncSetAttribute(tc_gemm<1>, cudaFuncAttributeMaxDynamicSharedMemorySize, TCSM_E);
    cudaFuncSetAttribute(tc_node, cudaFuncAttributeMaxDynamicSharedMemorySize, TCSM_N);
    cudaFuncSetAttribute(tc_node2<0>, cudaFuncAttributeMaxDynamicSharedMemorySize, TCSM_N);
    cudaFuncSetAttribute(tc_node2<1>, cudaFuncAttributeMaxDynamicSharedMemorySize, TCSM_N);

    zero_stats<<<1, 768>>>();
    wbwe1_kernel<<<200, 128>>>(Wb, We1);
    cvec_kernel<<<1, 128>>>(bb, We1, be1);
    table_kernel<<<4 * GTAB, 128>>>();
    split_kernel<<<NTILEN, 256>>>(x, d_xs);
    packnode_kernel<<<384, 128>>>(We1, Wd);
    packh_kernel<<<128, 128>>>(Wn1, d_Wn1s);

    tc_node<<<NTILEN, 256, TCSM_N>>>(bd, v);

    e1_fuse_kernel<<<NTILE, 128>>>(ea, eidx);
    fold_kernel<<<129, 128>>>(0, 1.0f / NEDGE, ge1, bte1, We2, be2);
    packh_kernel<<<128, 128>>>(d_W2p, d_W2s);

    tc_gemm<0><<<GRID_TC, 256, TCSM_E>>>(ea, eidx);
    fold_kernel<<<129, 128>>>(2, 1.0f / NEDGE, ge2, bte2, We3, be3);
    packh_kernel<<<128, 128>>>(d_W3p, d_W3s);

    tc_gemm<1><<<GRID_TC, 256, TCSM_E>>>(ea, eidx);

    split_kernel<<<NTILEN, 256>>>(d_z, d_zs);
    tc_node2<0><<<NTILEN, 256, TCSM_N>>>(bn1, nullptr, nullptr);
    fold_kernel<<<129, 128>>>(4, 1.0f / NNODE, gn, btn, Wn2, bn2);
    packh_kernel<<<128, 128>>>(d_Wn2p, d_Wn2s);
    tc_node2<1><<<NTILEN, 256, TCSM_N>>>(nullptr, x, outp);
}